// round 8
// baseline (speedup 1.0000x reference)
#include <cuda_runtime.h>
#include <cuda_bf16.h>
#include <cstdint>

#define NVV 50000
#define DD 128
#define FIN 32
#define DEG 16
#define INDIM 288
#define GRID_TC 152
#define NBLK_SIDE (GRID_TC / 2)          // 76 persistent CTAs per side

#define BM64 64
#define NT64 ((NVV + BM64 - 1) / BM64)   // 782

// W^T (k-major): 288 k-rows x 136 n-cols bf16, stride 272 B (validated R3/R5-7)
#define WSB 272
// Act slab: 64 rows x K=288 bf16 (+pad), stride 592 B (16-aligned, phase-distinct).
#define ACT_STR 592
#define ACT_IMG (64 * ACT_STR)            // 37888
#define ACT_SLAB (2 * ACT_IMG)            // 75776 (hi | lo)

#define SM_WHI 0
#define SM_WLO 78336
#define SM_ACT 156672
#define SM_DYN (SM_ACT + ACT_SLAB)        // 232448 == opt-in max (single slot)

// named barriers: 1 = "full", 2 = "empty"
#define BAR_SYNC(id)   asm volatile("bar.sync %0, 512;"   :: "r"(id) : "memory")
#define BAR_ARRIVE(id) asm volatile("bar.arrive %0, 512;" :: "r"(id) : "memory")

// ---------------------------------------------------------------------------
__device__ __align__(16) unsigned short g_wh[2][288 * 136];
__device__ __align__(16) unsigned short g_wl[2][288 * 136];
__device__ __align__(256) float g_bufs[4][(size_t)NVV * DD];
__device__ float g_colsum[DD];
__device__ int g_is64;

__device__ __forceinline__ uint32_t smem_u32(const void* p) {
    uint32_t a;
    asm("{ .reg .u64 t; cvta.to.shared.u64 t, %1; cvt.u32.u64 %0, t; }" : "=r"(a) : "l"(p));
    return a;
}
__device__ __forceinline__ void ldsm_x4(uint32_t* r, uint32_t addr) {
    asm volatile("ldmatrix.sync.aligned.m8n8.x4.shared.b16 {%0,%1,%2,%3}, [%4];"
                 : "=r"(r[0]), "=r"(r[1]), "=r"(r[2]), "=r"(r[3]) : "r"(addr));
}
__device__ __forceinline__ void ldsm_x4t(uint32_t* r, uint32_t addr) {
    asm volatile("ldmatrix.sync.aligned.m8n8.x4.trans.shared.b16 {%0,%1,%2,%3}, [%4];"
                 : "=r"(r[0]), "=r"(r[1]), "=r"(r[2]), "=r"(r[3]) : "r"(addr));
}
__device__ __forceinline__ void mma_bf16(float* d, const uint32_t* a, uint32_t b0, uint32_t b1) {
    asm volatile("mma.sync.aligned.m16n8k16.row.col.f32.bf16.bf16.f32 "
                 "{%0,%1,%2,%3}, {%4,%5,%6,%7}, {%8,%9}, {%0,%1,%2,%3};"
                 : "+f"(d[0]), "+f"(d[1]), "+f"(d[2]), "+f"(d[3])
                 : "r"(a[0]), "r"(a[1]), "r"(a[2]), "r"(a[3]), "r"(b0), "r"(b1));
}
__device__ __forceinline__ uint32_t pack_bf2(float a, float b) {
    uint32_t r;
    asm("cvt.rn.bf16x2.f32 %0, %1, %2;" : "=r"(r) : "f"(b), "f"(a));
    return r;
}
__device__ __forceinline__ void split4(float4 v, uint2& hi, uint2& lo) {
    uint32_t h01 = pack_bf2(v.x, v.y);
    uint32_t h23 = pack_bf2(v.z, v.w);
    float hx = __uint_as_float(h01 << 16);
    float hy = __uint_as_float(h01 & 0xffff0000u);
    float hz = __uint_as_float(h23 << 16);
    float hw = __uint_as_float(h23 & 0xffff0000u);
    hi.x = h01; hi.y = h23;
    lo.x = pack_bf2(v.x - hx, v.y - hy);
    lo.y = pack_bf2(v.z - hz, v.w - hw);
}

// ---------------------------------------------------------------------------
__global__ void detect_kernel(const int* __restrict__ idx32) {
    if (threadIdx.x == 0) {
        int nz = 0;
#pragma unroll
        for (int i = 0; i < 64; i++) nz |= idx32[2 * i + 1];
        g_is64 = (nz == 0) ? 1 : 0;
    }
}
__global__ void zero_colsum() { if (threadIdx.x < DD) g_colsum[threadIdx.x] = 0.f; }

__global__ void prep_w(const float* __restrict__ Wv, const float* __restrict__ Wc) {
    int which = blockIdx.x;
    const float* W = which ? Wc : Wv;
    for (int e = threadIdx.x; e < 288 * 136; e += blockDim.x) {
        int k = e / 136, nn = e - k * 136;
        float w = (nn < 128) ? W[nn * INDIM + k] : 0.f;
        uint32_t h = pack_bf2(w, 0.f);
        float hf = __uint_as_float(h << 16);
        uint32_t l = pack_bf2(w - hf, 0.f);
        g_wh[which][e] = (unsigned short)(h & 0xffff);
        g_wl[which][e] = (unsigned short)(l & 0xffff);
    }
}

// ---------------------------------------------------------------------------
// HMMA initial embedding, dual-side merged: even blocks V, odd blocks C.
// ---------------------------------------------------------------------------
#define ISM_BH 0
#define ISM_BL 8704
#define ISM_ACT 17408
#define IACT_STR 80
#define IACT_IMG (128 * IACT_STR)       // 10240
#define NB_INIT ((NVV + 127) / 128)     // 391

__global__ __launch_bounds__(256, 1)
void init_mma(const float* __restrict__ vfeat, const float* __restrict__ cfeat,
              const float* __restrict__ Wiv, const float* __restrict__ Wic,
              const float* __restrict__ biv, const float* __restrict__ bic, int n) {
    __shared__ __align__(16) char ism[ISM_ACT + 2 * IACT_IMG];   // 37888 B
    uint32_t smb = smem_u32(ism);
    int side = blockIdx.x & 1;
    int blk = blockIdx.x >> 1;
    const float* feat = side ? cfeat : vfeat;
    const float* W    = side ? Wic : Wiv;
    const float* b    = side ? bic : biv;
    float* out = g_bufs[side ? 2 : 0];

    int tid = threadIdx.x, wid = tid >> 5, lane = tid & 31;
    int row0 = blk * 128;

    for (int e = tid; e < 32 * 136; e += 256) {
        int k = e / 136, nn = e - k * 136;
        float w = (nn < 128) ? W[nn * FIN + k] : 0.f;
        uint32_t h = pack_bf2(w, 0.f);
        float hf = __uint_as_float(h << 16);
        uint32_t l = pack_bf2(w - hf, 0.f);
        *(unsigned short*)(ism + ISM_BH + k * WSB + nn * 2) = (unsigned short)(h & 0xffff);
        *(unsigned short*)(ism + ISM_BL + k * WSB + nn * 2) = (unsigned short)(l & 0xffff);
    }
    {
        int r = tid >> 1, half = tid & 1;
        int gr = row0 + r;
        char* rowp = ism + ISM_ACT + r * IACT_STR + half * 32;
#pragma unroll
        for (int i = 0; i < 4; i++) {
            float4 v = (gr < n)
                ? reinterpret_cast<const float4*>(feat + (size_t)gr * FIN)[half * 4 + i]
                : make_float4(0.f, 0.f, 0.f, 0.f);
            uint2 hi, lo; split4(v, hi, lo);
            *(uint2*)(rowp + i * 8) = hi;
            *(uint2*)(rowp + IACT_IMG + i * 8) = lo;
        }
    }
    __syncthreads();

    int wm = wid >> 1, wn = wid & 1;
    int rsel = lane & 15, csel = lane >> 4;
    uint32_t aBase = smb + ISM_ACT + (uint32_t)((32 * wm + rsel) * IACT_STR + csel * 16);
    uint32_t bBase = smb + ISM_BH + (uint32_t)(rsel * WSB + csel * 16 + 128 * wn);

    float acc[2][8][4];
#pragma unroll
    for (int mt = 0; mt < 2; mt++)
#pragma unroll
        for (int nt = 0; nt < 8; nt++)
#pragma unroll
            for (int q = 0; q < 4; q++) acc[mt][nt][q] = 0.f;

#pragma unroll
    for (int ks = 0; ks < 2; ks++) {
        uint32_t ahi[2][4], alo[2][4], bhi[4][4], blo[4][4];
#pragma unroll
        for (int mt = 0; mt < 2; mt++) {
            uint32_t ra = aBase + (uint32_t)(16 * mt * IACT_STR + ks * 32);
            ldsm_x4(ahi[mt], ra);
            ldsm_x4(alo[mt], ra + IACT_IMG);
        }
#pragma unroll
        for (int np = 0; np < 4; np++) {
            uint32_t rb = bBase + (uint32_t)(ks * 16 * WSB + 32 * np);
            ldsm_x4t(bhi[np], rb);
            ldsm_x4t(blo[np], rb + (ISM_BL - ISM_BH));
        }
#pragma unroll
        for (int mt = 0; mt < 2; mt++)
#pragma unroll
            for (int nt = 0; nt < 8; nt++)
                mma_bf16(acc[mt][nt], ahi[mt], bhi[nt >> 1][2 * (nt & 1)], bhi[nt >> 1][2 * (nt & 1) + 1]);
#pragma unroll
        for (int mt = 0; mt < 2; mt++)
#pragma unroll
            for (int nt = 0; nt < 8; nt++)
                mma_bf16(acc[mt][nt], ahi[mt], blo[nt >> 1][2 * (nt & 1)], blo[nt >> 1][2 * (nt & 1) + 1]);
#pragma unroll
        for (int mt = 0; mt < 2; mt++)
#pragma unroll
            for (int nt = 0; nt < 8; nt++)
                mma_bf16(acc[mt][nt], alo[mt], bhi[nt >> 1][2 * (nt & 1)], bhi[nt >> 1][2 * (nt & 1) + 1]);
    }

    int r_lo = lane >> 2;
    int cpair = (lane & 3) * 2;
#pragma unroll
    for (int mt = 0; mt < 2; mt++) {
        int ra = row0 + 32 * wm + 16 * mt + r_lo;
#pragma unroll
        for (int nt = 0; nt < 8; nt++) {
            int col = 64 * wn + 8 * nt + cpair;
            float b0 = b[col], b1 = b[col + 1];
            if (ra < n) {
                float2 v = make_float2(acc[mt][nt][0] + b0, acc[mt][nt][1] + b1);
                *(float2*)(out + (size_t)ra * DD + col) = v;
            }
            if (ra + 8 < n) {
                float2 v = make_float2(acc[mt][nt][2] + b0, acc[mt][nt][3] + b1);
                *(float2*)(out + (size_t)(ra + 8) * DD + col) = v;
            }
        }
    }
}

// ---------------------------------------------------------------------------
// Dual-side warp-specialized layer, 64-row tiles, SINGLE Act slot.
// Producers (warps 8-15, 8 rows each): phase A (4 rows) gathered+split into
// registers BEFORE the empty-wait (overlaps consumer MMA); phase B (4 rows)
// gathered inside the critical section. Consumers (warps 0-7): 32x32 warp
// tiles (2mt x 4nt), 3-term HMMA.
// ---------------------------------------------------------------------------
__global__ __launch_bounds__(512, 1)
void layer_dual(int lv_sel, int lc_sel, int nlv_sel, int nlc_sel,
                const float* __restrict__ vfeat, const float* __restrict__ cfeat,
                const int* __restrict__ vci, const int* __restrict__ cvi,
                const float* __restrict__ bv, const float* __restrict__ bc, int n)
{
    extern __shared__ char sm[];
    uint32_t smb = smem_u32(sm);

    int side = blockIdx.x & 1;   // 0 = C side, 1 = V side
    int blk = blockIdx.x >> 1;

    const float* aggsrc; const float* selfp; float* out;
    const float* feat; const int* idx32; const float* b; int which;
    if (side == 0) {
        aggsrc = g_bufs[lv_sel]; selfp = g_bufs[lc_sel]; out = g_bufs[nlc_sel];
        feat = cfeat; idx32 = cvi; b = bc; which = 1;
    } else {
        aggsrc = g_bufs[lc_sel]; selfp = g_bufs[lv_sel]; out = g_bufs[nlv_sel];
        feat = vfeat; idx32 = vci; b = bv; which = 0;
    }

    int tid = threadIdx.x, wid = tid >> 5, lane = tid & 31;
    int istride = g_is64 ? 2 : 1;

    // ---- stage W hi/lo (all 512 threads) ----
    {
        const uint4* sh = (const uint4*)g_wh[which];
        const uint4* sl = (const uint4*)g_wl[which];
        uint4* dh = (uint4*)(sm + SM_WHI);
        uint4* dl = (uint4*)(sm + SM_WLO);
        for (int i = tid; i < 78336 / 16; i += 512) { dh[i] = sh[i]; dl[i] = sl[i]; }
    }
    __syncthreads();

    if (wid >= 8) {
        // ================= PRODUCERS =================
        int pw = wid - 8;              // owns rows pw*8 .. pw*8+7
        char* act = sm + SM_ACT;
        for (int tile = blk; tile < NT64; tile += NBLK_SIDE) {
            int row0 = tile * BM64;

            // ---- phase A: rows 0-3, gather+split to regs BEFORE wait ----
            uint2 hA[4], lA[4], hS[4], lS[4], hF[4], lF[4];
#pragma unroll
            for (int rr = 0; rr < 4; rr++) {
                int gr = row0 + pw * 8 + rr;
                bool val = gr < n;
                const int* ip = idx32 + (size_t)(val ? gr : 0) * DEG * istride;
                int srcs[DEG];
#pragma unroll
                for (int j = 0; j < DEG; j++) srcs[j] = ip[j * istride];
                float4 v = make_float4(0.f, 0.f, 0.f, 0.f);
#pragma unroll
                for (int j = 0; j < DEG; j++) {
                    float4 t = reinterpret_cast<const float4*>(
                        aggsrc + (size_t)srcs[j] * DD)[lane];
                    v.x += t.x; v.y += t.y; v.z += t.z; v.w += t.w;
                }
                if (!val) v = make_float4(0.f, 0.f, 0.f, 0.f);
                split4(v, hA[rr], lA[rr]);
                float4 sv = val
                    ? reinterpret_cast<const float4*>(selfp + (size_t)gr * DD)[lane]
                    : make_float4(0.f, 0.f, 0.f, 0.f);
                split4(sv, hS[rr], lS[rr]);
                float4 fv = (val && lane < 8)
                    ? reinterpret_cast<const float4*>(feat + (size_t)gr * FIN)[lane]
                    : make_float4(0.f, 0.f, 0.f, 0.f);
                split4(fv, hF[rr], lF[rr]);
            }

            BAR_SYNC(2);               // wait slot empty

            // STS phase A
#pragma unroll
            for (int rr = 0; rr < 4; rr++) {
                char* rowp = act + (pw * 8 + rr) * ACT_STR;
                *(uint2*)(rowp + lane * 8) = hA[rr];
                *(uint2*)(rowp + ACT_IMG + lane * 8) = lA[rr];
                *(uint2*)(rowp + 256 + lane * 8) = hS[rr];
                *(uint2*)(rowp + ACT_IMG + 256 + lane * 8) = lS[rr];
                if (lane < 8) {
                    *(uint2*)(rowp + 512 + lane * 8) = hF[rr];
                    *(uint2*)(rowp + ACT_IMG + 512 + lane * 8) = lF[rr];
                }
            }

            // ---- phase B: rows 4-7, gather -> split -> STS streaming ----
#pragma unroll
            for (int rr = 4; rr < 8; rr++) {
                int gr = row0 + pw * 8 + rr;
                bool val = gr < n;
                const int* ip = idx32 + (size_t)(val ? gr : 0) * DEG * istride;
                int srcs[DEG];
#pragma unroll
                for (int j = 0; j < DEG; j++) srcs[j] = ip[j * istride];
                float4 v = make_float4(0.f, 0.f, 0.f, 0.f);
#pragma unroll
                for (int j = 0; j < DEG; j++) {
                    float4 t = reinterpret_cast<const float4*>(
                        aggsrc + (size_t)srcs[j] * DD)[lane];
                    v.x += t.x; v.y += t.y; v.z += t.z; v.w += t.w;
                }
                if (!val) v = make_float4(0.f, 0.f, 0.f, 0.f);
                uint2 hi, lo; split4(v, hi, lo);
                char* rowp = act + (pw * 8 + rr) * ACT_STR;
                *(uint2*)(rowp + lane * 8) = hi;
                *(uint2*)(rowp + ACT_IMG + lane * 8) = lo;
                float4 sv = val
                    ? reinterpret_cast<const float4*>(selfp + (size_t)gr * DD)[lane]
                    : make_float4(0.f, 0.f, 0.f, 0.f);
                split4(sv, hi, lo);
                *(uint2*)(rowp + 256 + lane * 8) = hi;
                *(uint2*)(rowp + ACT_IMG + 256 + lane * 8) = lo;
                float4 fv = (val && lane < 8)
                    ? reinterpret_cast<const float4*>(feat + (size_t)gr * FIN)[lane]
                    : make_float4(0.f, 0.f, 0.f, 0.f);
                split4(fv, hi, lo);
                if (lane < 8) {
                    *(uint2*)(rowp + 512 + lane * 8) = hi;
                    *(uint2*)(rowp + ACT_IMG + 512 + lane * 8) = lo;
                }
            }
            BAR_ARRIVE(1);             // mark slot full
        }
    } else {
        // ================= CONSUMERS =================
        int wm = wid >> 2, wn = wid & 3;   // 2(m) x 4(n): 32 rows x 32 cols each
        int rsel = lane & 15, csel = lane >> 4;
        BAR_ARRIVE(2);                 // prime slot empty

        uint32_t aOff = (uint32_t)((32 * wm + rsel) * ACT_STR + csel * 16);
        uint32_t bBase = smb + SM_WHI + (uint32_t)(rsel * WSB + csel * 16 + 64 * wn);

        int cpair = (lane & 3) * 2;
        float2 bb[4];
#pragma unroll
        for (int nt = 0; nt < 4; nt++) {
            int col = 32 * wn + 8 * nt + cpair;
            bb[nt].x = b[col]; bb[nt].y = b[col + 1];
        }

        for (int tile = blk; tile < NT64; tile += NBLK_SIDE) {
            BAR_SYNC(1);               // wait slot full
            uint32_t aBase = smb + SM_ACT + aOff;

            float acc[2][4][4];
#pragma unroll
            for (int mt = 0; mt < 2; mt++)
#pragma unroll
                for (int nt = 0; nt < 4; nt++)
#pragma unroll
                    for (int q = 0; q < 4; q++) acc[mt][nt][q] = 0.f;

#pragma unroll 2
            for (int ks = 0; ks < 18; ks++) {
                uint32_t ahi[2][4], alo[2][4], bhi[2][4], blo[2][4];
#pragma unroll
                for (int mt = 0; mt < 2; mt++) {
                    uint32_t ra = aBase + (uint32_t)(16 * mt * ACT_STR + ks * 32);
                    ldsm_x4(ahi[mt], ra);
                    ldsm_x4(alo[mt], ra + ACT_IMG);
                }
#pragma unroll
                for (int np = 0; np < 2; np++) {
                    uint32_t rb = bBase + (uint32_t)(ks * 16 * WSB + 32 * np);
                    ldsm_x4t(bhi[np], rb);
                    ldsm_x4t(blo[np], rb + (SM_WLO - SM_WHI));
                }
#pragma unroll
                for (int mt = 0; mt < 2; mt++)
#pragma unroll
                    for (int nt = 0; nt < 4; nt++)
                        mma_bf16(acc[mt][nt], ahi[mt], bhi[nt >> 1][2 * (nt & 1)], bhi[nt >> 1][2 * (nt & 1) + 1]);
#pragma unroll
                for (int mt = 0; mt < 2; mt++)
#pragma unroll
                    for (int nt = 0; nt < 4; nt++)
                        mma_bf16(acc[mt][nt], ahi[mt], blo[nt >> 1][2 * (nt & 1)], blo[nt >> 1][2 * (nt & 1) + 1]);
#pragma unroll
                for (int mt = 0; mt < 2; mt++)
#pragma unroll
                    for (int nt = 0; nt < 4; nt++)
                        mma_bf16(acc[mt][nt], alo[mt], bhi[nt >> 1][2 * (nt & 1)], bhi[nt >> 1][2 * (nt & 1) + 1]);
            }
            BAR_ARRIVE(2);             // slot free (acc in regs)

            // epilogue
            int row0 = tile * BM64;
            int r_lo = lane >> 2;
#pragma unroll
            for (int mt = 0; mt < 2; mt++) {
                int ra0 = row0 + 32 * wm + 16 * mt + r_lo;
#pragma unroll
                for (int nt = 0; nt < 4; nt++) {
                    int col = 32 * wn + 8 * nt + cpair;
                    if (ra0 < n) {
                        float2 v = make_float2(acc[mt][nt][0] + bb[nt].x, acc[mt][nt][1] + bb[nt].y);
                        *(float2*)(out + (size_t)ra0 * DD + col) = v;
                    }
                    if (ra0 + 8 < n) {
                        float2 v = make_float2(acc[mt][nt][2] + bb[nt].x, acc[mt][nt][3] + bb[nt].y);
                        *(float2*)(out + (size_t)(ra0 + 8) * DD + col) = v;
                    }
                }
            }
        }
    }
}

// ---------------------------------------------------------------------------
__global__ void colsum_kernel(int lv_sel, int n) {
    const float* lv = g_bufs[lv_sel];
    __shared__ float s[DD];
    int tid = threadIdx.x;
    int col = tid & (DD - 1);
    int half = tid >> 7;
    int r0 = blockIdx.x * 128 + half * 64;
    int r1 = r0 + 64; if (r1 > n) r1 = n;
    float acc = 0.f;
    for (int r = r0; r < r1; r++) acc += lv[(size_t)r * DD + col];
    if (half) s[col] = acc;
    __syncthreads();
    if (!half) atomicAdd(&g_colsum[col], acc + s[col]);
}

__global__ void final_kernel(int lv_sel, const float* __restrict__ Wq,
                             const float* __restrict__ bq,
                             float* __restrict__ Q, int n) {
    const float* lv = g_bufs[lv_sel];
    __shared__ float sW[DD];
    __shared__ float s_s;
    int tid = threadIdx.x;
    if (tid < DD) sW[tid] = Wq[DD + tid];
    if (tid < 32) {
        float p = 0.f;
#pragma unroll
        for (int t = 0; t < 4; t++) p += g_colsum[tid + 32 * t] * Wq[tid + 32 * t];
#pragma unroll
        for (int o = 16; o > 0; o >>= 1) p += __shfl_xor_sync(0xffffffffu, p, o);
        if (tid == 0) s_s = p + bq[0];
    }
    __syncthreads();
    int warp = tid >> 5, lane = tid & 31;
    int base = blockIdx.x * 64 + warp * 8;
    for (int i = 0; i < 8; i++) {
        int row = base + i;
        if (row >= n) break;
        const float* rp = lv + (size_t)row * DD;
        float p = rp[lane]      * sW[lane]
                + rp[lane + 32] * sW[lane + 32]
                + rp[lane + 64] * sW[lane + 64]
                + rp[lane + 96] * sW[lane + 96];
#pragma unroll
        for (int o = 16; o > 0; o >>= 1) p += __shfl_xor_sync(0xffffffffu, p, o);
        if (lane == 0) Q[row] = s_s + p;
    }
}

// ---------------------------------------------------------------------------
extern "C" void kernel_launch(void* const* d_in, const int* in_sizes, int n_in,
                              void* d_out, int out_size) {
    const float* x    = (const float*)d_in[0];
    const int*   vci  = (const int*)d_in[1];
    const int*   cvi  = (const int*)d_in[2];
    const float* W_iv = (const float*)d_in[3];
    const float* b_iv = (const float*)d_in[4];
    const float* W_ic = (const float*)d_in[5];
    const float* b_ic = (const float*)d_in[6];
    const float* W_v  = (const float*)d_in[7];
    const float* b_v  = (const float*)d_in[8];
    const float* W_c  = (const float*)d_in[9];
    const float* b_c  = (const float*)d_in[10];
    const float* W_q  = (const float*)d_in[11];
    const float* b_q  = (const float*)d_in[12];
    float* Q = (float*)d_out;

    cudaFuncSetAttribute(layer_dual,
                         cudaFuncAttributeMaxDynamicSharedMemorySize, SM_DYN);

    const float* var_feat = x;
    const float* con_feat = x + (size_t)NVV * FIN;

    detect_kernel<<<1, 32>>>(vci);
    prep_w<<<2, 256>>>(W_v, W_c);
    init_mma<<<2 * NB_INIT, 256>>>(var_feat, con_feat, W_iv, W_ic, b_iv, b_ic, NVV);

    int lv = 0, lc = 2;
    for (int t = 0; t < 3; t++) {
        int nlc = 5 - lc, nlv = 1 - lv;
        layer_dual<<<GRID_TC, 512, SM_DYN>>>(lv, lc, nlv, nlc,
                                             var_feat, con_feat, vci, cvi,
                                             b_v, b_c, NVV);
        lv = nlv; lc = nlc;
    }

    zero_colsum<<<1, 128>>>();
    colsum_kernel<<<(NVV + 127) / 128, 256>>>(lv, NVV);
    final_kernel<<<(NVV + 63) / 64, 256>>>(lv, W_q, b_q, Q, NVV);
}

// round 9
// speedup vs baseline: 1.0177x; 1.0177x over previous
#include <cuda_runtime.h>
#include <cuda_bf16.h>
#include <cstdint>

#define NVV 50000
#define DD 128
#define FIN 32
#define DEG 16
#define INDIM 288
#define GRID_TC 152
#define NBLK_SIDE (GRID_TC / 2)          // 76 persistent CTAs per side

#define BM64 64
#define NT64 ((NVV + BM64 - 1) / BM64)   // 782

// W^T (k-major): 288 k-rows x 136 n-cols bf16, stride 272 B (validated R3/R5-8)
#define WSB 272
// Act slab: 64 rows x K=288 bf16 (+pad), stride 592 B (16-aligned, phase-distinct).
#define ACT_STR 592
#define ACT_IMG (64 * ACT_STR)            // 37888
#define ACT_SLAB (2 * ACT_IMG)            // 75776 (hi | lo)

#define SM_WHI 0
#define SM_WLO 78336
#define SM_ACT 156672
#define SM_DYN (SM_ACT + ACT_SLAB)        // 232448 == opt-in max (single slot)

// named barriers over all 1024 threads: 1 = "full", 2 = "empty"
#define BAR_SYNC(id)   asm volatile("bar.sync %0, 1024;"   :: "r"(id) : "memory")
#define BAR_ARRIVE(id) asm volatile("bar.arrive %0, 1024;" :: "r"(id) : "memory")

// ---------------------------------------------------------------------------
__device__ __align__(16) unsigned short g_wh[2][288 * 136];
__device__ __align__(16) unsigned short g_wl[2][288 * 136];
__device__ __align__(256) float g_bufs[4][(size_t)NVV * DD];
__device__ float g_colsum[DD];
__device__ int g_is64;

__device__ __forceinline__ uint32_t smem_u32(const void* p) {
    uint32_t a;
    asm("{ .reg .u64 t; cvta.to.shared.u64 t, %1; cvt.u32.u64 %0, t; }" : "=r"(a) : "l"(p));
    return a;
}
__device__ __forceinline__ void ldsm_x4(uint32_t* r, uint32_t addr) {
    asm volatile("ldmatrix.sync.aligned.m8n8.x4.shared.b16 {%0,%1,%2,%3}, [%4];"
                 : "=r"(r[0]), "=r"(r[1]), "=r"(r[2]), "=r"(r[3]) : "r"(addr));
}
__device__ __forceinline__ void ldsm_x4t(uint32_t* r, uint32_t addr) {
    asm volatile("ldmatrix.sync.aligned.m8n8.x4.trans.shared.b16 {%0,%1,%2,%3}, [%4];"
                 : "=r"(r[0]), "=r"(r[1]), "=r"(r[2]), "=r"(r[3]) : "r"(addr));
}
__device__ __forceinline__ void mma_bf16(float* d, const uint32_t* a, uint32_t b0, uint32_t b1) {
    asm volatile("mma.sync.aligned.m16n8k16.row.col.f32.bf16.bf16.f32 "
                 "{%0,%1,%2,%3}, {%4,%5,%6,%7}, {%8,%9}, {%0,%1,%2,%3};"
                 : "+f"(d[0]), "+f"(d[1]), "+f"(d[2]), "+f"(d[3])
                 : "r"(a[0]), "r"(a[1]), "r"(a[2]), "r"(a[3]), "r"(b0), "r"(b1));
}
__device__ __forceinline__ uint32_t pack_bf2(float a, float b) {
    uint32_t r;
    asm("cvt.rn.bf16x2.f32 %0, %1, %2;" : "=r"(r) : "f"(b), "f"(a));
    return r;
}
__device__ __forceinline__ void split4(float4 v, uint2& hi, uint2& lo) {
    uint32_t h01 = pack_bf2(v.x, v.y);
    uint32_t h23 = pack_bf2(v.z, v.w);
    float hx = __uint_as_float(h01 << 16);
    float hy = __uint_as_float(h01 & 0xffff0000u);
    float hz = __uint_as_float(h23 << 16);
    float hw = __uint_as_float(h23 & 0xffff0000u);
    hi.x = h01; hi.y = h23;
    lo.x = pack_bf2(v.x - hx, v.y - hy);
    lo.y = pack_bf2(v.z - hz, v.w - hw);
}

// ---------------------------------------------------------------------------
__global__ void detect_kernel(const int* __restrict__ idx32) {
    if (threadIdx.x == 0) {
        int nz = 0;
#pragma unroll
        for (int i = 0; i < 64; i++) nz |= idx32[2 * i + 1];
        g_is64 = (nz == 0) ? 1 : 0;
    }
}
__global__ void zero_colsum() { if (threadIdx.x < DD) g_colsum[threadIdx.x] = 0.f; }

__global__ void prep_w(const float* __restrict__ Wv, const float* __restrict__ Wc) {
    int which = blockIdx.x;
    const float* W = which ? Wc : Wv;
    for (int e = threadIdx.x; e < 288 * 136; e += blockDim.x) {
        int k = e / 136, nn = e - k * 136;
        float w = (nn < 128) ? W[nn * INDIM + k] : 0.f;
        uint32_t h = pack_bf2(w, 0.f);
        float hf = __uint_as_float(h << 16);
        uint32_t l = pack_bf2(w - hf, 0.f);
        g_wh[which][e] = (unsigned short)(h & 0xffff);
        g_wl[which][e] = (unsigned short)(l & 0xffff);
    }
}

// ---------------------------------------------------------------------------
// HMMA initial embedding, dual-side merged (unchanged from R7/R8).
// ---------------------------------------------------------------------------
#define ISM_BH 0
#define ISM_BL 8704
#define ISM_ACT 17408
#define IACT_STR 80
#define IACT_IMG (128 * IACT_STR)       // 10240
#define NB_INIT ((NVV + 127) / 128)     // 391

__global__ __launch_bounds__(256, 1)
void init_mma(const float* __restrict__ vfeat, const float* __restrict__ cfeat,
              const float* __restrict__ Wiv, const float* __restrict__ Wic,
              const float* __restrict__ biv, const float* __restrict__ bic, int n) {
    __shared__ __align__(16) char ism[ISM_ACT + 2 * IACT_IMG];   // 37888 B
    uint32_t smb = smem_u32(ism);
    int side = blockIdx.x & 1;
    int blk = blockIdx.x >> 1;
    const float* feat = side ? cfeat : vfeat;
    const float* W    = side ? Wic : Wiv;
    const float* b    = side ? bic : biv;
    float* out = g_bufs[side ? 2 : 0];

    int tid = threadIdx.x, wid = tid >> 5, lane = tid & 31;
    int row0 = blk * 128;

    for (int e = tid; e < 32 * 136; e += 256) {
        int k = e / 136, nn = e - k * 136;
        float w = (nn < 128) ? W[nn * FIN + k] : 0.f;
        uint32_t h = pack_bf2(w, 0.f);
        float hf = __uint_as_float(h << 16);
        uint32_t l = pack_bf2(w - hf, 0.f);
        *(unsigned short*)(ism + ISM_BH + k * WSB + nn * 2) = (unsigned short)(h & 0xffff);
        *(unsigned short*)(ism + ISM_BL + k * WSB + nn * 2) = (unsigned short)(l & 0xffff);
    }
    {
        int r = tid >> 1, half = tid & 1;
        int gr = row0 + r;
        char* rowp = ism + ISM_ACT + r * IACT_STR + half * 32;
#pragma unroll
        for (int i = 0; i < 4; i++) {
            float4 v = (gr < n)
                ? reinterpret_cast<const float4*>(feat + (size_t)gr * FIN)[half * 4 + i]
                : make_float4(0.f, 0.f, 0.f, 0.f);
            uint2 hi, lo; split4(v, hi, lo);
            *(uint2*)(rowp + i * 8) = hi;
            *(uint2*)(rowp + IACT_IMG + i * 8) = lo;
        }
    }
    __syncthreads();

    int wm = wid >> 1, wn = wid & 1;
    int rsel = lane & 15, csel = lane >> 4;
    uint32_t aBase = smb + ISM_ACT + (uint32_t)((32 * wm + rsel) * IACT_STR + csel * 16);
    uint32_t bBase = smb + ISM_BH + (uint32_t)(rsel * WSB + csel * 16 + 128 * wn);

    float acc[2][8][4];
#pragma unroll
    for (int mt = 0; mt < 2; mt++)
#pragma unroll
        for (int nt = 0; nt < 8; nt++)
#pragma unroll
            for (int q = 0; q < 4; q++) acc[mt][nt][q] = 0.f;

#pragma unroll
    for (int ks = 0; ks < 2; ks++) {
        uint32_t ahi[2][4], alo[2][4], bhi[4][4], blo[4][4];
#pragma unroll
        for (int mt = 0; mt < 2; mt++) {
            uint32_t ra = aBase + (uint32_t)(16 * mt * IACT_STR + ks * 32);
            ldsm_x4(ahi[mt], ra);
            ldsm_x4(alo[mt], ra + IACT_IMG);
        }
#pragma unroll
        for (int np = 0; np < 4; np++) {
            uint32_t rb = bBase + (uint32_t)(ks * 16 * WSB + 32 * np);
            ldsm_x4t(bhi[np], rb);
            ldsm_x4t(blo[np], rb + (ISM_BL - ISM_BH));
        }
#pragma unroll
        for (int mt = 0; mt < 2; mt++)
#pragma unroll
            for (int nt = 0; nt < 8; nt++)
                mma_bf16(acc[mt][nt], ahi[mt], bhi[nt >> 1][2 * (nt & 1)], bhi[nt >> 1][2 * (nt & 1) + 1]);
#pragma unroll
        for (int mt = 0; mt < 2; mt++)
#pragma unroll
            for (int nt = 0; nt < 8; nt++)
                mma_bf16(acc[mt][nt], ahi[mt], blo[nt >> 1][2 * (nt & 1)], blo[nt >> 1][2 * (nt & 1) + 1]);
#pragma unroll
        for (int mt = 0; mt < 2; mt++)
#pragma unroll
            for (int nt = 0; nt < 8; nt++)
                mma_bf16(acc[mt][nt], alo[mt], bhi[nt >> 1][2 * (nt & 1)], bhi[nt >> 1][2 * (nt & 1) + 1]);
    }

    int r_lo = lane >> 2;
    int cpair = (lane & 3) * 2;
#pragma unroll
    for (int mt = 0; mt < 2; mt++) {
        int ra = row0 + 32 * wm + 16 * mt + r_lo;
#pragma unroll
        for (int nt = 0; nt < 8; nt++) {
            int col = 64 * wn + 8 * nt + cpair;
            float b0 = b[col], b1 = b[col + 1];
            if (ra < n) {
                float2 v = make_float2(acc[mt][nt][0] + b0, acc[mt][nt][1] + b1);
                *(float2*)(out + (size_t)ra * DD + col) = v;
            }
            if (ra + 8 < n) {
                float2 v = make_float2(acc[mt][nt][2] + b0, acc[mt][nt][3] + b1);
                *(float2*)(out + (size_t)(ra + 8) * DD + col) = v;
            }
        }
    }
}

// ---------------------------------------------------------------------------
// Producer helpers: gather one 288-wide row into 6 uint2 (hi/lo bf16 pairs).
// ---------------------------------------------------------------------------
__device__ __forceinline__ void gather_row(
    const float* __restrict__ aggsrc, const float* __restrict__ selfp,
    const float* __restrict__ feat, const int* __restrict__ idx32,
    int gr, int n, int istride, int lane, uint2* G)
{
    bool val = gr < n;
    const int* ip = idx32 + (size_t)(val ? gr : 0) * DEG * istride;
    int srcs[DEG];
#pragma unroll
    for (int j = 0; j < DEG; j++) srcs[j] = ip[j * istride];
    float4 v = make_float4(0.f, 0.f, 0.f, 0.f);
#pragma unroll
    for (int j = 0; j < DEG; j++) {
        float4 t = reinterpret_cast<const float4*>(aggsrc + (size_t)srcs[j] * DD)[lane];
        v.x += t.x; v.y += t.y; v.z += t.z; v.w += t.w;
    }
    if (!val) v = make_float4(0.f, 0.f, 0.f, 0.f);
    split4(v, G[0], G[1]);
    float4 sv = val
        ? reinterpret_cast<const float4*>(selfp + (size_t)gr * DD)[lane]
        : make_float4(0.f, 0.f, 0.f, 0.f);
    split4(sv, G[2], G[3]);
    float4 fv = (val && lane < 8)
        ? reinterpret_cast<const float4*>(feat + (size_t)gr * FIN)[lane]
        : make_float4(0.f, 0.f, 0.f, 0.f);
    split4(fv, G[4], G[5]);
}

__device__ __forceinline__ void sts_row(char* act, int r, int lane, const uint2* G) {
    char* rowp = act + r * ACT_STR;
    *(uint2*)(rowp + lane * 8) = G[0];
    *(uint2*)(rowp + ACT_IMG + lane * 8) = G[1];
    *(uint2*)(rowp + 256 + lane * 8) = G[2];
    *(uint2*)(rowp + ACT_IMG + 256 + lane * 8) = G[3];
    if (lane < 8) {
        *(uint2*)(rowp + 512 + lane * 8) = G[4];
        *(uint2*)(rowp + ACT_IMG + 512 + lane * 8) = G[5];
    }
}

// ---------------------------------------------------------------------------
// Dual-side warp-specialized layer, 1024 threads (32 warps/SM, 2x occupancy).
// Warps 16-31 produce (4 rows each: 2 staged pre-wait, 2 streamed),
// warps 0-15 consume (4m x 4n grid, 16x32 warp tiles, 3-term HMMA).
// ---------------------------------------------------------------------------
__global__ __launch_bounds__(1024, 1)
void layer_dual(int lv_sel, int lc_sel, int nlv_sel, int nlc_sel,
                const float* __restrict__ vfeat, const float* __restrict__ cfeat,
                const int* __restrict__ vci, const int* __restrict__ cvi,
                const float* __restrict__ bv, const float* __restrict__ bc, int n)
{
    extern __shared__ char sm[];
    uint32_t smb = smem_u32(sm);

    int side = blockIdx.x & 1;   // 0 = C side, 1 = V side
    int blk = blockIdx.x >> 1;

    const float* aggsrc; const float* selfp; float* out;
    const float* feat; const int* idx32; const float* b; int which;
    if (side == 0) {
        aggsrc = g_bufs[lv_sel]; selfp = g_bufs[lc_sel]; out = g_bufs[nlc_sel];
        feat = cfeat; idx32 = cvi; b = bc; which = 1;
    } else {
        aggsrc = g_bufs[lc_sel]; selfp = g_bufs[lv_sel]; out = g_bufs[nlv_sel];
        feat = vfeat; idx32 = vci; b = bv; which = 0;
    }

    int tid = threadIdx.x, wid = tid >> 5, lane = tid & 31;
    int istride = g_is64 ? 2 : 1;

    // ---- stage W hi/lo (all 1024 threads) ----
    {
        const uint4* sh = (const uint4*)g_wh[which];
        const uint4* sl = (const uint4*)g_wl[which];
        uint4* dh = (uint4*)(sm + SM_WHI);
        uint4* dl = (uint4*)(sm + SM_WLO);
        for (int i = tid; i < 78336 / 16; i += 1024) { dh[i] = sh[i]; dl[i] = sl[i]; }
    }
    __syncthreads();

    if (wid >= 16) {
        // ================= PRODUCERS (16 warps, 4 rows each) =================
        int pw = wid - 16;             // owns rows pw*4 .. pw*4+3
        char* act = sm + SM_ACT;
        for (int tile = blk; tile < NT64; tile += NBLK_SIDE) {
            int row0 = tile * BM64 + pw * 4;

            // stage rows 0-1 into registers BEFORE the empty-wait
            uint2 G0[6], G1[6];
            gather_row(aggsrc, selfp, feat, idx32, row0 + 0, n, istride, lane, G0);
            gather_row(aggsrc, selfp, feat, idx32, row0 + 1, n, istride, lane, G1);

            BAR_SYNC(2);               // wait slot empty

            sts_row(act, pw * 4 + 0, lane, G0);
            sts_row(act, pw * 4 + 1, lane, G1);
            // stream rows 2-3
            gather_row(aggsrc, selfp, feat, idx32, row0 + 2, n, istride, lane, G0);
            sts_row(act, pw * 4 + 2, lane, G0);
            gather_row(aggsrc, selfp, feat, idx32, row0 + 3, n, istride, lane, G1);
            sts_row(act, pw * 4 + 3, lane, G1);

            BAR_ARRIVE(1);             // mark slot full
        }
    } else {
        // ================= CONSUMERS (16 warps: 4m x 4n) =================
        int wm = wid >> 2, wn = wid & 3;   // 16 rows x 32 cols per warp
        int rsel = lane & 15, csel = lane >> 4;
        BAR_ARRIVE(2);                 // prime slot empty

        uint32_t aOff = (uint32_t)((16 * wm + rsel) * ACT_STR + csel * 16);
        uint32_t bBase = smb + SM_WHI + (uint32_t)(rsel * WSB + csel * 16 + 64 * wn);

        int cpair = (lane & 3) * 2;
        float2 bb[4];
#pragma unroll
        for (int nt = 0; nt < 4; nt++) {
            int col = 32 * wn + 8 * nt + cpair;
            bb[nt].x = b[col]; bb[nt].y = b[col + 1];
        }

        for (int tile = blk; tile < NT64; tile += NBLK_SIDE) {
            BAR_SYNC(1);               // wait slot full
            uint32_t aBase = smb + SM_ACT + aOff;

            float acc[4][4];
#pragma unroll
            for (int nt = 0; nt < 4; nt++)
#pragma unroll
                for (int q = 0; q < 4; q++) acc[nt][q] = 0.f;

#pragma unroll 2
            for (int ks = 0; ks < 18; ks++) {
                uint32_t ahi[4], alo[4], bhi[2][4], blo[2][4];
                uint32_t ra = aBase + (uint32_t)(ks * 32);
                ldsm_x4(ahi, ra);
                ldsm_x4(alo, ra + ACT_IMG);
#pragma unroll
                for (int np = 0; np < 2; np++) {
                    uint32_t rb = bBase + (uint32_t)(ks * 16 * WSB + 32 * np);
                    ldsm_x4t(bhi[np], rb);
                    ldsm_x4t(blo[np], rb + (SM_WLO - SM_WHI));
                }
#pragma unroll
                for (int nt = 0; nt < 4; nt++)
                    mma_bf16(acc[nt], ahi, bhi[nt >> 1][2 * (nt & 1)], bhi[nt >> 1][2 * (nt & 1) + 1]);
#pragma unroll
                for (int nt = 0; nt < 4; nt++)
                    mma_bf16(acc[nt], ahi, blo[nt >> 1][2 * (nt & 1)], blo[nt >> 1][2 * (nt & 1) + 1]);
#pragma unroll
                for (int nt = 0; nt < 4; nt++)
                    mma_bf16(acc[nt], alo, bhi[nt >> 1][2 * (nt & 1)], bhi[nt >> 1][2 * (nt & 1) + 1]);
            }
            BAR_ARRIVE(2);             // slot free (acc in regs)

            // epilogue
            int row0 = tile * BM64;
            int r_lo = lane >> 2;
            int ra0 = row0 + 16 * wm + r_lo;
#pragma unroll
            for (int nt = 0; nt < 4; nt++) {
                int col = 32 * wn + 8 * nt + cpair;
                if (ra0 < n) {
                    float2 v = make_float2(acc[nt][0] + bb[nt].x, acc[nt][1] + bb[nt].y);
                    *(float2*)(out + (size_t)ra0 * DD + col) = v;
                }
                if (ra0 + 8 < n) {
                    float2 v = make_float2(acc[nt][2] + bb[nt].x, acc[nt][3] + bb[nt].y);
                    *(float2*)(out + (size_t)(ra0 + 8) * DD + col) = v;
                }
            }
        }
    }
}

// ---------------------------------------------------------------------------
__global__ void colsum_kernel(int lv_sel, int n) {
    const float* lv = g_bufs[lv_sel];
    __shared__ float s[DD];
    int tid = threadIdx.x;
    int col = tid & (DD - 1);
    int half = tid >> 7;
    int r0 = blockIdx.x * 128 + half * 64;
    int r1 = r0 + 64; if (r1 > n) r1 = n;
    float acc = 0.f;
    for (int r = r0; r < r1; r++) acc += lv[(size_t)r * DD + col];
    if (half) s[col] = acc;
    __syncthreads();
    if (!half) atomicAdd(&g_colsum[col], acc + s[col]);
}

__global__ void final_kernel(int lv_sel, const float* __restrict__ Wq,
                             const float* __restrict__ bq,
                             float* __restrict__ Q, int n) {
    const float* lv = g_bufs[lv_sel];
    __shared__ float sW[DD];
    __shared__ float s_s;
    int tid = threadIdx.x;
    if (tid < DD) sW[tid] = Wq[DD + tid];
    if (tid < 32) {
        float p = 0.f;
#pragma unroll
        for (int t = 0; t < 4; t++) p += g_colsum[tid + 32 * t] * Wq[tid + 32 * t];
#pragma unroll
        for (int o = 16; o > 0; o >>= 1) p += __shfl_xor_sync(0xffffffffu, p, o);
        if (tid == 0) s_s = p + bq[0];
    }
    __syncthreads();
    int warp = tid >> 5, lane = tid & 31;
    int base = blockIdx.x * 64 + warp * 8;
    for (int i = 0; i < 8; i++) {
        int row = base + i;
        if (row >= n) break;
        const float* rp = lv + (size_t)row * DD;
        float p = rp[lane]      * sW[lane]
                + rp[lane + 32] * sW[lane + 32]
                + rp[lane + 64] * sW[lane + 64]
                + rp[lane + 96] * sW[lane + 96];
#pragma unroll
        for (int o = 16; o > 0; o >>= 1) p += __shfl_xor_sync(0xffffffffu, p, o);
        if (lane == 0) Q[row] = s_s + p;
    }
}

// ---------------------------------------------------------------------------
extern "C" void kernel_launch(void* const* d_in, const int* in_sizes, int n_in,
                              void* d_out, int out_size) {
    const float* x    = (const float*)d_in[0];
    const int*   vci  = (const int*)d_in[1];
    const int*   cvi  = (const int*)d_in[2];
    const float* W_iv = (const float*)d_in[3];
    const float* b_iv = (const float*)d_in[4];
    const float* W_ic = (const float*)d_in[5];
    const float* b_ic = (const float*)d_in[6];
    const float* W_v  = (const float*)d_in[7];
    const float* b_v  = (const float*)d_in[8];
    const float* W_c  = (const float*)d_in[9];
    const float* b_c  = (const float*)d_in[10];
    const float* W_q  = (const float*)d_in[11];
    const float* b_q  = (const float*)d_in[12];
    float* Q = (float*)d_out;

    cudaFuncSetAttribute(layer_dual,
                         cudaFuncAttributeMaxDynamicSharedMemorySize, SM_DYN);

    const float* var_feat = x;
    const float* con_feat = x + (size_t)NVV * FIN;

    detect_kernel<<<1, 32>>>(vci);
    prep_w<<<2, 256>>>(W_v, W_c);
    init_mma<<<2 * NB_INIT, 256>>>(var_feat, con_feat, W_iv, W_ic, b_iv, b_ic, NVV);

    int lv = 0, lc = 2;
    for (int t = 0; t < 3; t++) {
        int nlc = 5 - lc, nlv = 1 - lv;
        layer_dual<<<GRID_TC, 1024, SM_DYN>>>(lv, lc, nlv, nlc,
                                              var_feat, con_feat, vci, cvi,
                                              b_v, b_c, NVV);
        lv = nlv; lc = nlc;
    }

    zero_colsum<<<1, 128>>>();
    colsum_kernel<<<(NVV + 127) / 128, 256>>>(lv, NVV);
    final_kernel<<<(NVV + 63) / 64, 256>>>(lv, W_q, b_q, Q, NVV);
}

// round 10
// speedup vs baseline: 1.1004x; 1.0813x over previous
#include <cuda_runtime.h>
#include <cuda_bf16.h>
#include <cuda_fp16.h>
#include <cstdint>

#define NVV 50000
#define DD 128
#define FIN 32
#define DEG 16
#define INDIM 288
#define GRID_TC 152
#define NBLK_SIDE (GRID_TC / 2)          // 76 persistent CTAs per side

#define BM64 64
#define NT64 ((NVV + BM64 - 1) / BM64)   // 782

#define WSB 272
#define ACT_STR 592
#define ACT_IMG (64 * ACT_STR)            // 37888
#define ACT_SLAB (2 * ACT_IMG)            // 75776

#define SM_WHI 0
#define SM_WLO 78336
#define SM_ACT 156672
#define SM_DYN (SM_ACT + ACT_SLAB)        // 232448 == opt-in max

#define BAR_SYNC(id)   asm volatile("bar.sync %0, 1024;"   :: "r"(id) : "memory")
#define BAR_ARRIVE(id) asm volatile("bar.arrive %0, 1024;" :: "r"(id) : "memory")

// ---------------------------------------------------------------------------
__device__ __align__(16) unsigned short g_wh[2][288 * 136];
__device__ __align__(16) unsigned short g_wl[2][288 * 136];
__device__ __align__(256) float g_bufs[4][(size_t)NVV * DD];   // fp32 master
__device__ __align__(256) __half g_h16[4][(size_t)NVV * DD];   // fp16 gather plane
__device__ float g_colsum[DD];
__device__ int g_is64;

__device__ __forceinline__ uint32_t smem_u32(const void* p) {
    uint32_t a;
    asm("{ .reg .u64 t; cvta.to.shared.u64 t, %1; cvt.u32.u64 %0, t; }" : "=r"(a) : "l"(p));
    return a;
}
__device__ __forceinline__ void ldsm_x4(uint32_t* r, uint32_t addr) {
    asm volatile("ldmatrix.sync.aligned.m8n8.x4.shared.b16 {%0,%1,%2,%3}, [%4];"
                 : "=r"(r[0]), "=r"(r[1]), "=r"(r[2]), "=r"(r[3]) : "r"(addr));
}
__device__ __forceinline__ void ldsm_x4t(uint32_t* r, uint32_t addr) {
    asm volatile("ldmatrix.sync.aligned.m8n8.x4.trans.shared.b16 {%0,%1,%2,%3}, [%4];"
                 : "=r"(r[0]), "=r"(r[1]), "=r"(r[2]), "=r"(r[3]) : "r"(addr));
}
__device__ __forceinline__ void mma_bf16(float* d, const uint32_t* a, uint32_t b0, uint32_t b1) {
    asm volatile("mma.sync.aligned.m16n8k16.row.col.f32.bf16.bf16.f32 "
                 "{%0,%1,%2,%3}, {%4,%5,%6,%7}, {%8,%9}, {%0,%1,%2,%3};"
                 : "+f"(d[0]), "+f"(d[1]), "+f"(d[2]), "+f"(d[3])
                 : "r"(a[0]), "r"(a[1]), "r"(a[2]), "r"(a[3]), "r"(b0), "r"(b1));
}
__device__ __forceinline__ uint32_t pack_bf2(float a, float b) {
    uint32_t r;
    asm("cvt.rn.bf16x2.f32 %0, %1, %2;" : "=r"(r) : "f"(b), "f"(a));
    return r;
}
__device__ __forceinline__ void split4(float4 v, uint2& hi, uint2& lo) {
    uint32_t h01 = pack_bf2(v.x, v.y);
    uint32_t h23 = pack_bf2(v.z, v.w);
    float hx = __uint_as_float(h01 << 16);
    float hy = __uint_as_float(h01 & 0xffff0000u);
    float hz = __uint_as_float(h23 << 16);
    float hw = __uint_as_float(h23 & 0xffff0000u);
    hi.x = h01; hi.y = h23;
    lo.x = pack_bf2(v.x - hx, v.y - hy);
    lo.y = pack_bf2(v.z - hz, v.w - hw);
}

// ---------------------------------------------------------------------------
// prep: blocks 0,1 split W; block 2 does idx-width detect + colsum zero.
// ---------------------------------------------------------------------------
__global__ void prep_w(const float* __restrict__ Wv, const float* __restrict__ Wc,
                       const int* __restrict__ idx32) {
    int which = blockIdx.x;
    if (which == 2) {
        if (threadIdx.x == 0) {
            int nz = 0;
#pragma unroll
            for (int i = 0; i < 64; i++) nz |= idx32[2 * i + 1];
            g_is64 = (nz == 0) ? 1 : 0;
        }
        if (threadIdx.x < DD) g_colsum[threadIdx.x] = 0.f;
        return;
    }
    const float* W = which ? Wc : Wv;
    for (int e = threadIdx.x; e < 288 * 136; e += blockDim.x) {
        int k = e / 136, nn = e - k * 136;
        float w = (nn < 128) ? W[nn * INDIM + k] : 0.f;
        uint32_t h = pack_bf2(w, 0.f);
        float hf = __uint_as_float(h << 16);
        uint32_t l = pack_bf2(w - hf, 0.f);
        g_wh[which][e] = (unsigned short)(h & 0xffff);
        g_wl[which][e] = (unsigned short)(l & 0xffff);
    }
}

// ---------------------------------------------------------------------------
// HMMA initial embedding, dual-side merged. Writes fp32 master + fp16 plane.
// ---------------------------------------------------------------------------
#define ISM_BH 0
#define ISM_BL 8704
#define ISM_ACT 17408
#define IACT_STR 80
#define IACT_IMG (128 * IACT_STR)
#define NB_INIT ((NVV + 127) / 128)

__global__ __launch_bounds__(256, 1)
void init_mma(const float* __restrict__ vfeat, const float* __restrict__ cfeat,
              const float* __restrict__ Wiv, const float* __restrict__ Wic,
              const float* __restrict__ biv, const float* __restrict__ bic, int n) {
    __shared__ __align__(16) char ism[ISM_ACT + 2 * IACT_IMG];
    uint32_t smb = smem_u32(ism);
    int side = blockIdx.x & 1;
    int blk = blockIdx.x >> 1;
    const float* feat = side ? cfeat : vfeat;
    const float* W    = side ? Wic : Wiv;
    const float* b    = side ? bic : biv;
    float* out = g_bufs[side ? 2 : 0];
    __half* out16 = g_h16[side ? 2 : 0];

    int tid = threadIdx.x, wid = tid >> 5, lane = tid & 31;
    int row0 = blk * 128;

    for (int e = tid; e < 32 * 136; e += 256) {
        int k = e / 136, nn = e - k * 136;
        float w = (nn < 128) ? W[nn * FIN + k] : 0.f;
        uint32_t h = pack_bf2(w, 0.f);
        float hf = __uint_as_float(h << 16);
        uint32_t l = pack_bf2(w - hf, 0.f);
        *(unsigned short*)(ism + ISM_BH + k * WSB + nn * 2) = (unsigned short)(h & 0xffff);
        *(unsigned short*)(ism + ISM_BL + k * WSB + nn * 2) = (unsigned short)(l & 0xffff);
    }
    {
        int r = tid >> 1, half = tid & 1;
        int gr = row0 + r;
        char* rowp = ism + ISM_ACT + r * IACT_STR + half * 32;
#pragma unroll
        for (int i = 0; i < 4; i++) {
            float4 v = (gr < n)
                ? reinterpret_cast<const float4*>(feat + (size_t)gr * FIN)[half * 4 + i]
                : make_float4(0.f, 0.f, 0.f, 0.f);
            uint2 hi, lo; split4(v, hi, lo);
            *(uint2*)(rowp + i * 8) = hi;
            *(uint2*)(rowp + IACT_IMG + i * 8) = lo;
        }
    }
    __syncthreads();

    int wm = wid >> 1, wn = wid & 1;
    int rsel = lane & 15, csel = lane >> 4;
    uint32_t aBase = smb + ISM_ACT + (uint32_t)((32 * wm + rsel) * IACT_STR + csel * 16);
    uint32_t bBase = smb + ISM_BH + (uint32_t)(rsel * WSB + csel * 16 + 128 * wn);

    float acc[2][8][4];
#pragma unroll
    for (int mt = 0; mt < 2; mt++)
#pragma unroll
        for (int nt = 0; nt < 8; nt++)
#pragma unroll
            for (int q = 0; q < 4; q++) acc[mt][nt][q] = 0.f;

#pragma unroll
    for (int ks = 0; ks < 2; ks++) {
        uint32_t ahi[2][4], alo[2][4], bhi[4][4], blo[4][4];
#pragma unroll
        for (int mt = 0; mt < 2; mt++) {
            uint32_t ra = aBase + (uint32_t)(16 * mt * IACT_STR + ks * 32);
            ldsm_x4(ahi[mt], ra);
            ldsm_x4(alo[mt], ra + IACT_IMG);
        }
#pragma unroll
        for (int np = 0; np < 4; np++) {
            uint32_t rb = bBase + (uint32_t)(ks * 16 * WSB + 32 * np);
            ldsm_x4t(bhi[np], rb);
            ldsm_x4t(blo[np], rb + (ISM_BL - ISM_BH));
        }
#pragma unroll
        for (int mt = 0; mt < 2; mt++)
#pragma unroll
            for (int nt = 0; nt < 8; nt++)
                mma_bf16(acc[mt][nt], ahi[mt], bhi[nt >> 1][2 * (nt & 1)], bhi[nt >> 1][2 * (nt & 1) + 1]);
#pragma unroll
        for (int mt = 0; mt < 2; mt++)
#pragma unroll
            for (int nt = 0; nt < 8; nt++)
                mma_bf16(acc[mt][nt], ahi[mt], blo[nt >> 1][2 * (nt & 1)], blo[nt >> 1][2 * (nt & 1) + 1]);
#pragma unroll
        for (int mt = 0; mt < 2; mt++)
#pragma unroll
            for (int nt = 0; nt < 8; nt++)
                mma_bf16(acc[mt][nt], alo[mt], bhi[nt >> 1][2 * (nt & 1)], bhi[nt >> 1][2 * (nt & 1) + 1]);
    }

    int r_lo = lane >> 2;
    int cpair = (lane & 3) * 2;
#pragma unroll
    for (int mt = 0; mt < 2; mt++) {
        int ra = row0 + 32 * wm + 16 * mt + r_lo;
#pragma unroll
        for (int nt = 0; nt < 8; nt++) {
            int col = 64 * wn + 8 * nt + cpair;
            float b0 = b[col], b1 = b[col + 1];
            if (ra < n) {
                float2 v = make_float2(acc[mt][nt][0] + b0, acc[mt][nt][1] + b1);
                *(float2*)(out + (size_t)ra * DD + col) = v;
                *(__half2*)(out16 + (size_t)ra * DD + col) = __floats2half2_rn(v.x, v.y);
            }
            if (ra + 8 < n) {
                float2 v = make_float2(acc[mt][nt][2] + b0, acc[mt][nt][3] + b1);
                *(float2*)(out + (size_t)(ra + 8) * DD + col) = v;
                *(__half2*)(out16 + (size_t)(ra + 8) * DD + col) = __floats2half2_rn(v.x, v.y);
            }
        }
    }
}

// ---------------------------------------------------------------------------
// Producer: gather one 288-wide row from the fp16 plane (256B/src-row).
// ---------------------------------------------------------------------------
__device__ __forceinline__ void gather_row(
    const __half* __restrict__ agg16, const float* __restrict__ selfp,
    const float* __restrict__ feat, const int* __restrict__ idx32,
    int gr, int n, int istride, int lane, uint2* G)
{
    bool val = gr < n;
    const int* ip = idx32 + (size_t)(val ? gr : 0) * DEG * istride;
    int srcs[DEG];
#pragma unroll
    for (int j = 0; j < DEG; j++) srcs[j] = ip[j * istride];
    float4 v = make_float4(0.f, 0.f, 0.f, 0.f);
#pragma unroll
    for (int j = 0; j < DEG; j++) {
        uint2 d = reinterpret_cast<const uint2*>(agg16 + (size_t)srcs[j] * DD)[lane];
        __half2 h0 = *reinterpret_cast<__half2*>(&d.x);
        __half2 h1 = *reinterpret_cast<__half2*>(&d.y);
        float2 f0 = __half22float2(h0);
        float2 f1 = __half22float2(h1);
        v.x += f0.x; v.y += f0.y; v.z += f1.x; v.w += f1.y;
    }
    if (!val) v = make_float4(0.f, 0.f, 0.f, 0.f);
    split4(v, G[0], G[1]);
    float4 sv = val
        ? reinterpret_cast<const float4*>(selfp + (size_t)gr * DD)[lane]
        : make_float4(0.f, 0.f, 0.f, 0.f);
    split4(sv, G[2], G[3]);
    float4 fv = (val && lane < 8)
        ? reinterpret_cast<const float4*>(feat + (size_t)gr * FIN)[lane]
        : make_float4(0.f, 0.f, 0.f, 0.f);
    split4(fv, G[4], G[5]);
}

__device__ __forceinline__ void sts_row(char* act, int r, int lane, const uint2* G) {
    char* rowp = act + r * ACT_STR;
    *(uint2*)(rowp + lane * 8) = G[0];
    *(uint2*)(rowp + ACT_IMG + lane * 8) = G[1];
    *(uint2*)(rowp + 256 + lane * 8) = G[2];
    *(uint2*)(rowp + ACT_IMG + 256 + lane * 8) = G[3];
    if (lane < 8) {
        *(uint2*)(rowp + 512 + lane * 8) = G[4];
        *(uint2*)(rowp + ACT_IMG + 512 + lane * 8) = G[5];
    }
}

// ---------------------------------------------------------------------------
// Dual-side warp-specialized layer, 1024 threads. fp16 gather plane.
// When `last` != 0, the V side (side==1) also accumulates the global column
// sum of the final lv into g_colsum (register partials + one flush per warp).
// ---------------------------------------------------------------------------
__global__ __launch_bounds__(1024, 1)
void layer_dual(int lv_sel, int lc_sel, int nlv_sel, int nlc_sel,
                const float* __restrict__ vfeat, const float* __restrict__ cfeat,
                const int* __restrict__ vci, const int* __restrict__ cvi,
                const float* __restrict__ bv, const float* __restrict__ bc,
                int n, int last)
{
    extern __shared__ char sm[];
    uint32_t smb = smem_u32(sm);

    int side = blockIdx.x & 1;   // 0 = C side, 1 = V side
    int blk = blockIdx.x >> 1;

    const __half* agg16; const float* selfp; float* out; __half* out16;
    const float* feat; const int* idx32; const float* b; int which;
    if (side == 0) {
        agg16 = g_h16[lv_sel]; selfp = g_bufs[lc_sel];
        out = g_bufs[nlc_sel]; out16 = g_h16[nlc_sel];
        feat = cfeat; idx32 = cvi; b = bc; which = 1;
    } else {
        agg16 = g_h16[lc_sel]; selfp = g_bufs[lv_sel];
        out = g_bufs[nlv_sel]; out16 = g_h16[nlv_sel];
        feat = vfeat; idx32 = vci; b = bv; which = 0;
    }

    int tid = threadIdx.x, wid = tid >> 5, lane = tid & 31;
    int istride = g_is64 ? 2 : 1;

    {
        const uint4* sh = (const uint4*)g_wh[which];
        const uint4* sl = (const uint4*)g_wl[which];
        uint4* dh = (uint4*)(sm + SM_WHI);
        uint4* dl = (uint4*)(sm + SM_WLO);
        for (int i = tid; i < 78336 / 16; i += 1024) { dh[i] = sh[i]; dl[i] = sl[i]; }
    }
    __syncthreads();

    if (wid >= 16) {
        // ================= PRODUCERS (16 warps, 4 rows each) =================
        int pw = wid - 16;
        char* act = sm + SM_ACT;
        for (int tile = blk; tile < NT64; tile += NBLK_SIDE) {
            int row0 = tile * BM64 + pw * 4;

            uint2 G0[6], G1[6];
            gather_row(agg16, selfp, feat, idx32, row0 + 0, n, istride, lane, G0);
            gather_row(agg16, selfp, feat, idx32, row0 + 1, n, istride, lane, G1);

            BAR_SYNC(2);

            sts_row(act, pw * 4 + 0, lane, G0);
            sts_row(act, pw * 4 + 1, lane, G1);
            gather_row(agg16, selfp, feat, idx32, row0 + 2, n, istride, lane, G0);
            sts_row(act, pw * 4 + 2, lane, G0);
            gather_row(agg16, selfp, feat, idx32, row0 + 3, n, istride, lane, G1);
            sts_row(act, pw * 4 + 3, lane, G1);

            BAR_ARRIVE(1);
        }
    } else {
        // ================= CONSUMERS (16 warps: 4m x 4n) =================
        int wm = wid >> 2, wn = wid & 3;
        int rsel = lane & 15, csel = lane >> 4;
        BAR_ARRIVE(2);

        uint32_t aOff = (uint32_t)((16 * wm + rsel) * ACT_STR + csel * 16);
        uint32_t bBase = smb + SM_WHI + (uint32_t)(rsel * WSB + csel * 16 + 64 * wn);

        int cpair = (lane & 3) * 2;
        float2 bb[4];
#pragma unroll
        for (int nt = 0; nt < 4; nt++) {
            int col = 32 * wn + 8 * nt + cpair;
            bb[nt].x = b[col]; bb[nt].y = b[col + 1];
        }
        int do_cs = last && (side == 1);
        float2 csum[4];
#pragma unroll
        for (int nt = 0; nt < 4; nt++) csum[nt] = make_float2(0.f, 0.f);

        for (int tile = blk; tile < NT64; tile += NBLK_SIDE) {
            BAR_SYNC(1);
            uint32_t aBase = smb + SM_ACT + aOff;

            float acc[4][4];
#pragma unroll
            for (int nt = 0; nt < 4; nt++)
#pragma unroll
                for (int q = 0; q < 4; q++) acc[nt][q] = 0.f;

#pragma unroll 2
            for (int ks = 0; ks < 18; ks++) {
                uint32_t ahi[4], alo[4], bhi[2][4], blo[2][4];
                uint32_t ra = aBase + (uint32_t)(ks * 32);
                ldsm_x4(ahi, ra);
                ldsm_x4(alo, ra + ACT_IMG);
#pragma unroll
                for (int np = 0; np < 2; np++) {
                    uint32_t rb = bBase + (uint32_t)(ks * 16 * WSB + 32 * np);
                    ldsm_x4t(bhi[np], rb);
                    ldsm_x4t(blo[np], rb + (SM_WLO - SM_WHI));
                }
#pragma unroll
                for (int nt = 0; nt < 4; nt++)
                    mma_bf16(acc[nt], ahi, bhi[nt >> 1][2 * (nt & 1)], bhi[nt >> 1][2 * (nt & 1) + 1]);
#pragma unroll
                for (int nt = 0; nt < 4; nt++)
                    mma_bf16(acc[nt], ahi, blo[nt >> 1][2 * (nt & 1)], blo[nt >> 1][2 * (nt & 1) + 1]);
#pragma unroll
                for (int nt = 0; nt < 4; nt++)
                    mma_bf16(acc[nt], alo, bhi[nt >> 1][2 * (nt & 1)], bhi[nt >> 1][2 * (nt & 1) + 1]);
            }
            BAR_ARRIVE(2);

            int row0 = tile * BM64;
            int r_lo = lane >> 2;
            int ra0 = row0 + 16 * wm + r_lo;
#pragma unroll
            for (int nt = 0; nt < 4; nt++) {
                int col = 32 * wn + 8 * nt + cpair;
                if (ra0 < n) {
                    float2 v = make_float2(acc[nt][0] + bb[nt].x, acc[nt][1] + bb[nt].y);
                    *(float2*)(out + (size_t)ra0 * DD + col) = v;
                    *(__half2*)(out16 + (size_t)ra0 * DD + col) = __floats2half2_rn(v.x, v.y);
                    if (do_cs) { csum[nt].x += v.x; csum[nt].y += v.y; }
                }
                if (ra0 + 8 < n) {
                    float2 v = make_float2(acc[nt][2] + bb[nt].x, acc[nt][3] + bb[nt].y);
                    *(float2*)(out + (size_t)(ra0 + 8) * DD + col) = v;
                    *(__half2*)(out16 + (size_t)(ra0 + 8) * DD + col) = __floats2half2_rn(v.x, v.y);
                    if (do_cs) { csum[nt].x += v.x; csum[nt].y += v.y; }
                }
            }
        }

        if (do_cs) {
#pragma unroll
            for (int nt = 0; nt < 4; nt++) {
                float c0 = csum[nt].x, c1 = csum[nt].y;
#pragma unroll
                for (int o = 4; o < 32; o <<= 1) {
                    c0 += __shfl_xor_sync(0xffffffffu, c0, o);
                    c1 += __shfl_xor_sync(0xffffffffu, c1, o);
                }
                if (lane < 4) {
                    int col = 32 * wn + 8 * nt + lane * 2;
                    atomicAdd(&g_colsum[col], c0);
                    atomicAdd(&g_colsum[col + 1], c1);
                }
            }
        }
    }
}

// ---------------------------------------------------------------------------
__global__ void final_kernel(int lv_sel, const float* __restrict__ Wq,
                             const float* __restrict__ bq,
                             float* __restrict__ Q, int n) {
    const float* lv = g_bufs[lv_sel];
    __shared__ float sW[DD];
    __shared__ float s_s;
    int tid = threadIdx.x;
    if (tid < DD) sW[tid] = Wq[DD + tid];
    if (tid < 32) {
        float p = 0.f;
#pragma unroll
        for (int t = 0; t < 4; t++) p += g_colsum[tid + 32 * t] * Wq[tid + 32 * t];
#pragma unroll
        for (int o = 16; o > 0; o >>= 1) p += __shfl_xor_sync(0xffffffffu, p, o);
        if (tid == 0) s_s = p + bq[0];
    }
    __syncthreads();
    int warp = tid >> 5, lane = tid & 31;
    int base = blockIdx.x * 64 + warp * 8;
    for (int i = 0; i < 8; i++) {
        int row = base + i;
        if (row >= n) break;
        const float* rp = lv + (size_t)row * DD;
        float p = rp[lane]      * sW[lane]
                + rp[lane + 32] * sW[lane + 32]
                + rp[lane + 64] * sW[lane + 64]
                + rp[lane + 96] * sW[lane + 96];
#pragma unroll
        for (int o = 16; o > 0; o >>= 1) p += __shfl_xor_sync(0xffffffffu, p, o);
        if (lane == 0) Q[row] = s_s + p;
    }
}

// ---------------------------------------------------------------------------
extern "C" void kernel_launch(void* const* d_in, const int* in_sizes, int n_in,
                              void* d_out, int out_size) {
    const float* x    = (const float*)d_in[0];
    const int*   vci  = (const int*)d_in[1];
    const int*   cvi  = (const int*)d_in[2];
    const float* W_iv = (const float*)d_in[3];
    const float* b_iv = (const float*)d_in[4];
    const float* W_ic = (const float*)d_in[5];
    const float* b_ic = (const float*)d_in[6];
    const float* W_v  = (const float*)d_in[7];
    const float* b_v  = (const float*)d_in[8];
    const float* W_c  = (const float*)d_in[9];
    const float* b_c  = (const float*)d_in[10];
    const float* W_q  = (const float*)d_in[11];
    const float* b_q  = (const float*)d_in[12];
    float* Q = (float*)d_out;

    cudaFuncSetAttribute(layer_dual,
                         cudaFuncAttributeMaxDynamicSharedMemorySize, SM_DYN);

    const float* var_feat = x;
    const float* con_feat = x + (size_t)NVV * FIN;

    prep_w<<<3, 256>>>(W_v, W_c, vci);
    init_mma<<<2 * NB_INIT, 256>>>(var_feat, con_feat, W_iv, W_ic, b_iv, b_ic, NVV);

    int lv = 0, lc = 2;
    for (int t = 0; t < 3; t++) {
        int nlc = 5 - lc, nlv = 1 - lv;
        layer_dual<<<GRID_TC, 1024, SM_DYN>>>(lv, lc, nlv, nlc,
                                              var_feat, con_feat, vci, cvi,
                                              b_v, b_c, NVV, t == 2);
        lv = nlv; lc = nlc;
    }

    final_kernel<<<(NVV + 63) / 64, 256>>>(lv, W_q, b_q, Q, NVV);
}

// round 11
// speedup vs baseline: 1.2711x; 1.1551x over previous
#include <cuda_runtime.h>
#include <cuda_bf16.h>
#include <cuda_fp16.h>
#include <cstdint>

#define NVV 50000
#define DD 128
#define FIN 32
#define DEG 16
#define INDIM 288
#define GRID_TC 152
#define NBLK_SIDE (GRID_TC / 2)

#define BM32 32
#define NT32 ((NVV + BM32 - 1) / BM32)   // 1563

#define WSB 272
#define ACT_STR 592
#define ACT_IMG (32 * ACT_STR)            // 18944
#define ACT_SLAB (2 * ACT_IMG)            // 37888 (hi|lo)

#define SM_WHI 0
#define SM_WLO 78336
#define SM_ACT 156672
#define SM_DYN (SM_ACT + 2 * ACT_SLAB)    // 232448 == opt-in max

// named barriers: 1+slot = full, 3+slot = empty
#define BAR_SYNC(id)   asm volatile("bar.sync %0, 1024;"   :: "r"(id) : "memory")
#define BAR_ARRIVE(id) asm volatile("bar.arrive %0, 1024;" :: "r"(id) : "memory")

// ---------------------------------------------------------------------------
__device__ __align__(16) unsigned short g_wh[2][288 * 136];
__device__ __align__(16) unsigned short g_wl[2][288 * 136];
__device__ __align__(256) float g_lv32[(size_t)NVV * DD];      // final lv only
__device__ __align__(256) __half g_h16[4][(size_t)NVV * DD];   // fp16 activations
__device__ float g_colsum[DD];
__device__ int g_is64;

__device__ __forceinline__ uint32_t smem_u32(const void* p) {
    uint32_t a;
    asm("{ .reg .u64 t; cvta.to.shared.u64 t, %1; cvt.u32.u64 %0, t; }" : "=r"(a) : "l"(p));
    return a;
}
__device__ __forceinline__ void ldsm_x4(uint32_t* r, uint32_t addr) {
    asm volatile("ldmatrix.sync.aligned.m8n8.x4.shared.b16 {%0,%1,%2,%3}, [%4];"
                 : "=r"(r[0]), "=r"(r[1]), "=r"(r[2]), "=r"(r[3]) : "r"(addr));
}
__device__ __forceinline__ void ldsm_x4t(uint32_t* r, uint32_t addr) {
    asm volatile("ldmatrix.sync.aligned.m8n8.x4.trans.shared.b16 {%0,%1,%2,%3}, [%4];"
                 : "=r"(r[0]), "=r"(r[1]), "=r"(r[2]), "=r"(r[3]) : "r"(addr));
}
__device__ __forceinline__ void mma_bf16(float* d, const uint32_t* a, uint32_t b0, uint32_t b1) {
    asm volatile("mma.sync.aligned.m16n8k16.row.col.f32.bf16.bf16.f32 "
                 "{%0,%1,%2,%3}, {%4,%5,%6,%7}, {%8,%9}, {%0,%1,%2,%3};"
                 : "+f"(d[0]), "+f"(d[1]), "+f"(d[2]), "+f"(d[3])
                 : "r"(a[0]), "r"(a[1]), "r"(a[2]), "r"(a[3]), "r"(b0), "r"(b1));
}
__device__ __forceinline__ uint32_t pack_bf2(float a, float b) {
    uint32_t r;
    asm("cvt.rn.bf16x2.f32 %0, %1, %2;" : "=r"(r) : "f"(b), "f"(a));
    return r;
}
__device__ __forceinline__ void split4(float4 v, uint2& hi, uint2& lo) {
    uint32_t h01 = pack_bf2(v.x, v.y);
    uint32_t h23 = pack_bf2(v.z, v.w);
    float hx = __uint_as_float(h01 << 16);
    float hy = __uint_as_float(h01 & 0xffff0000u);
    float hz = __uint_as_float(h23 << 16);
    float hw = __uint_as_float(h23 & 0xffff0000u);
    hi.x = h01; hi.y = h23;
    lo.x = pack_bf2(v.x - hx, v.y - hy);
    lo.y = pack_bf2(v.z - hz, v.w - hw);
}
__device__ __forceinline__ float4 h16_row4(const __half* p, int lane) {
    uint2 d = reinterpret_cast<const uint2*>(p)[lane];
    __half2 h0 = *reinterpret_cast<__half2*>(&d.x);
    __half2 h1 = *reinterpret_cast<__half2*>(&d.y);
    float2 f0 = __half22float2(h0);
    float2 f1 = __half22float2(h1);
    return make_float4(f0.x, f0.y, f1.x, f1.y);
}

// ---------------------------------------------------------------------------
__global__ void prep_w(const float* __restrict__ Wv, const float* __restrict__ Wc,
                       const int* __restrict__ idx32) {
    int which = blockIdx.x;
    if (which == 2) {
        if (threadIdx.x == 0) {
            int nz = 0;
#pragma unroll
            for (int i = 0; i < 64; i++) nz |= idx32[2 * i + 1];
            g_is64 = (nz == 0) ? 1 : 0;
        }
        if (threadIdx.x < DD) g_colsum[threadIdx.x] = 0.f;
        return;
    }
    const float* W = which ? Wc : Wv;
    for (int e = threadIdx.x; e < 288 * 136; e += blockDim.x) {
        int k = e / 136, nn = e - k * 136;
        float w = (nn < 128) ? W[nn * INDIM + k] : 0.f;
        uint32_t h = pack_bf2(w, 0.f);
        float hf = __uint_as_float(h << 16);
        uint32_t l = pack_bf2(w - hf, 0.f);
        g_wh[which][e] = (unsigned short)(h & 0xffff);
        g_wl[which][e] = (unsigned short)(l & 0xffff);
    }
}

// ---------------------------------------------------------------------------
// HMMA initial embedding -> fp16 plane only.
// ---------------------------------------------------------------------------
#define ISM_BH 0
#define ISM_BL 8704
#define ISM_ACT 17408
#define IACT_STR 80
#define IACT_IMG (128 * IACT_STR)
#define NB_INIT ((NVV + 127) / 128)

__global__ __launch_bounds__(256, 1)
void init_mma(const float* __restrict__ vfeat, const float* __restrict__ cfeat,
              const float* __restrict__ Wiv, const float* __restrict__ Wic,
              const float* __restrict__ biv, const float* __restrict__ bic, int n) {
    __shared__ __align__(16) char ism[ISM_ACT + 2 * IACT_IMG];
    uint32_t smb = smem_u32(ism);
    int side = blockIdx.x & 1;
    int blk = blockIdx.x >> 1;
    const float* feat = side ? cfeat : vfeat;
    const float* W    = side ? Wic : Wiv;
    const float* b    = side ? bic : biv;
    __half* out16 = g_h16[side ? 2 : 0];

    int tid = threadIdx.x, wid = tid >> 5, lane = tid & 31;
    int row0 = blk * 128;

    for (int e = tid; e < 32 * 136; e += 256) {
        int k = e / 136, nn = e - k * 136;
        float w = (nn < 128) ? W[nn * FIN + k] : 0.f;
        uint32_t h = pack_bf2(w, 0.f);
        float hf = __uint_as_float(h << 16);
        uint32_t l = pack_bf2(w - hf, 0.f);
        *(unsigned short*)(ism + ISM_BH + k * WSB + nn * 2) = (unsigned short)(h & 0xffff);
        *(unsigned short*)(ism + ISM_BL + k * WSB + nn * 2) = (unsigned short)(l & 0xffff);
    }
    {
        int r = tid >> 1, half = tid & 1;
        int gr = row0 + r;
        char* rowp = ism + ISM_ACT + r * IACT_STR + half * 32;
#pragma unroll
        for (int i = 0; i < 4; i++) {
            float4 v = (gr < n)
                ? reinterpret_cast<const float4*>(feat + (size_t)gr * FIN)[half * 4 + i]
                : make_float4(0.f, 0.f, 0.f, 0.f);
            uint2 hi, lo; split4(v, hi, lo);
            *(uint2*)(rowp + i * 8) = hi;
            *(uint2*)(rowp + IACT_IMG + i * 8) = lo;
        }
    }
    __syncthreads();

    int wm = wid >> 1, wn = wid & 1;
    int rsel = lane & 15, csel = lane >> 4;
    uint32_t aBase = smb + ISM_ACT + (uint32_t)((32 * wm + rsel) * IACT_STR + csel * 16);
    uint32_t bBase = smb + ISM_BH + (uint32_t)(rsel * WSB + csel * 16 + 128 * wn);

    float acc[2][8][4];
#pragma unroll
    for (int mt = 0; mt < 2; mt++)
#pragma unroll
        for (int nt = 0; nt < 8; nt++)
#pragma unroll
            for (int q = 0; q < 4; q++) acc[mt][nt][q] = 0.f;

#pragma unroll
    for (int ks = 0; ks < 2; ks++) {
        uint32_t ahi[2][4], alo[2][4], bhi[4][4], blo[4][4];
#pragma unroll
        for (int mt = 0; mt < 2; mt++) {
            uint32_t ra = aBase + (uint32_t)(16 * mt * IACT_STR + ks * 32);
            ldsm_x4(ahi[mt], ra);
            ldsm_x4(alo[mt], ra + IACT_IMG);
        }
#pragma unroll
        for (int np = 0; np < 4; np++) {
            uint32_t rb = bBase + (uint32_t)(ks * 16 * WSB + 32 * np);
            ldsm_x4t(bhi[np], rb);
            ldsm_x4t(blo[np], rb + (ISM_BL - ISM_BH));
        }
#pragma unroll
        for (int mt = 0; mt < 2; mt++)
#pragma unroll
            for (int nt = 0; nt < 8; nt++)
                mma_bf16(acc[mt][nt], ahi[mt], bhi[nt >> 1][2 * (nt & 1)], bhi[nt >> 1][2 * (nt & 1) + 1]);
#pragma unroll
        for (int mt = 0; mt < 2; mt++)
#pragma unroll
            for (int nt = 0; nt < 8; nt++)
                mma_bf16(acc[mt][nt], ahi[mt], blo[nt >> 1][2 * (nt & 1)], blo[nt >> 1][2 * (nt & 1) + 1]);
#pragma unroll
        for (int mt = 0; mt < 2; mt++)
#pragma unroll
            for (int nt = 0; nt < 8; nt++)
                mma_bf16(acc[mt][nt], alo[mt], bhi[nt >> 1][2 * (nt & 1)], bhi[nt >> 1][2 * (nt & 1) + 1]);
    }

    int r_lo = lane >> 2;
    int cpair = (lane & 3) * 2;
#pragma unroll
    for (int mt = 0; mt < 2; mt++) {
        int ra = row0 + 32 * wm + 16 * mt + r_lo;
#pragma unroll
        for (int nt = 0; nt < 8; nt++) {
            int col = 64 * wn + 8 * nt + cpair;
            float b0 = b[col], b1 = b[col + 1];
            if (ra < n)
                *(__half2*)(out16 + (size_t)ra * DD + col) =
                    __floats2half2_rn(acc[mt][nt][0] + b0, acc[mt][nt][1] + b1);
            if (ra + 8 < n)
                *(__half2*)(out16 + (size_t)(ra + 8) * DD + col) =
                    __floats2half2_rn(acc[mt][nt][2] + b0, acc[mt][nt][3] + b1);
        }
    }
}

// ---------------------------------------------------------------------------
// Producer: one 288-wide row, agg + self from fp16 planes, feat fp32.
// ---------------------------------------------------------------------------
__device__ __forceinline__ void gather_row(
    const __half* __restrict__ agg16, const __half* __restrict__ self16,
    const float* __restrict__ feat, const int* __restrict__ idx32,
    int gr, int n, int istride, int lane, uint2* G)
{
    bool val = gr < n;
    const int* ip = idx32 + (size_t)(val ? gr : 0) * DEG * istride;
    int srcs[DEG];
#pragma unroll
    for (int j = 0; j < DEG; j++) srcs[j] = ip[j * istride];
    float4 v = make_float4(0.f, 0.f, 0.f, 0.f);
#pragma unroll
    for (int j = 0; j < DEG; j++) {
        float4 t = h16_row4(agg16 + (size_t)srcs[j] * DD, lane);
        v.x += t.x; v.y += t.y; v.z += t.z; v.w += t.w;
    }
    if (!val) v = make_float4(0.f, 0.f, 0.f, 0.f);
    split4(v, G[0], G[1]);
    float4 sv = val ? h16_row4(self16 + (size_t)gr * DD, lane)
                    : make_float4(0.f, 0.f, 0.f, 0.f);
    split4(sv, G[2], G[3]);
    float4 fv = (val && lane < 8)
        ? reinterpret_cast<const float4*>(feat + (size_t)gr * FIN)[lane]
        : make_float4(0.f, 0.f, 0.f, 0.f);
    split4(fv, G[4], G[5]);
}

__device__ __forceinline__ void sts_row(char* act, int r, int lane, const uint2* G) {
    char* rowp = act + r * ACT_STR;
    *(uint2*)(rowp + lane * 8) = G[0];
    *(uint2*)(rowp + ACT_IMG + lane * 8) = G[1];
    *(uint2*)(rowp + 256 + lane * 8) = G[2];
    *(uint2*)(rowp + ACT_IMG + 256 + lane * 8) = G[3];
    if (lane < 8) {
        *(uint2*)(rowp + 512 + lane * 8) = G[4];
        *(uint2*)(rowp + ACT_IMG + 512 + lane * 8) = G[5];
    }
}

// ---------------------------------------------------------------------------
// Dual-side warp-specialized layer: 1024 threads, 32-row slabs, 2-slot ring.
// Producers (warps 16-31, 2 rows each) pre-gather EVERYTHING before the
// empty-wait -> gather fully overlaps consumer MMA.
// Consumers (warps 0-15, 2m x 8n, 16x16 tiles).
// last!=0: V side writes fp32 lv master + accumulates colsum.
// ---------------------------------------------------------------------------
__global__ __launch_bounds__(1024, 1)
void layer_dual(int lv_sel, int lc_sel, int nlv_sel, int nlc_sel,
                const float* __restrict__ vfeat, const float* __restrict__ cfeat,
                const int* __restrict__ vci, const int* __restrict__ cvi,
                const float* __restrict__ bv, const float* __restrict__ bc,
                int n, int last)
{
    extern __shared__ char sm[];
    uint32_t smb = smem_u32(sm);

    int side = blockIdx.x & 1;
    int blk = blockIdx.x >> 1;

    const __half* agg16; const __half* self16; __half* out16;
    const float* feat; const int* idx32; const float* b; int which;
    if (side == 0) {
        agg16 = g_h16[lv_sel]; self16 = g_h16[lc_sel]; out16 = g_h16[nlc_sel];
        feat = cfeat; idx32 = cvi; b = bc; which = 1;
    } else {
        agg16 = g_h16[lc_sel]; self16 = g_h16[lv_sel]; out16 = g_h16[nlv_sel];
        feat = vfeat; idx32 = vci; b = bv; which = 0;
    }

    int tid = threadIdx.x, wid = tid >> 5, lane = tid & 31;
    int istride = g_is64 ? 2 : 1;

    {
        const uint4* sh = (const uint4*)g_wh[which];
        const uint4* sl = (const uint4*)g_wl[which];
        uint4* dh = (uint4*)(sm + SM_WHI);
        uint4* dl = (uint4*)(sm + SM_WLO);
        for (int i = tid; i < 78336 / 16; i += 1024) { dh[i] = sh[i]; dl[i] = sl[i]; }
    }
    __syncthreads();

    if (wid >= 16) {
        // ================= PRODUCERS (16 warps, 2 rows each) =================
        int pw = wid - 16;
        int it = 0;
        for (int tile = blk; tile < NT32; tile += NBLK_SIDE, it++) {
            int slot = it & 1;
            int row0 = tile * BM32 + pw * 2;

            uint2 G0[6], G1[6];
            gather_row(agg16, self16, feat, idx32, row0 + 0, n, istride, lane, G0);
            gather_row(agg16, self16, feat, idx32, row0 + 1, n, istride, lane, G1);

            BAR_SYNC(3 + slot);        // wait slot empty
            char* act = sm + SM_ACT + slot * ACT_SLAB;
            sts_row(act, pw * 2 + 0, lane, G0);
            sts_row(act, pw * 2 + 1, lane, G1);
            BAR_ARRIVE(1 + slot);      // mark full
        }
    } else {
        // ================= CONSUMERS (16 warps: 2m x 8n, 16x16) =============
        int wm = wid >> 3, wn = wid & 7;
        int rsel = lane & 15, csel = lane >> 4;
        BAR_ARRIVE(3); BAR_ARRIVE(4);  // prime both slots empty

        uint32_t aOff = (uint32_t)((16 * wm + rsel) * ACT_STR + csel * 16);
        uint32_t bBase = smb + SM_WHI + (uint32_t)(rsel * WSB + csel * 16 + 32 * wn);

        int cpair = (lane & 3) * 2;
        float2 bb[2];
#pragma unroll
        for (int nt = 0; nt < 2; nt++) {
            int col = 16 * wn + 8 * nt + cpair;
            bb[nt].x = b[col]; bb[nt].y = b[col + 1];
        }
        int do32 = last && (side == 1);
        float2 csum[2];
#pragma unroll
        for (int nt = 0; nt < 2; nt++) csum[nt] = make_float2(0.f, 0.f);

        int it = 0;
        for (int tile = blk; tile < NT32; tile += NBLK_SIDE, it++) {
            int slot = it & 1;
            BAR_SYNC(1 + slot);        // wait full
            uint32_t aBase = smb + SM_ACT + (uint32_t)(slot * ACT_SLAB) + aOff;

            float acc[2][4];
#pragma unroll
            for (int nt = 0; nt < 2; nt++)
#pragma unroll
                for (int q = 0; q < 4; q++) acc[nt][q] = 0.f;

#pragma unroll 3
            for (int ks = 0; ks < 18; ks++) {
                uint32_t ahi[4], alo[4], bhi[4], blo[4];
                uint32_t ra = aBase + (uint32_t)(ks * 32);
                ldsm_x4(ahi, ra);
                ldsm_x4(alo, ra + ACT_IMG);
                uint32_t rb = bBase + (uint32_t)(ks * 16 * WSB);
                ldsm_x4t(bhi, rb);
                ldsm_x4t(blo, rb + (SM_WLO - SM_WHI));
#pragma unroll
                for (int nt = 0; nt < 2; nt++)
                    mma_bf16(acc[nt], ahi, bhi[2 * nt], bhi[2 * nt + 1]);
#pragma unroll
                for (int nt = 0; nt < 2; nt++)
                    mma_bf16(acc[nt], ahi, blo[2 * nt], blo[2 * nt + 1]);
#pragma unroll
                for (int nt = 0; nt < 2; nt++)
                    mma_bf16(acc[nt], alo, bhi[2 * nt], bhi[2 * nt + 1]);
            }
            BAR_ARRIVE(3 + slot);      // slot free

            // epilogue
            int row0 = tile * BM32;
            int r_lo = lane >> 2;
            int ra0 = row0 + 16 * wm + r_lo;
#pragma unroll
            for (int nt = 0; nt < 2; nt++) {
                int col = 16 * wn + 8 * nt + cpair;
                if (ra0 < n) {
                    float v0 = acc[nt][0] + bb[nt].x, v1 = acc[nt][1] + bb[nt].y;
                    *(__half2*)(out16 + (size_t)ra0 * DD + col) = __floats2half2_rn(v0, v1);
                    if (do32) {
                        *(float2*)(g_lv32 + (size_t)ra0 * DD + col) = make_float2(v0, v1);
                        csum[nt].x += v0; csum[nt].y += v1;
                    }
                }
                if (ra0 + 8 < n) {
                    float v0 = acc[nt][2] + bb[nt].x, v1 = acc[nt][3] + bb[nt].y;
                    *(__half2*)(out16 + (size_t)(ra0 + 8) * DD + col) = __floats2half2_rn(v0, v1);
                    if (do32) {
                        *(float2*)(g_lv32 + (size_t)(ra0 + 8) * DD + col) = make_float2(v0, v1);
                        csum[nt].x += v0; csum[nt].y += v1;
                    }
                }
            }
        }

        if (do32) {
#pragma unroll
            for (int nt = 0; nt < 2; nt++) {
                float c0 = csum[nt].x, c1 = csum[nt].y;
#pragma unroll
                for (int o = 4; o < 32; o <<= 1) {
                    c0 += __shfl_xor_sync(0xffffffffu, c0, o);
                    c1 += __shfl_xor_sync(0xffffffffu, c1, o);
                }
                if (lane < 4) {
                    int col = 16 * wn + 8 * nt + lane * 2;
                    atomicAdd(&g_colsum[col], c0);
                    atomicAdd(&g_colsum[col + 1], c1);
                }
            }
        }
    }
}

// ---------------------------------------------------------------------------
__global__ void final_kernel(const float* __restrict__ Wq,
                             const float* __restrict__ bq,
                             float* __restrict__ Q, int n) {
    const float* lv = g_lv32;
    __shared__ float sW[DD];
    __shared__ float s_s;
    int tid = threadIdx.x;
    if (tid < DD) sW[tid] = Wq[DD + tid];
    if (tid < 32) {
        float p = 0.f;
#pragma unroll
        for (int t = 0; t < 4; t++) p += g_colsum[tid + 32 * t] * Wq[tid + 32 * t];
#pragma unroll
        for (int o = 16; o > 0; o >>= 1) p += __shfl_xor_sync(0xffffffffu, p, o);
        if (tid == 0) s_s = p + bq[0];
    }
    __syncthreads();
    int warp = tid >> 5, lane = tid & 31;
    int base = blockIdx.x * 64 + warp * 8;
    for (int i = 0; i < 8; i++) {
        int row = base + i;
        if (row >= n) break;
        const float* rp = lv + (size_t)row * DD;
        float p = rp[lane]      * sW[lane]
                + rp[lane + 32] * sW[lane + 32]
                + rp[lane + 64] * sW[lane + 64]
                + rp[lane + 96] * sW[lane + 96];
#pragma unroll
        for (int o = 16; o > 0; o >>= 1) p += __shfl_xor_sync(0xffffffffu, p, o);
        if (lane == 0) Q[row] = s_s + p;
    }
}

// ---------------------------------------------------------------------------
extern "C" void kernel_launch(void* const* d_in, const int* in_sizes, int n_in,
                              void* d_out, int out_size) {
    const float* x    = (const float*)d_in[0];
    const int*   vci  = (const int*)d_in[1];
    const int*   cvi  = (const int*)d_in[2];
    const float* W_iv = (const float*)d_in[3];
    const float* b_iv = (const float*)d_in[4];
    const float* W_ic = (const float*)d_in[5];
    const float* b_ic = (const float*)d_in[6];
    const float* W_v  = (const float*)d_in[7];
    const float* b_v  = (const float*)d_in[8];
    const float* W_c  = (const float*)d_in[9];
    const float* b_c  = (const float*)d_in[10];
    const float* W_q  = (const float*)d_in[11];
    const float* b_q  = (const float*)d_in[12];
    float* Q = (float*)d_out;

    cudaFuncSetAttribute(layer_dual,
                         cudaFuncAttributeMaxDynamicSharedMemorySize, SM_DYN);

    const float* var_feat = x;
    const float* con_feat = x + (size_t)NVV * FIN;

    prep_w<<<3, 256>>>(W_v, W_c, vci);
    init_mma<<<2 * NB_INIT, 256>>>(var_feat, con_feat, W_iv, W_ic, b_iv, b_ic, NVV);

    int lv = 0, lc = 2;
    for (int t = 0; t < 3; t++) {
        int nlc = 5 - lc, nlv = 1 - lv;
        layer_dual<<<GRID_TC, 1024, SM_DYN>>>(lv, lc, nlv, nlc,
                                              var_feat, con_feat, vci, cvi,
                                              b_v, b_c, NVV, t == 2);
        lv = nlv; lc = nlc;
    }

    final_kernel<<<(NVV + 63) / 64, 256>>>(W_q, b_q, Q, NVV);
}

// round 12
// speedup vs baseline: 1.4703x; 1.1567x over previous
#include <cuda_runtime.h>
#include <cuda_fp16.h>
#include <cstdint>

#define NVV 50000
#define DD 128
#define FIN 32
#define DEG 16
#define INDIM 288
#define GRID_TC 152
#define NBLK_SIDE (GRID_TC / 2)

#define BM32 32
#define NT32 ((NVV + BM32 - 1) / BM32)   // 1563
#define NSLOT 4

#define WSB 272
#define ACT_STR 592
#define ACT_IMG (32 * ACT_STR)            // 18944 (single fp16 image)

#define SM_W16 0
#define SM_ACT 78336
#define SM_DYN (SM_ACT + NSLOT * ACT_IMG) // 154112

// named barriers: 1+slot = full, 5+slot = empty (slots 0..3)
#define BAR_SYNC(id)   asm volatile("bar.sync %0, 1024;"   :: "r"(id) : "memory")
#define BAR_ARRIVE(id) asm volatile("bar.arrive %0, 1024;" :: "r"(id) : "memory")

// ---------------------------------------------------------------------------
__device__ __align__(16) unsigned short g_w16[2][288 * 136];
__device__ __align__(256) float g_lv32[(size_t)NVV * DD];      // final lv only
__device__ __align__(256) __half g_h16[4][(size_t)NVV * DD];   // fp16 activations
__device__ float g_colsum[DD];
__device__ int g_is64;

__device__ __forceinline__ uint32_t smem_u32(const void* p) {
    uint32_t a;
    asm("{ .reg .u64 t; cvta.to.shared.u64 t, %1; cvt.u32.u64 %0, t; }" : "=r"(a) : "l"(p));
    return a;
}
__device__ __forceinline__ void ldsm_x4(uint32_t* r, uint32_t addr) {
    asm volatile("ldmatrix.sync.aligned.m8n8.x4.shared.b16 {%0,%1,%2,%3}, [%4];"
                 : "=r"(r[0]), "=r"(r[1]), "=r"(r[2]), "=r"(r[3]) : "r"(addr));
}
__device__ __forceinline__ void ldsm_x4t(uint32_t* r, uint32_t addr) {
    asm volatile("ldmatrix.sync.aligned.m8n8.x4.trans.shared.b16 {%0,%1,%2,%3}, [%4];"
                 : "=r"(r[0]), "=r"(r[1]), "=r"(r[2]), "=r"(r[3]) : "r"(addr));
}
__device__ __forceinline__ void mma_f16(float* d, const uint32_t* a, uint32_t b0, uint32_t b1) {
    asm volatile("mma.sync.aligned.m16n8k16.row.col.f32.f16.f16.f32 "
                 "{%0,%1,%2,%3}, {%4,%5,%6,%7}, {%8,%9}, {%0,%1,%2,%3};"
                 : "+f"(d[0]), "+f"(d[1]), "+f"(d[2]), "+f"(d[3])
                 : "r"(a[0]), "r"(a[1]), "r"(a[2]), "r"(a[3]), "r"(b0), "r"(b1));
}
__device__ __forceinline__ uint32_t pack_h2(float lo, float hi) {
    __half2 h = __floats2half2_rn(lo, hi);
    return *reinterpret_cast<uint32_t*>(&h);
}
__device__ __forceinline__ uint2 pack4_h(float4 v) {
    uint2 r;
    r.x = pack_h2(v.x, v.y);
    r.y = pack_h2(v.z, v.w);
    return r;
}
__device__ __forceinline__ float4 h16_row4(const __half* p, int lane) {
    uint2 d = reinterpret_cast<const uint2*>(p)[lane];
    __half2 h0 = *reinterpret_cast<__half2*>(&d.x);
    __half2 h1 = *reinterpret_cast<__half2*>(&d.y);
    float2 f0 = __half22float2(h0);
    float2 f1 = __half22float2(h1);
    return make_float4(f0.x, f0.y, f1.x, f1.y);
}

// ---------------------------------------------------------------------------
__global__ void prep_w(const float* __restrict__ Wv, const float* __restrict__ Wc,
                       const int* __restrict__ idx32) {
    int which = blockIdx.x;
    if (which == 2) {
        if (threadIdx.x == 0) {
            int nz = 0;
#pragma unroll
            for (int i = 0; i < 64; i++) nz |= idx32[2 * i + 1];
            g_is64 = (nz == 0) ? 1 : 0;
        }
        if (threadIdx.x < DD) g_colsum[threadIdx.x] = 0.f;
        return;
    }
    const float* W = which ? Wc : Wv;
    for (int e = threadIdx.x; e < 288 * 136; e += blockDim.x) {
        int k = e / 136, nn = e - k * 136;
        float w = (nn < 128) ? W[nn * INDIM + k] : 0.f;
        __half h = __float2half_rn(w);
        g_w16[which][e] = *reinterpret_cast<unsigned short*>(&h);
    }
}

// ---------------------------------------------------------------------------
// HMMA initial embedding, fp16 single-term, dual-side merged.
// ---------------------------------------------------------------------------
#define ISM_B 0
#define ISM_ACT 8704
#define IACT_STR 80
#define NB_INIT ((NVV + 127) / 128)

__global__ __launch_bounds__(256, 1)
void init_mma(const float* __restrict__ vfeat, const float* __restrict__ cfeat,
              const float* __restrict__ Wiv, const float* __restrict__ Wic,
              const float* __restrict__ biv, const float* __restrict__ bic, int n) {
    __shared__ __align__(16) char ism[ISM_ACT + 128 * IACT_STR];  // 18944 B
    uint32_t smb = smem_u32(ism);
    int side = blockIdx.x & 1;
    int blk = blockIdx.x >> 1;
    const float* feat = side ? cfeat : vfeat;
    const float* W    = side ? Wic : Wiv;
    const float* b    = side ? bic : biv;
    __half* out16 = g_h16[side ? 2 : 0];

    int tid = threadIdx.x, wid = tid >> 5, lane = tid & 31;
    int row0 = blk * 128;

    for (int e = tid; e < 32 * 136; e += 256) {
        int k = e / 136, nn = e - k * 136;
        float w = (nn < 128) ? W[nn * FIN + k] : 0.f;
        __half h = __float2half_rn(w);
        *(unsigned short*)(ism + ISM_B + k * WSB + nn * 2) =
            *reinterpret_cast<unsigned short*>(&h);
    }
    {
        int r = tid >> 1, half = tid & 1;
        int gr = row0 + r;
        char* rowp = ism + ISM_ACT + r * IACT_STR + half * 32;
#pragma unroll
        for (int i = 0; i < 4; i++) {
            float4 v = (gr < n)
                ? reinterpret_cast<const float4*>(feat + (size_t)gr * FIN)[half * 4 + i]
                : make_float4(0.f, 0.f, 0.f, 0.f);
            *(uint2*)(rowp + i * 8) = pack4_h(v);
        }
    }
    __syncthreads();

    int wm = wid >> 1, wn = wid & 1;
    int rsel = lane & 15, csel = lane >> 4;
    uint32_t aBase = smb + ISM_ACT + (uint32_t)((32 * wm + rsel) * IACT_STR + csel * 16);
    uint32_t bBase = smb + ISM_B + (uint32_t)(rsel * WSB + csel * 16 + 128 * wn);

    float acc[2][8][4];
#pragma unroll
    for (int mt = 0; mt < 2; mt++)
#pragma unroll
        for (int nt = 0; nt < 8; nt++)
#pragma unroll
            for (int q = 0; q < 4; q++) acc[mt][nt][q] = 0.f;

#pragma unroll
    for (int ks = 0; ks < 2; ks++) {
        uint32_t a[2][4], bf[4][4];
#pragma unroll
        for (int mt = 0; mt < 2; mt++)
            ldsm_x4(a[mt], aBase + (uint32_t)(16 * mt * IACT_STR + ks * 32));
#pragma unroll
        for (int np = 0; np < 4; np++)
            ldsm_x4t(bf[np], bBase + (uint32_t)(ks * 16 * WSB + 32 * np));
#pragma unroll
        for (int mt = 0; mt < 2; mt++)
#pragma unroll
            for (int nt = 0; nt < 8; nt++)
                mma_f16(acc[mt][nt], a[mt], bf[nt >> 1][2 * (nt & 1)], bf[nt >> 1][2 * (nt & 1) + 1]);
    }

    int r_lo = lane >> 2;
    int cpair = (lane & 3) * 2;
#pragma unroll
    for (int mt = 0; mt < 2; mt++) {
        int ra = row0 + 32 * wm + 16 * mt + r_lo;
#pragma unroll
        for (int nt = 0; nt < 8; nt++) {
            int col = 64 * wn + 8 * nt + cpair;
            float b0 = b[col], b1 = b[col + 1];
            if (ra < n)
                *(__half2*)(out16 + (size_t)ra * DD + col) =
                    __floats2half2_rn(acc[mt][nt][0] + b0, acc[mt][nt][1] + b1);
            if (ra + 8 < n)
                *(__half2*)(out16 + (size_t)(ra + 8) * DD + col) =
                    __floats2half2_rn(acc[mt][nt][2] + b0, acc[mt][nt][3] + b1);
        }
    }
}

// ---------------------------------------------------------------------------
// Producer: one 288-wide row -> 3 uint2 (fp16 pairs): agg, self, feat.
// ---------------------------------------------------------------------------
__device__ __forceinline__ void gather_row(
    const __half* __restrict__ agg16, const __half* __restrict__ self16,
    const float* __restrict__ feat, const int* __restrict__ idx32,
    int gr, int n, int istride, int lane, uint2* G)
{
    bool val = gr < n;
    const int* ip = idx32 + (size_t)(val ? gr : 0) * DEG * istride;
    int srcs[DEG];
#pragma unroll
    for (int j = 0; j < DEG; j++) srcs[j] = ip[j * istride];
    float4 v = make_float4(0.f, 0.f, 0.f, 0.f);
#pragma unroll
    for (int j = 0; j < DEG; j++) {
        float4 t = h16_row4(agg16 + (size_t)srcs[j] * DD, lane);
        v.x += t.x; v.y += t.y; v.z += t.z; v.w += t.w;
    }
    if (!val) v = make_float4(0.f, 0.f, 0.f, 0.f);
    G[0] = pack4_h(v);
    float4 sv = val ? h16_row4(self16 + (size_t)gr * DD, lane)
                    : make_float4(0.f, 0.f, 0.f, 0.f);
    G[1] = pack4_h(sv);
    float4 fv = (val && lane < 8)
        ? reinterpret_cast<const float4*>(feat + (size_t)gr * FIN)[lane]
        : make_float4(0.f, 0.f, 0.f, 0.f);
    G[2] = pack4_h(fv);
}

__device__ __forceinline__ void sts_row(char* act, int r, int lane, const uint2* G) {
    char* rowp = act + r * ACT_STR;
    *(uint2*)(rowp + lane * 8) = G[0];
    *(uint2*)(rowp + 256 + lane * 8) = G[1];
    if (lane < 8) *(uint2*)(rowp + 512 + lane * 8) = G[2];
}

// ---------------------------------------------------------------------------
// Dual-side warp-specialized layer: fp16 single-term HMMA, 4-slot ring.
// Producers warps 16-31 (2 rows each, pre-gathered before empty-wait).
// Consumers warps 0-15 (2m x 8n, 16x16 tiles, 2 MMA/kstep).
// ---------------------------------------------------------------------------
__global__ __launch_bounds__(1024, 1)
void layer_dual(int lv_sel, int lc_sel, int nlv_sel, int nlc_sel,
                const float* __restrict__ vfeat, const float* __restrict__ cfeat,
                const int* __restrict__ vci, const int* __restrict__ cvi,
                const float* __restrict__ bv, const float* __restrict__ bc,
                int n, int last)
{
    extern __shared__ char sm[];
    uint32_t smb = smem_u32(sm);

    int side = blockIdx.x & 1;
    int blk = blockIdx.x >> 1;

    const __half* agg16; const __half* self16; __half* out16;
    const float* feat; const int* idx32; const float* b; int which;
    if (side == 0) {
        agg16 = g_h16[lv_sel]; self16 = g_h16[lc_sel]; out16 = g_h16[nlc_sel];
        feat = cfeat; idx32 = cvi; b = bc; which = 1;
    } else {
        agg16 = g_h16[lc_sel]; self16 = g_h16[lv_sel]; out16 = g_h16[nlv_sel];
        feat = vfeat; idx32 = vci; b = bv; which = 0;
    }

    int tid = threadIdx.x, wid = tid >> 5, lane = tid & 31;
    int istride = g_is64 ? 2 : 1;

    {
        const uint4* sw = (const uint4*)g_w16[which];
        uint4* dw = (uint4*)(sm + SM_W16);
        for (int i = tid; i < 78336 / 16; i += 1024) dw[i] = sw[i];
    }
    __syncthreads();

    if (wid >= 16) {
        // ================= PRODUCERS (16 warps, 2 rows each) =================
        int pw = wid - 16;
        int it = 0;
        for (int tile = blk; tile < NT32; tile += NBLK_SIDE, it++) {
            int slot = it & (NSLOT - 1);
            int row0 = tile * BM32 + pw * 2;

            uint2 G0[3], G1[3];
            gather_row(agg16, self16, feat, idx32, row0 + 0, n, istride, lane, G0);
            gather_row(agg16, self16, feat, idx32, row0 + 1, n, istride, lane, G1);

            BAR_SYNC(5 + slot);        // wait slot empty
            char* act = sm + SM_ACT + slot * ACT_IMG;
            sts_row(act, pw * 2 + 0, lane, G0);
            sts_row(act, pw * 2 + 1, lane, G1);
            BAR_ARRIVE(1 + slot);      // mark full
        }
    } else {
        // ================= CONSUMERS (16 warps: 2m x 8n, 16x16) =============
        int wm = wid >> 3, wn = wid & 7;
        int rsel = lane & 15, csel = lane >> 4;
        BAR_ARRIVE(5); BAR_ARRIVE(6); BAR_ARRIVE(7); BAR_ARRIVE(8);

        uint32_t aOff = (uint32_t)((16 * wm + rsel) * ACT_STR + csel * 16);
        uint32_t bBase = smb + SM_W16 + (uint32_t)(rsel * WSB + csel * 16 + 32 * wn);

        int cpair = (lane & 3) * 2;
        float2 bb[2];
#pragma unroll
        for (int nt = 0; nt < 2; nt++) {
            int col = 16 * wn + 8 * nt + cpair;
            bb[nt].x = b[col]; bb[nt].y = b[col + 1];
        }
        int do32 = last && (side == 1);
        float2 csum[2];
#pragma unroll
        for (int nt = 0; nt < 2; nt++) csum[nt] = make_float2(0.f, 0.f);

        int it = 0;
        for (int tile = blk; tile < NT32; tile += NBLK_SIDE, it++) {
            int slot = it & (NSLOT - 1);
            BAR_SYNC(1 + slot);        // wait full
            uint32_t aBase = smb + SM_ACT + (uint32_t)(slot * ACT_IMG) + aOff;

            float acc[2][4];
#pragma unroll
            for (int nt = 0; nt < 2; nt++)
#pragma unroll
                for (int q = 0; q < 4; q++) acc[nt][q] = 0.f;

#pragma unroll 6
            for (int ks = 0; ks < 18; ks++) {
                uint32_t a[4], bf[4];
                ldsm_x4(a, aBase + (uint32_t)(ks * 32));
                ldsm_x4t(bf, bBase + (uint32_t)(ks * 16 * WSB));
                mma_f16(acc[0], a, bf[0], bf[1]);
                mma_f16(acc[1], a, bf[2], bf[3]);
            }
            BAR_ARRIVE(5 + slot);      // slot free

            int row0 = tile * BM32;
            int r_lo = lane >> 2;
            int ra0 = row0 + 16 * wm + r_lo;
#pragma unroll
            for (int nt = 0; nt < 2; nt++) {
                int col = 16 * wn + 8 * nt + cpair;
                if (ra0 < n) {
                    float v0 = acc[nt][0] + bb[nt].x, v1 = acc[nt][1] + bb[nt].y;
                    *(__half2*)(out16 + (size_t)ra0 * DD + col) = __floats2half2_rn(v0, v1);
                    if (do32) {
                        *(float2*)(g_lv32 + (size_t)ra0 * DD + col) = make_float2(v0, v1);
                        csum[nt].x += v0; csum[nt].y += v1;
                    }
                }
                if (ra0 + 8 < n) {
                    float v0 = acc[nt][2] + bb[nt].x, v1 = acc[nt][3] + bb[nt].y;
                    *(__half2*)(out16 + (size_t)(ra0 + 8) * DD + col) = __floats2half2_rn(v0, v1);
                    if (do32) {
                        *(float2*)(g_lv32 + (size_t)(ra0 + 8) * DD + col) = make_float2(v0, v1);
                        csum[nt].x += v0; csum[nt].y += v1;
                    }
                }
            }
        }

        if (do32) {
#pragma unroll
            for (int nt = 0; nt < 2; nt++) {
                float c0 = csum[nt].x, c1 = csum[nt].y;
#pragma unroll
                for (int o = 4; o < 32; o <<= 1) {
                    c0 += __shfl_xor_sync(0xffffffffu, c0, o);
                    c1 += __shfl_xor_sync(0xffffffffu, c1, o);
                }
                if (lane < 4) {
                    int col = 16 * wn + 8 * nt + lane * 2;
                    atomicAdd(&g_colsum[col], c0);
                    atomicAdd(&g_colsum[col + 1], c1);
                }
            }
        }
    }
}

// ---------------------------------------------------------------------------
__global__ void final_kernel(const float* __restrict__ Wq,
                             const float* __restrict__ bq,
                             float* __restrict__ Q, int n) {
    const float* lv = g_lv32;
    __shared__ float sW[DD];
    __shared__ float s_s;
    int tid = threadIdx.x;
    if (tid < DD) sW[tid] = Wq[DD + tid];
    if (tid < 32) {
        float p = 0.f;
#pragma unroll
        for (int t = 0; t < 4; t++) p += g_colsum[tid + 32 * t] * Wq[tid + 32 * t];
#pragma unroll
        for (int o = 16; o > 0; o >>= 1) p += __shfl_xor_sync(0xffffffffu, p, o);
        if (tid == 0) s_s = p + bq[0];
    }
    __syncthreads();
    int warp = tid >> 5, lane = tid & 31;
    int base = blockIdx.x * 64 + warp * 8;
    for (int i = 0; i < 8; i++) {
        int row = base + i;
        if (row >= n) break;
        const float* rp = lv + (size_t)row * DD;
        float p = rp[lane]      * sW[lane]
                + rp[lane + 32] * sW[lane + 32]
                + rp[lane + 64] * sW[lane + 64]
                + rp[lane + 96] * sW[lane + 96];
#pragma unroll
        for (int o = 16; o > 0; o >>= 1) p += __shfl_xor_sync(0xffffffffu, p, o);
        if (lane == 0) Q[row] = s_s + p;
    }
}

// ---------------------------------------------------------------------------
extern "C" void kernel_launch(void* const* d_in, const int* in_sizes, int n_in,
                              void* d_out, int out_size) {
    const float* x    = (const float*)d_in[0];
    const int*   vci  = (const int*)d_in[1];
    const int*   cvi  = (const int*)d_in[2];
    const float* W_iv = (const float*)d_in[3];
    const float* b_iv = (const float*)d_in[4];
    const float* W_ic = (const float*)d_in[5];
    const float* b_ic = (const float*)d_in[6];
    const float* W_v  = (const float*)d_in[7];
    const float* b_v  = (const float*)d_in[8];
    const float* W_c  = (const float*)d_in[9];
    const float* b_c  = (const float*)d_in[10];
    const float* W_q  = (const float*)d_in[11];
    const float* b_q  = (const float*)d_in[12];
    float* Q = (float*)d_out;

    cudaFuncSetAttribute(layer_dual,
                         cudaFuncAttributeMaxDynamicSharedMemorySize, SM_DYN);

    const float* var_feat = x;
    const float* con_feat = x + (size_t)NVV * FIN;

    prep_w<<<3, 256>>>(W_v, W_c, vci);
    init_mma<<<2 * NB_INIT, 256>>>(var_feat, con_feat, W_iv, W_ic, b_iv, b_ic, NVV);

    int lv = 0, lc = 2;
    for (int t = 0; t < 3; t++) {
        int nlc = 5 - lc, nlv = 1 - lv;
        layer_dual<<<GRID_TC, 1024, SM_DYN>>>(lv, lc, nlv, nlc,
                                              var_feat, con_feat, vci, cvi,
                                              b_v, b_c, NVV, t == 2);
        lv = nlv; lc = nlc;
    }

    final_kernel<<<(NVV + 63) / 64, 256>>>(W_q, b_q, Q, NVV);
}

// round 13
// speedup vs baseline: 1.5221x; 1.0353x over previous
#include <cuda_runtime.h>
#include <cuda_fp16.h>
#include <cstdint>

#define NVV 50000
#define DD 128
#define FIN 32
#define DEG 16
#define INDIM 288
#define GRID_TC 152
#define NBLK_SIDE (GRID_TC / 2)

#define BM32 32
#define NT32 ((NVV + BM32 - 1) / BM32)   // 1563
#define NSLOT 4

#define WSB 272
#define ACT_STR 592
#define ACT_IMG (32 * ACT_STR)            // 18944

#define SM_W16 0
#define SM_ACT 78336
#define SM_DYN (SM_ACT + NSLOT * ACT_IMG) // 154112

#define BAR_SYNC(id)   asm volatile("bar.sync %0, 1024;"   :: "r"(id) : "memory")
#define BAR_ARRIVE(id) asm volatile("bar.arrive %0, 1024;" :: "r"(id) : "memory")

// ---------------------------------------------------------------------------
__device__ __align__(16) unsigned short g_w16[2][288 * 136];
__device__ __align__(256) float g_lv32[(size_t)NVV * DD];      // final lv only
__device__ __align__(256) __half g_h16[4][(size_t)NVV * DD];   // fp16 activations
__device__ __align__(16) __half g_feat16[(size_t)2 * NVV * FIN];
__device__ float g_colsum[DD];
__device__ int g_is64;

__device__ __forceinline__ uint32_t smem_u32(const void* p) {
    uint32_t a;
    asm("{ .reg .u64 t; cvta.to.shared.u64 t, %1; cvt.u32.u64 %0, t; }" : "=r"(a) : "l"(p));
    return a;
}
__device__ __forceinline__ void ldsm_x4(uint32_t* r, uint32_t addr) {
    asm volatile("ldmatrix.sync.aligned.m8n8.x4.shared.b16 {%0,%1,%2,%3}, [%4];"
                 : "=r"(r[0]), "=r"(r[1]), "=r"(r[2]), "=r"(r[3]) : "r"(addr));
}
__device__ __forceinline__ void ldsm_x4t(uint32_t* r, uint32_t addr) {
    asm volatile("ldmatrix.sync.aligned.m8n8.x4.trans.shared.b16 {%0,%1,%2,%3}, [%4];"
                 : "=r"(r[0]), "=r"(r[1]), "=r"(r[2]), "=r"(r[3]) : "r"(addr));
}
__device__ __forceinline__ void mma_f16(float* d, const uint32_t* a, uint32_t b0, uint32_t b1) {
    asm volatile("mma.sync.aligned.m16n8k16.row.col.f32.f16.f16.f32 "
                 "{%0,%1,%2,%3}, {%4,%5,%6,%7}, {%8,%9}, {%0,%1,%2,%3};"
                 : "+f"(d[0]), "+f"(d[1]), "+f"(d[2]), "+f"(d[3])
                 : "r"(a[0]), "r"(a[1]), "r"(a[2]), "r"(a[3]), "r"(b0), "r"(b1));
}
__device__ __forceinline__ uint32_t pack_h2(float lo, float hi) {
    __half2 h = __floats2half2_rn(lo, hi);
    return *reinterpret_cast<uint32_t*>(&h);
}
__device__ __forceinline__ uint2 pack4_h(float4 v) {
    uint2 r;
    r.x = pack_h2(v.x, v.y);
    r.y = pack_h2(v.z, v.w);
    return r;
}
__device__ __forceinline__ __half2 u2h(uint32_t u) { return *reinterpret_cast<__half2*>(&u); }
__device__ __forceinline__ uint32_t h2u(__half2 h) { return *reinterpret_cast<uint32_t*>(&h); }

// ---------------------------------------------------------------------------
// prep: block 0/1 split W; block 2 detect + colsum zero; blocks 3+ feat->fp16.
// ---------------------------------------------------------------------------
#define PREP_FEAT_BLOCKS 64
__global__ void prep_w(const float* __restrict__ Wv, const float* __restrict__ Wc,
                       const int* __restrict__ idx32, const float* __restrict__ x) {
    int which = blockIdx.x;
    if (which == 2) {
        if (threadIdx.x == 0) {
            int nz = 0;
#pragma unroll
            for (int i = 0; i < 64; i++) nz |= idx32[2 * i + 1];
            g_is64 = (nz == 0) ? 1 : 0;
        }
        if (threadIdx.x < DD) g_colsum[threadIdx.x] = 0.f;
        return;
    }
    if (which >= 3) {
        int fb = which - 3;
        const int total = 2 * NVV * FIN;
        for (int e = fb * 256 + threadIdx.x; e < total; e += PREP_FEAT_BLOCKS * 256)
            g_feat16[e] = __float2half_rn(x[e]);
        return;
    }
    const float* W = which ? Wc : Wv;
    for (int e = threadIdx.x; e < 288 * 136; e += blockDim.x) {
        int k = e / 136, nn = e - k * 136;
        float w = (nn < 128) ? W[nn * INDIM + k] : 0.f;
        __half h = __float2half_rn(w);
        g_w16[which][e] = *reinterpret_cast<unsigned short*>(&h);
    }
}

// ---------------------------------------------------------------------------
// HMMA initial embedding, fp16 single-term, dual-side merged (as R12).
// ---------------------------------------------------------------------------
#define ISM_B 0
#define ISM_ACT 8704
#define IACT_STR 80
#define NB_INIT ((NVV + 127) / 128)

__global__ __launch_bounds__(256, 1)
void init_mma(const float* __restrict__ vfeat, const float* __restrict__ cfeat,
              const float* __restrict__ Wiv, const float* __restrict__ Wic,
              const float* __restrict__ biv, const float* __restrict__ bic, int n) {
    __shared__ __align__(16) char ism[ISM_ACT + 128 * IACT_STR];
    uint32_t smb = smem_u32(ism);
    int side = blockIdx.x & 1;
    int blk = blockIdx.x >> 1;
    const float* feat = side ? cfeat : vfeat;
    const float* W    = side ? Wic : Wiv;
    const float* b    = side ? bic : biv;
    __half* out16 = g_h16[side ? 2 : 0];

    int tid = threadIdx.x, wid = tid >> 5, lane = tid & 31;
    int row0 = blk * 128;

    for (int e = tid; e < 32 * 136; e += 256) {
        int k = e / 136, nn = e - k * 136;
        float w = (nn < 128) ? W[nn * FIN + k] : 0.f;
        __half h = __float2half_rn(w);
        *(unsigned short*)(ism + ISM_B + k * WSB + nn * 2) =
            *reinterpret_cast<unsigned short*>(&h);
    }
    {
        int r = tid >> 1, half = tid & 1;
        int gr = row0 + r;
        char* rowp = ism + ISM_ACT + r * IACT_STR + half * 32;
#pragma unroll
        for (int i = 0; i < 4; i++) {
            float4 v = (gr < n)
                ? reinterpret_cast<const float4*>(feat + (size_t)gr * FIN)[half * 4 + i]
                : make_float4(0.f, 0.f, 0.f, 0.f);
            *(uint2*)(rowp + i * 8) = pack4_h(v);
        }
    }
    __syncthreads();

    int wm = wid >> 1, wn = wid & 1;
    int rsel = lane & 15, csel = lane >> 4;
    uint32_t aBase = smb + ISM_ACT + (uint32_t)((32 * wm + rsel) * IACT_STR + csel * 16);
    uint32_t bBase = smb + ISM_B + (uint32_t)(rsel * WSB + csel * 16 + 128 * wn);

    float acc[2][8][4];
#pragma unroll
    for (int mt = 0; mt < 2; mt++)
#pragma unroll
        for (int nt = 0; nt < 8; nt++)
#pragma unroll
            for (int q = 0; q < 4; q++) acc[mt][nt][q] = 0.f;

#pragma unroll
    for (int ks = 0; ks < 2; ks++) {
        uint32_t a[2][4], bf[4][4];
#pragma unroll
        for (int mt = 0; mt < 2; mt++)
            ldsm_x4(a[mt], aBase + (uint32_t)(16 * mt * IACT_STR + ks * 32));
#pragma unroll
        for (int np = 0; np < 4; np++)
            ldsm_x4t(bf[np], bBase + (uint32_t)(ks * 16 * WSB + 32 * np));
#pragma unroll
        for (int mt = 0; mt < 2; mt++)
#pragma unroll
            for (int nt = 0; nt < 8; nt++)
                mma_f16(acc[mt][nt], a[mt], bf[nt >> 1][2 * (nt & 1)], bf[nt >> 1][2 * (nt & 1) + 1]);
    }

    int r_lo = lane >> 2;
    int cpair = (lane & 3) * 2;
#pragma unroll
    for (int mt = 0; mt < 2; mt++) {
        int ra = row0 + 32 * wm + 16 * mt + r_lo;
#pragma unroll
        for (int nt = 0; nt < 8; nt++) {
            int col = 64 * wn + 8 * nt + cpair;
            float b0 = b[col], b1 = b[col + 1];
            if (ra < n)
                *(__half2*)(out16 + (size_t)ra * DD + col) =
                    __floats2half2_rn(acc[mt][nt][0] + b0, acc[mt][nt][1] + b1);
            if (ra + 8 < n)
                *(__half2*)(out16 + (size_t)(ra + 8) * DD + col) =
                    __floats2half2_rn(acc[mt][nt][2] + b0, acc[mt][nt][3] + b1);
        }
    }
}

// ---------------------------------------------------------------------------
// Producer: agg via native HADD2 (4 parallel accumulator pairs), self & feat
// raw uint2 copies. No fp32 converts anywhere.
// ---------------------------------------------------------------------------
__device__ __forceinline__ void gather_row(
    const __half* __restrict__ agg16, const __half* __restrict__ self16,
    const __half* __restrict__ feat16, const int* __restrict__ idx32,
    int gr, int n, int istride, int lane, uint2* G)
{
    bool val = gr < n;
    const int* ip = idx32 + (size_t)(val ? gr : 0) * DEG * istride;
    int srcs[DEG];
    if (istride == 1) {
        const int4* p = (const int4*)ip;
#pragma unroll
        for (int q = 0; q < 4; q++) {
            int4 t = p[q];
            srcs[4*q] = t.x; srcs[4*q+1] = t.y; srcs[4*q+2] = t.z; srcs[4*q+3] = t.w;
        }
    } else {
        const int4* p = (const int4*)ip;
#pragma unroll
        for (int q = 0; q < 8; q++) {
            int4 t = p[q];
            srcs[2*q] = t.x; srcs[2*q+1] = t.z;
        }
    }

    __half2 ax[4], ay[4];
#pragma unroll
    for (int j = 0; j < 4; j++) {
        uint2 d = reinterpret_cast<const uint2*>(agg16 + (size_t)srcs[j] * DD)[lane];
        ax[j] = u2h(d.x); ay[j] = u2h(d.y);
    }
#pragma unroll
    for (int j = 4; j < DEG; j++) {
        uint2 d = reinterpret_cast<const uint2*>(agg16 + (size_t)srcs[j] * DD)[lane];
        ax[j & 3] = __hadd2(ax[j & 3], u2h(d.x));
        ay[j & 3] = __hadd2(ay[j & 3], u2h(d.y));
    }
    __half2 sx = __hadd2(__hadd2(ax[0], ax[1]), __hadd2(ax[2], ax[3]));
    __half2 sy = __hadd2(__hadd2(ay[0], ay[1]), __hadd2(ay[2], ay[3]));

    uint2 sv = val ? reinterpret_cast<const uint2*>(self16 + (size_t)gr * DD)[lane]
                   : make_uint2(0u, 0u);
    uint2 fv = (val && lane < 8)
        ? reinterpret_cast<const uint2*>(feat16 + (size_t)gr * FIN)[lane]
        : make_uint2(0u, 0u);

    if (!val) { sx = u2h(0u); sy = u2h(0u); }
    G[0].x = h2u(sx); G[0].y = h2u(sy);
    G[1] = sv;
    G[2] = fv;
}

__device__ __forceinline__ void sts_row(char* act, int r, int lane, const uint2* G) {
    char* rowp = act + r * ACT_STR;
    *(uint2*)(rowp + lane * 8) = G[0];
    *(uint2*)(rowp + 256 + lane * 8) = G[1];
    if (lane < 8) *(uint2*)(rowp + 512 + lane * 8) = G[2];
}

// ---------------------------------------------------------------------------
// Dual-side warp-specialized layer: fp16 single-term HMMA, 4-slot ring.
// ---------------------------------------------------------------------------
__global__ __launch_bounds__(1024, 1)
void layer_dual(int lv_sel, int lc_sel, int nlv_sel, int nlc_sel,
                const int* __restrict__ vci, const int* __restrict__ cvi,
                const float* __restrict__ bv, const float* __restrict__ bc,
                int n, int last)
{
    extern __shared__ char sm[];
    uint32_t smb = smem_u32(sm);

    int side = blockIdx.x & 1;
    int blk = blockIdx.x >> 1;

    const __half* agg16; const __half* self16; __half* out16;
    const __half* feat16; const int* idx32; const float* b; int which;
    if (side == 0) {
        agg16 = g_h16[lv_sel]; self16 = g_h16[lc_sel]; out16 = g_h16[nlc_sel];
        feat16 = g_feat16 + (size_t)NVV * FIN; idx32 = cvi; b = bc; which = 1;
    } else {
        agg16 = g_h16[lc_sel]; self16 = g_h16[lv_sel]; out16 = g_h16[nlv_sel];
        feat16 = g_feat16; idx32 = vci; b = bv; which = 0;
    }

    int tid = threadIdx.x, wid = tid >> 5, lane = tid & 31;
    int istride = g_is64 ? 2 : 1;

    {
        const uint4* sw = (const uint4*)g_w16[which];
        uint4* dw = (uint4*)(sm + SM_W16);
        for (int i = tid; i < 78336 / 16; i += 1024) dw[i] = sw[i];
    }
    __syncthreads();

    if (wid >= 16) {
        // ================= PRODUCERS (16 warps, 2 rows each) =================
        int pw = wid - 16;
        int it = 0;
        for (int tile = blk; tile < NT32; tile += NBLK_SIDE, it++) {
            int slot = it & (NSLOT - 1);
            int row0 = tile * BM32 + pw * 2;

            uint2 G0[3], G1[3];
            gather_row(agg16, self16, feat16, idx32, row0 + 0, n, istride, lane, G0);
            gather_row(agg16, self16, feat16, idx32, row0 + 1, n, istride, lane, G1);

            BAR_SYNC(5 + slot);        // wait slot empty
            char* act = sm + SM_ACT + slot * ACT_IMG;
            sts_row(act, pw * 2 + 0, lane, G0);
            sts_row(act, pw * 2 + 1, lane, G1);
            BAR_ARRIVE(1 + slot);      // mark full
        }
    } else {
        // ================= CONSUMERS (16 warps: 2m x 8n, 16x16) =============
        int wm = wid >> 3, wn = wid & 7;
        int rsel = lane & 15, csel = lane >> 4;
        BAR_ARRIVE(5); BAR_ARRIVE(6); BAR_ARRIVE(7); BAR_ARRIVE(8);

        uint32_t aOff = (uint32_t)((16 * wm + rsel) * ACT_STR + csel * 16);
        uint32_t bBase = smb + SM_W16 + (uint32_t)(rsel * WSB + csel * 16 + 32 * wn);

        int cpair = (lane & 3) * 2;
        float2 bb[2];
#pragma unroll
        for (int nt = 0; nt < 2; nt++) {
            int col = 16 * wn + 8 * nt + cpair;
            bb[nt].x = b[col]; bb[nt].y = b[col + 1];
        }
        int do32 = last && (side == 1);
        float2 csum[2];
#pragma unroll
        for (int nt = 0; nt < 2; nt++) csum[nt] = make_float2(0.f, 0.f);

        int it = 0;
        for (int tile = blk; tile < NT32; tile += NBLK_SIDE, it++) {
            int slot = it & (NSLOT - 1);
            BAR_SYNC(1 + slot);        // wait full
            uint32_t aBase = smb + SM_ACT + (uint32_t)(slot * ACT_IMG) + aOff;

            float acc[2][4];
#pragma unroll
            for (int nt = 0; nt < 2; nt++)
#pragma unroll
                for (int q = 0; q < 4; q++) acc[nt][q] = 0.f;

#pragma unroll 6
            for (int ks = 0; ks < 18; ks++) {
                uint32_t a[4], bf[4];
                ldsm_x4(a, aBase + (uint32_t)(ks * 32));
                ldsm_x4t(bf, bBase + (uint32_t)(ks * 16 * WSB));
                mma_f16(acc[0], a, bf[0], bf[1]);
                mma_f16(acc[1], a, bf[2], bf[3]);
            }
            BAR_ARRIVE(5 + slot);      // slot free

            int row0 = tile * BM32;
            int r_lo = lane >> 2;
            int ra0 = row0 + 16 * wm + r_lo;
#pragma unroll
            for (int nt = 0; nt < 2; nt++) {
                int col = 16 * wn + 8 * nt + cpair;
                if (ra0 < n) {
                    float v0 = acc[nt][0] + bb[nt].x, v1 = acc[nt][1] + bb[nt].y;
                    *(__half2*)(out16 + (size_t)ra0 * DD + col) = __floats2half2_rn(v0, v1);
                    if (do32) {
                        *(float2*)(g_lv32 + (size_t)ra0 * DD + col) = make_float2(v0, v1);
                        csum[nt].x += v0; csum[nt].y += v1;
                    }
                }
                if (ra0 + 8 < n) {
                    float v0 = acc[nt][2] + bb[nt].x, v1 = acc[nt][3] + bb[nt].y;
                    *(__half2*)(out16 + (size_t)(ra0 + 8) * DD + col) = __floats2half2_rn(v0, v1);
                    if (do32) {
                        *(float2*)(g_lv32 + (size_t)(ra0 + 8) * DD + col) = make_float2(v0, v1);
                        csum[nt].x += v0; csum[nt].y += v1;
                    }
                }
            }
        }

        if (do32) {
#pragma unroll
            for (int nt = 0; nt < 2; nt++) {
                float c0 = csum[nt].x, c1 = csum[nt].y;
#pragma unroll
                for (int o = 4; o < 32; o <<= 1) {
                    c0 += __shfl_xor_sync(0xffffffffu, c0, o);
                    c1 += __shfl_xor_sync(0xffffffffu, c1, o);
                }
                if (lane < 4) {
                    int col = 16 * wn + 8 * nt + lane * 2;
                    atomicAdd(&g_colsum[col], c0);
                    atomicAdd(&g_colsum[col + 1], c1);
                }
            }
        }
    }
}

// ---------------------------------------------------------------------------
__global__ void final_kernel(const float* __restrict__ Wq,
                             const float* __restrict__ bq,
                             float* __restrict__ Q, int n) {
    const float* lv = g_lv32;
    __shared__ float sW[DD];
    __shared__ float s_s;
    int tid = threadIdx.x;
    if (tid < DD) sW[tid] = Wq[DD + tid];
    if (tid < 32) {
        float p = 0.f;
#pragma unroll
        for (int t = 0; t < 4; t++) p += g_colsum[tid + 32 * t] * Wq[tid + 32 * t];
#pragma unroll
        for (int o = 16; o > 0; o >>= 1) p += __shfl_xor_sync(0xffffffffu, p, o);
        if (tid == 0) s_s = p + bq[0];
    }
    __syncthreads();
    int warp = tid >> 5, lane = tid & 31;
    int base = blockIdx.x * 64 + warp * 8;
    for (int i = 0; i < 8; i++) {
        int row = base + i;
        if (row >= n) break;
        const float* rp = lv + (size_t)row * DD;
        float p = rp[lane]      * sW[lane]
                + rp[lane + 32] * sW[lane + 32]
                + rp[lane + 64] * sW[lane + 64]
                + rp[lane + 96] * sW[lane + 96];
#pragma unroll
        for (int o = 16; o > 0; o >>= 1) p += __shfl_xor_sync(0xffffffffu, p, o);
        if (lane == 0) Q[row] = s_s + p;
    }
}

// ---------------------------------------------------------------------------
extern "C" void kernel_launch(void* const* d_in, const int* in_sizes, int n_in,
                              void* d_out, int out_size) {
    const float* x    = (const float*)d_in[0];
    const int*   vci  = (const int*)d_in[1];
    const int*   cvi  = (const int*)d_in[2];
    const float* W_iv = (const float*)d_in[3];
    const float* b_iv = (const float*)d_in[4];
    const float* W_ic = (const float*)d_in[5];
    const float* b_ic = (const float*)d_in[6];
    const float* W_v  = (const float*)d_in[7];
    const float* b_v  = (const float*)d_in[8];
    const float* W_c  = (const float*)d_in[9];
    const float* b_c  = (const float*)d_in[10];
    const float* W_q  = (const float*)d_in[11];
    const float* b_q  = (const float*)d_in[12];
    float* Q = (float*)d_out;

    cudaFuncSetAttribute(layer_dual,
                         cudaFuncAttributeMaxDynamicSharedMemorySize, SM_DYN);

    const float* var_feat = x;
    const float* con_feat = x + (size_t)NVV * FIN;

    prep_w<<<3 + PREP_FEAT_BLOCKS, 256>>>(W_v, W_c, vci, x);
    init_mma<<<2 * NB_INIT, 256>>>(var_feat, con_feat, W_iv, W_ic, b_iv, b_ic, NVV);

    int lv = 0, lc = 2;
    for (int t = 0; t < 3; t++) {
        int nlc = 5 - lc, nlv = 1 - lv;
        layer_dual<<<GRID_TC, 1024, SM_DYN>>>(lv, lc, nlv, nlc,
                                              vci, cvi, b_v, b_c, NVV, t == 2);
        lv = nlv; lc = nlc;
    }

    final_kernel<<<(NVV + 63) / 64, 256>>>(W_q, b_q, Q, NVV);
}

// round 14
// speedup vs baseline: 1.5788x; 1.0372x over previous
#include <cuda_runtime.h>
#include <cuda_fp16.h>
#include <cstdint>

#define NVV 50000
#define DD 128
#define FIN 32
#define DEG 16
#define GRID_TC 152
#define NBLK_SIDE (GRID_TC / 2)

#define BM64 64
#define NT64 ((NVV + BM64 - 1) / BM64)   // 782
#define NSLOT 2

#define WSB 272
#define ACT_STR 592
#define ACT_IMG (64 * ACT_STR)            // 37888

#define SM_W16 0
#define SM_ACT 78336
#define SM_DYN (SM_ACT + NSLOT * ACT_IMG) // 154112

#define BAR_SYNC(id)   asm volatile("bar.sync %0, 1024;"   :: "r"(id) : "memory")
#define BAR_ARRIVE(id) asm volatile("bar.arrive %0, 1024;" :: "r"(id) : "memory")

// ---------------------------------------------------------------------------
__device__ __align__(16) unsigned short g_w16[2][288 * 136];
__device__ __align__(256) float g_lv32[(size_t)NVV * DD];      // final lv only
__device__ __align__(256) __half g_h16[4][(size_t)NVV * DD];   // fp16 activations
__device__ __align__(16) __half g_feat16[(size_t)2 * NVV * FIN];
__device__ float g_colsum[DD];
__device__ int g_is64;

__device__ __forceinline__ uint32_t smem_u32(const void* p) {
    uint32_t a;
    asm("{ .reg .u64 t; cvta.to.shared.u64 t, %1; cvt.u32.u64 %0, t; }" : "=r"(a) : "l"(p));
    return a;
}
__device__ __forceinline__ void ldsm_x4(uint32_t* r, uint32_t addr) {
    asm volatile("ldmatrix.sync.aligned.m8n8.x4.shared.b16 {%0,%1,%2,%3}, [%4];"
                 : "=r"(r[0]), "=r"(r[1]), "=r"(r[2]), "=r"(r[3]) : "r"(addr));
}
__device__ __forceinline__ void ldsm_x4t(uint32_t* r, uint32_t addr) {
    asm volatile("ldmatrix.sync.aligned.m8n8.x4.trans.shared.b16 {%0,%1,%2,%3}, [%4];"
                 : "=r"(r[0]), "=r"(r[1]), "=r"(r[2]), "=r"(r[3]) : "r"(addr));
}
__device__ __forceinline__ void mma_f16(float* d, const uint32_t* a, uint32_t b0, uint32_t b1) {
    asm volatile("mma.sync.aligned.m16n8k16.row.col.f32.f16.f16.f32 "
                 "{%0,%1,%2,%3}, {%4,%5,%6,%7}, {%8,%9}, {%0,%1,%2,%3};"
                 : "+f"(d[0]), "+f"(d[1]), "+f"(d[2]), "+f"(d[3])
                 : "r"(a[0]), "r"(a[1]), "r"(a[2]), "r"(a[3]), "r"(b0), "r"(b1));
}
__device__ __forceinline__ uint32_t pack_h2(float lo, float hi) {
    __half2 h = __floats2half2_rn(lo, hi);
    return *reinterpret_cast<uint32_t*>(&h);
}
__device__ __forceinline__ uint2 pack4_h(float4 v) {
    uint2 r;
    r.x = pack_h2(v.x, v.y);
    r.y = pack_h2(v.z, v.w);
    return r;
}
__device__ __forceinline__ __half2 u2h(uint32_t u) { return *reinterpret_cast<__half2*>(&u); }
__device__ __forceinline__ uint32_t h2u(__half2 h) { return *reinterpret_cast<uint32_t*>(&h); }

// ---------------------------------------------------------------------------
#define PREP_FEAT_BLOCKS 64
__global__ void prep_w(const float* __restrict__ Wv, const float* __restrict__ Wc,
                       const int* __restrict__ idx32, const float* __restrict__ x) {
    int which = blockIdx.x;
    if (which == 2) {
        if (threadIdx.x == 0) {
            int nz = 0;
#pragma unroll
            for (int i = 0; i < 64; i++) nz |= idx32[2 * i + 1];
            g_is64 = (nz == 0) ? 1 : 0;
        }
        if (threadIdx.x < DD) g_colsum[threadIdx.x] = 0.f;
        return;
    }
    if (which >= 3) {
        int fb = which - 3;
        const int total = 2 * NVV * FIN;
        for (int e = fb * 256 + threadIdx.x; e < total; e += PREP_FEAT_BLOCKS * 256)
            g_feat16[e] = __float2half_rn(x[e]);
        return;
    }
    const float* W = which ? Wc : Wv;
    for (int e = threadIdx.x; e < 288 * 136; e += blockDim.x) {
        int k = e / 136, nn = e - k * 136;
        float w = (nn < 128) ? W[nn * 288 + k] : 0.f;
        __half h = __float2half_rn(w);
        g_w16[which][e] = *reinterpret_cast<unsigned short*>(&h);
    }
}

// ---------------------------------------------------------------------------
// HMMA initial embedding (unchanged from R13).
// ---------------------------------------------------------------------------
#define ISM_B 0
#define ISM_ACT 8704
#define IACT_STR 80
#define NB_INIT ((NVV + 127) / 128)

__global__ __launch_bounds__(256, 1)
void init_mma(const float* __restrict__ vfeat, const float* __restrict__ cfeat,
              const float* __restrict__ Wiv, const float* __restrict__ Wic,
              const float* __restrict__ biv, const float* __restrict__ bic, int n) {
    __shared__ __align__(16) char ism[ISM_ACT + 128 * IACT_STR];
    uint32_t smb = smem_u32(ism);
    int side = blockIdx.x & 1;
    int blk = blockIdx.x >> 1;
    const float* feat = side ? cfeat : vfeat;
    const float* W    = side ? Wic : Wiv;
    const float* b    = side ? bic : biv;
    __half* out16 = g_h16[side ? 2 : 0];

    int tid = threadIdx.x, wid = tid >> 5, lane = tid & 31;
    int row0 = blk * 128;

    for (int e = tid; e < 32 * 136; e += 256) {
        int k = e / 136, nn = e - k * 136;
        float w = (nn < 128) ? W[nn * FIN + k] : 0.f;
        __half h = __float2half_rn(w);
        *(unsigned short*)(ism + ISM_B + k * WSB + nn * 2) =
            *reinterpret_cast<unsigned short*>(&h);
    }
    {
        int r = tid >> 1, half = tid & 1;
        int gr = row0 + r;
        char* rowp = ism + ISM_ACT + r * IACT_STR + half * 32;
#pragma unroll
        for (int i = 0; i < 4; i++) {
            float4 v = (gr < n)
                ? reinterpret_cast<const float4*>(feat + (size_t)gr * FIN)[half * 4 + i]
                : make_float4(0.f, 0.f, 0.f, 0.f);
            *(uint2*)(rowp + i * 8) = pack4_h(v);
        }
    }
    __syncthreads();

    int wm = wid >> 1, wn = wid & 1;
    int rsel = lane & 15, csel = lane >> 4;
    uint32_t aBase = smb + ISM_ACT + (uint32_t)((32 * wm + rsel) * IACT_STR + csel * 16);
    uint32_t bBase = smb + ISM_B + (uint32_t)(rsel * WSB + csel * 16 + 128 * wn);

    float acc[2][8][4];
#pragma unroll
    for (int mt = 0; mt < 2; mt++)
#pragma unroll
        for (int nt = 0; nt < 8; nt++)
#pragma unroll
            for (int q = 0; q < 4; q++) acc[mt][nt][q] = 0.f;

#pragma unroll
    for (int ks = 0; ks < 2; ks++) {
        uint32_t a[2][4], bf[4][4];
#pragma unroll
        for (int mt = 0; mt < 2; mt++)
            ldsm_x4(a[mt], aBase + (uint32_t)(16 * mt * IACT_STR + ks * 32));
#pragma unroll
        for (int np = 0; np < 4; np++)
            ldsm_x4t(bf[np], bBase + (uint32_t)(ks * 16 * WSB + 32 * np));
#pragma unroll
        for (int mt = 0; mt < 2; mt++)
#pragma unroll
            for (int nt = 0; nt < 8; nt++)
                mma_f16(acc[mt][nt], a[mt], bf[nt >> 1][2 * (nt & 1)], bf[nt >> 1][2 * (nt & 1) + 1]);
    }

    int r_lo = lane >> 2;
    int cpair = (lane & 3) * 2;
#pragma unroll
    for (int mt = 0; mt < 2; mt++) {
        int ra = row0 + 32 * wm + 16 * mt + r_lo;
#pragma unroll
        for (int nt = 0; nt < 8; nt++) {
            int col = 64 * wn + 8 * nt + cpair;
            float b0 = b[col], b1 = b[col + 1];
            if (ra < n)
                *(__half2*)(out16 + (size_t)ra * DD + col) =
                    __floats2half2_rn(acc[mt][nt][0] + b0, acc[mt][nt][1] + b1);
            if (ra + 8 < n)
                *(__half2*)(out16 + (size_t)(ra + 8) * DD + col) =
                    __floats2half2_rn(acc[mt][nt][2] + b0, acc[mt][nt][3] + b1);
        }
    }
}

// ---------------------------------------------------------------------------
// Producer: agg via native HADD2, self & feat raw copies (as R13).
// ---------------------------------------------------------------------------
__device__ __forceinline__ void gather_row(
    const __half* __restrict__ agg16, const __half* __restrict__ self16,
    const __half* __restrict__ feat16, const int* __restrict__ idx32,
    int gr, int n, int istride, int lane, uint2* G)
{
    bool val = gr < n;
    const int* ip = idx32 + (size_t)(val ? gr : 0) * DEG * istride;
    int srcs[DEG];
    if (istride == 1) {
        const int4* p = (const int4*)ip;
#pragma unroll
        for (int q = 0; q < 4; q++) {
            int4 t = p[q];
            srcs[4*q] = t.x; srcs[4*q+1] = t.y; srcs[4*q+2] = t.z; srcs[4*q+3] = t.w;
        }
    } else {
        const int4* p = (const int4*)ip;
#pragma unroll
        for (int q = 0; q < 8; q++) {
            int4 t = p[q];
            srcs[2*q] = t.x; srcs[2*q+1] = t.z;
        }
    }

    __half2 ax[4], ay[4];
#pragma unroll
    for (int j = 0; j < 4; j++) {
        uint2 d = reinterpret_cast<const uint2*>(agg16 + (size_t)srcs[j] * DD)[lane];
        ax[j] = u2h(d.x); ay[j] = u2h(d.y);
    }
#pragma unroll
    for (int j = 4; j < DEG; j++) {
        uint2 d = reinterpret_cast<const uint2*>(agg16 + (size_t)srcs[j] * DD)[lane];
        ax[j & 3] = __hadd2(ax[j & 3], u2h(d.x));
        ay[j & 3] = __hadd2(ay[j & 3], u2h(d.y));
    }
    __half2 sx = __hadd2(__hadd2(ax[0], ax[1]), __hadd2(ax[2], ax[3]));
    __half2 sy = __hadd2(__hadd2(ay[0], ay[1]), __hadd2(ay[2], ay[3]));

    uint2 sv = val ? reinterpret_cast<const uint2*>(self16 + (size_t)gr * DD)[lane]
                   : make_uint2(0u, 0u);
    uint2 fv = (val && lane < 8)
        ? reinterpret_cast<const uint2*>(feat16 + (size_t)gr * FIN)[lane]
        : make_uint2(0u, 0u);

    if (!val) { sx = u2h(0u); sy = u2h(0u); }
    G[0].x = h2u(sx); G[0].y = h2u(sy);
    G[1] = sv;
    G[2] = fv;
}

__device__ __forceinline__ void sts_row(char* act, int r, int lane, const uint2* G) {
    char* rowp = act + r * ACT_STR;
    *(uint2*)(rowp + lane * 8) = G[0];
    *(uint2*)(rowp + 256 + lane * 8) = G[1];
    if (lane < 8) *(uint2*)(rowp + 512 + lane * 8) = G[2];
}

// ---------------------------------------------------------------------------
// Dual-side warp-specialized layer: 64-row slabs, 2-slot ring, 4m x 4n
// consumer grid (A dup 4x, B dup 4x — minimal LDSM duplication).
// Producers: 16 warps x 4 rows, all pre-gathered before empty-wait.
// ---------------------------------------------------------------------------
__global__ __launch_bounds__(1024, 1)
void layer_dual(int lv_sel, int lc_sel, int nlv_sel, int nlc_sel,
                const int* __restrict__ vci, const int* __restrict__ cvi,
                const float* __restrict__ bv, const float* __restrict__ bc,
                int n, int last)
{
    extern __shared__ char sm[];
    uint32_t smb = smem_u32(sm);

    int side = blockIdx.x & 1;
    int blk = blockIdx.x >> 1;

    const __half* agg16; const __half* self16; __half* out16;
    const __half* feat16; const int* idx32; const float* b; int which;
    if (side == 0) {
        agg16 = g_h16[lv_sel]; self16 = g_h16[lc_sel]; out16 = g_h16[nlc_sel];
        feat16 = g_feat16 + (size_t)NVV * FIN; idx32 = cvi; b = bc; which = 1;
    } else {
        agg16 = g_h16[lc_sel]; self16 = g_h16[lv_sel]; out16 = g_h16[nlv_sel];
        feat16 = g_feat16; idx32 = vci; b = bv; which = 0;
    }

    int tid = threadIdx.x, wid = tid >> 5, lane = tid & 31;
    int istride = g_is64 ? 2 : 1;

    {
        const uint4* sw = (const uint4*)g_w16[which];
        uint4* dw = (uint4*)(sm + SM_W16);
        for (int i = tid; i < 78336 / 16; i += 1024) dw[i] = sw[i];
    }
    __syncthreads();

    if (wid >= 16) {
        // ================= PRODUCERS (16 warps, 4 rows each) =================
        int pw = wid - 16;
        int it = 0;
        for (int tile = blk; tile < NT64; tile += NBLK_SIDE, it++) {
            int slot = it & (NSLOT - 1);
            int row0 = tile * BM64 + pw * 4;

            uint2 G[4][3];
#pragma unroll
            for (int rr = 0; rr < 4; rr++)
                gather_row(agg16, self16, feat16, idx32, row0 + rr, n, istride, lane, G[rr]);

            BAR_SYNC(3 + slot);        // wait slot empty
            char* act = sm + SM_ACT + slot * ACT_IMG;
#pragma unroll
            for (int rr = 0; rr < 4; rr++)
                sts_row(act, pw * 4 + rr, lane, G[rr]);
            BAR_ARRIVE(1 + slot);      // mark full
        }
    } else {
        // ================= CONSUMERS (16 warps: 4m x 4n, 16x32) =============
        int wm = wid >> 2, wn = wid & 3;
        int rsel = lane & 15, csel = lane >> 4;
        BAR_ARRIVE(3); BAR_ARRIVE(4);  // prime both slots empty

        uint32_t aOff = (uint32_t)((16 * wm + rsel) * ACT_STR + csel * 16);
        uint32_t bBase = smb + SM_W16 + (uint32_t)(rsel * WSB + csel * 16 + 64 * wn);

        int cpair = (lane & 3) * 2;
        float2 bb[4];
#pragma unroll
        for (int nt = 0; nt < 4; nt++) {
            int col = 32 * wn + 8 * nt + cpair;
            bb[nt].x = b[col]; bb[nt].y = b[col + 1];
        }
        int do32 = last && (side == 1);
        float2 csum[4];
#pragma unroll
        for (int nt = 0; nt < 4; nt++) csum[nt] = make_float2(0.f, 0.f);

        int it = 0;
        for (int tile = blk; tile < NT64; tile += NBLK_SIDE, it++) {
            int slot = it & (NSLOT - 1);
            BAR_SYNC(1 + slot);        // wait full
            uint32_t aBase = smb + SM_ACT + (uint32_t)(slot * ACT_IMG) + aOff;

            float acc[4][4];
#pragma unroll
            for (int nt = 0; nt < 4; nt++)
#pragma unroll
                for (int q = 0; q < 4; q++) acc[nt][q] = 0.f;

#pragma unroll 3
            for (int ks = 0; ks < 18; ks++) {
                uint32_t a[4], bf[2][4];
                ldsm_x4(a, aBase + (uint32_t)(ks * 32));
#pragma unroll
                for (int np = 0; np < 2; np++)
                    ldsm_x4t(bf[np], bBase + (uint32_t)(ks * 16 * WSB + 32 * np));
#pragma unroll
                for (int nt = 0; nt < 4; nt++)
                    mma_f16(acc[nt], a, bf[nt >> 1][2 * (nt & 1)], bf[nt >> 1][2 * (nt & 1) + 1]);
            }
            BAR_ARRIVE(3 + slot);      // slot free

            int row0 = tile * BM64;
            int r_lo = lane >> 2;
            int ra0 = row0 + 16 * wm + r_lo;
#pragma unroll
            for (int nt = 0; nt < 4; nt++) {
                int col = 32 * wn + 8 * nt + cpair;
                if (ra0 < n) {
                    float v0 = acc[nt][0] + bb[nt].x, v1 = acc[nt][1] + bb[nt].y;
                    *(__half2*)(out16 + (size_t)ra0 * DD + col) = __floats2half2_rn(v0, v1);
                    if (do32) {
                        *(float2*)(g_lv32 + (size_t)ra0 * DD + col) = make_float2(v0, v1);
                        csum[nt].x += v0; csum[nt].y += v1;
                    }
                }
                if (ra0 + 8 < n) {
                    float v0 = acc[nt][2] + bb[nt].x, v1 = acc[nt][3] + bb[nt].y;
                    *(__half2*)(out16 + (size_t)(ra0 + 8) * DD + col) = __floats2half2_rn(v0, v1);
                    if (do32) {
                        *(float2*)(g_lv32 + (size_t)(ra0 + 8) * DD + col) = make_float2(v0, v1);
                        csum[nt].x += v0; csum[nt].y += v1;
                    }
                }
            }
        }

        if (do32) {
#pragma unroll
            for (int nt = 0; nt < 4; nt++) {
                float c0 = csum[nt].x, c1 = csum[nt].y;
#pragma unroll
                for (int o = 4; o < 32; o <<= 1) {
                    c0 += __shfl_xor_sync(0xffffffffu, c0, o);
                    c1 += __shfl_xor_sync(0xffffffffu, c1, o);
                }
                if (lane < 4) {
                    int col = 32 * wn + 8 * nt + lane * 2;
                    atomicAdd(&g_colsum[col], c0);
                    atomicAdd(&g_colsum[col + 1], c1);
                }
            }
        }
    }
}

// ---------------------------------------------------------------------------
__global__ void final_kernel(const float* __restrict__ Wq,
                             const float* __restrict__ bq,
                             float* __restrict__ Q, int n) {
    const float* lv = g_lv32;
    __shared__ float sW[DD];
    __shared__ float s_s;
    int tid = threadIdx.x;
    if (tid < DD) sW[tid] = Wq[DD + tid];
    if (tid < 32) {
        float p = 0.f;
#pragma unroll
        for (int t = 0; t < 4; t++) p += g_colsum[tid + 32 * t] * Wq[tid + 32 * t];
#pragma unroll
        for (int o = 16; o > 0; o >>= 1) p += __shfl_xor_sync(0xffffffffu, p, o);
        if (tid == 0) s_s = p + bq[0];
    }
    __syncthreads();
    int warp = tid >> 5, lane = tid & 31;
    int base = blockIdx.x * 64 + warp * 8;
    for (int i = 0; i < 8; i++) {
        int row = base + i;
        if (row >= n) break;
        const float* rp = lv + (size_t)row * DD;
        float p = rp[lane]      * sW[lane]
                + rp[lane + 32] * sW[lane + 32]
                + rp[lane + 64] * sW[lane + 64]
                + rp[lane + 96] * sW[lane + 96];
#pragma unroll
        for (int o = 16; o > 0; o >>= 1) p += __shfl_xor_sync(0xffffffffu, p, o);
        if (lane == 0) Q[row] = s_s + p;
    }
}

// ---------------------------------------------------------------------------
extern "C" void kernel_launch(void* const* d_in, const int* in_sizes, int n_in,
                              void* d_out, int out_size) {
    const float* x    = (const float*)d_in[0];
    const int*   vci  = (const int*)d_in[1];
    const int*   cvi  = (const int*)d_in[2];
    const float* W_iv = (const float*)d_in[3];
    const float* b_iv = (const float*)d_in[4];
    const float* W_ic = (const float*)d_in[5];
    const float* b_ic = (const float*)d_in[6];
    const float* W_v  = (const float*)d_in[7];
    const float* b_v  = (const float*)d_in[8];
    const float* W_c  = (const float*)d_in[9];
    const float* b_c  = (const float*)d_in[10];
    const float* W_q  = (const float*)d_in[11];
    const float* b_q  = (const float*)d_in[12];
    float* Q = (float*)d_out;

    cudaFuncSetAttribute(layer_dual,
                         cudaFuncAttributeMaxDynamicSharedMemorySize, SM_DYN);

    const float* var_feat = x;
    const float* con_feat = x + (size_t)NVV * FIN;

    prep_w<<<3 + PREP_FEAT_BLOCKS, 256>>>(W_v, W_c, vci, x);
    init_mma<<<2 * NB_INIT, 256>>>(var_feat, con_feat, W_iv, W_ic, b_iv, b_ic, NVV);

    int lv = 0, lc = 2;
    for (int t = 0; t < 3; t++) {
        int nlc = 5 - lc, nlv = 1 - lv;
        layer_dual<<<GRID_TC, 1024, SM_DYN>>>(lv, lc, nlv, nlc,
                                              vci, cvi, b_v, b_c, NVV, t == 2);
        lv = nlv; lc = nlc;
    }

    final_kernel<<<(NVV + 63) / 64, 256>>>(W_q, b_q, Q, NVV);
}

// round 15
// speedup vs baseline: 1.7549x; 1.1115x over previous
#include <cuda_runtime.h>
#include <cuda_fp16.h>
#include <cstdint>

#define NVV 50000
#define DD 128
#define FIN 32
#define DEG 16
#define GRID_TC 304
#define NBLK_SIDE (GRID_TC / 2)          // 152 CTAs per side

#define BM32 32
#define NT32 ((NVV + BM32 - 1) / BM32)   // 1563
#define NSLOT 2

#define WSB 272
#define ACT_STR 592
#define ACT_IMG (32 * ACT_STR)            // 18944

#define SM_W16 0
#define SM_ACT 78336
#define SM_DYN (SM_ACT + NSLOT * ACT_IMG) // 116224 = 232448/2 -> 2 CTAs/SM

#define BAR_SYNC(id)   asm volatile("bar.sync %0, 512;"   :: "r"(id) : "memory")
#define BAR_ARRIVE(id) asm volatile("bar.arrive %0, 512;" :: "r"(id) : "memory")

// ---------------------------------------------------------------------------
__device__ __align__(16) unsigned short g_w16[2][288 * 136];
__device__ __align__(256) float g_lv32[(size_t)NVV * DD];
__device__ __align__(256) __half g_h16[4][(size_t)NVV * DD];
__device__ __align__(16) __half g_feat16[(size_t)2 * NVV * FIN];
__device__ __align__(16) unsigned short g_idx16[2][(size_t)NVV * DEG];
__device__ float g_colsum[DD];

__device__ __forceinline__ uint32_t smem_u32(const void* p) {
    uint32_t a;
    asm("{ .reg .u64 t; cvta.to.shared.u64 t, %1; cvt.u32.u64 %0, t; }" : "=r"(a) : "l"(p));
    return a;
}
__device__ __forceinline__ void ldsm_x4(uint32_t* r, uint32_t addr) {
    asm volatile("ldmatrix.sync.aligned.m8n8.x4.shared.b16 {%0,%1,%2,%3}, [%4];"
                 : "=r"(r[0]), "=r"(r[1]), "=r"(r[2]), "=r"(r[3]) : "r"(addr));
}
__device__ __forceinline__ void ldsm_x4t(uint32_t* r, uint32_t addr) {
    asm volatile("ldmatrix.sync.aligned.m8n8.x4.trans.shared.b16 {%0,%1,%2,%3}, [%4];"
                 : "=r"(r[0]), "=r"(r[1]), "=r"(r[2]), "=r"(r[3]) : "r"(addr));
}
__device__ __forceinline__ void mma_f16(float* d, const uint32_t* a, uint32_t b0, uint32_t b1) {
    asm volatile("mma.sync.aligned.m16n8k16.row.col.f32.f16.f16.f32 "
                 "{%0,%1,%2,%3}, {%4,%5,%6,%7}, {%8,%9}, {%0,%1,%2,%3};"
                 : "+f"(d[0]), "+f"(d[1]), "+f"(d[2]), "+f"(d[3])
                 : "r"(a[0]), "r"(a[1]), "r"(a[2]), "r"(a[3]), "r"(b0), "r"(b1));
}
__device__ __forceinline__ uint32_t pack_h2(float lo, float hi) {
    __half2 h = __floats2half2_rn(lo, hi);
    return *reinterpret_cast<uint32_t*>(&h);
}
__device__ __forceinline__ uint2 pack4_h(float4 v) {
    uint2 r;
    r.x = pack_h2(v.x, v.y);
    r.y = pack_h2(v.z, v.w);
    return r;
}
__device__ __forceinline__ __half2 u2h(uint32_t u) { return *reinterpret_cast<__half2*>(&u); }
__device__ __forceinline__ uint32_t h2u(__half2 h) { return *reinterpret_cast<uint32_t*>(&h); }

// ---------------------------------------------------------------------------
// setup_all: one launch does init-embedding GEMMs + W split + feat16 + idx16.
// blocks [0, 2*NB_INIT)            : init embedding tiles (even V, odd C)
// block  2*NB_INIT + 0 / + 1       : W_v / W_c split
// block  2*NB_INIT + 2             : colsum zero
// blocks [2*NB_INIT+3, +3+32)      : feat -> fp16
// blocks [2*NB_INIT+35, +35+64)    : idx -> uint16 compaction
// ---------------------------------------------------------------------------
#define NB_INIT ((NVV + 127) / 128)       // 391
#define AUX0 (2 * NB_INIT)                // 782
#define NB_FEAT 32
#define NB_IDX 64
#define NB_SETUP (AUX0 + 3 + NB_FEAT + NB_IDX)

#define ISM_B 0
#define ISM_ACT 8704
#define IACT_STR 80

__global__ __launch_bounds__(256, 1)
void setup_all(const float* __restrict__ x,
               const int* __restrict__ vci, const int* __restrict__ cvi,
               const float* __restrict__ Wiv, const float* __restrict__ Wic,
               const float* __restrict__ biv, const float* __restrict__ bic,
               const float* __restrict__ Wv, const float* __restrict__ Wc, int n) {
    int bid = blockIdx.x;
    int tid = threadIdx.x;

    if (bid >= AUX0) {
        int aux = bid - AUX0;
        if (aux == 0 || aux == 1) {
            const float* W = aux ? Wc : Wv;
            for (int e = tid; e < 288 * 136; e += 256) {
                int k = e / 136, nn = e - k * 136;
                float w = (nn < 128) ? W[nn * 288 + k] : 0.f;
                __half h = __float2half_rn(w);
                g_w16[aux][e] = *reinterpret_cast<unsigned short*>(&h);
            }
        } else if (aux == 2) {
            if (tid < DD) g_colsum[tid] = 0.f;
        } else if (aux < 3 + NB_FEAT) {
            int fb = aux - 3;
            const int total = 2 * NVV * FIN;
            for (int e = fb * 256 + tid; e < total; e += NB_FEAT * 256)
                g_feat16[e] = __float2half_rn(x[e]);
        } else {
            // idx compaction: detect width from vci, then pack both arrays.
            __shared__ int s_is64;
            if (tid == 0) {
                int nz = 0;
#pragma unroll
                for (int i = 0; i < 64; i++) nz |= vci[2 * i + 1];
                s_is64 = (nz == 0) ? 1 : 0;
            }
            __syncthreads();
            int is64 = s_is64;
            int ib = aux - (3 + NB_FEAT);
            const int rows = 2 * NVV;
            for (int r = ib * 256 + tid; r < rows; r += NB_IDX * 256) {
                const int* src = (r < NVV) ? vci : cvi;
                int lr = (r < NVV) ? r : r - NVV;
                unsigned short* dst = g_idx16[(r < NVV) ? 0 : 1] + (size_t)lr * DEG;
                const int* ip = src + (size_t)lr * DEG * (is64 ? 2 : 1);
                uint32_t w[8];
#pragma unroll
                for (int q = 0; q < 8; q++) {
                    int a = is64 ? ip[4 * q]     : ip[2 * q];
                    int b = is64 ? ip[4 * q + 2] : ip[2 * q + 1];
                    w[q] = (uint32_t)(a & 0xffff) | ((uint32_t)(b & 0xffff) << 16);
                }
                uint4* d4 = (uint4*)dst;
                d4[0] = make_uint4(w[0], w[1], w[2], w[3]);
                d4[1] = make_uint4(w[4], w[5], w[6], w[7]);
            }
        }
        return;
    }

    // ---- init embedding tile ----
    __shared__ __align__(16) char ism[ISM_ACT + 128 * IACT_STR];
    uint32_t smb = smem_u32(ism);
    int side = bid & 1;
    int blk = bid >> 1;
    const float* feat = x + (side ? (size_t)NVV * FIN : 0);
    const float* W    = side ? Wic : Wiv;
    const float* b    = side ? bic : biv;
    __half* out16 = g_h16[side ? 2 : 0];

    int wid = tid >> 5, lane = tid & 31;
    int row0 = blk * 128;

    for (int e = tid; e < 32 * 136; e += 256) {
        int k = e / 136, nn = e - k * 136;
        float w = (nn < 128) ? W[nn * FIN + k] : 0.f;
        __half h = __float2half_rn(w);
        *(unsigned short*)(ism + ISM_B + k * WSB + nn * 2) =
            *reinterpret_cast<unsigned short*>(&h);
    }
    {
        int r = tid >> 1, half = tid & 1;
        int gr = row0 + r;
        char* rowp = ism + ISM_ACT + r * IACT_STR + half * 32;
#pragma unroll
        for (int i = 0; i < 4; i++) {
            float4 v = (gr < n)
                ? reinterpret_cast<const float4*>(feat + (size_t)gr * FIN)[half * 4 + i]
                : make_float4(0.f, 0.f, 0.f, 0.f);
            *(uint2*)(rowp + i * 8) = pack4_h(v);
        }
    }
    __syncthreads();

    int wm = wid >> 1, wn = wid & 1;
    int rsel = lane & 15, csel = lane >> 4;
    uint32_t aBase = smb + ISM_ACT + (uint32_t)((32 * wm + rsel) * IACT_STR + csel * 16);
    uint32_t bBase = smb + ISM_B + (uint32_t)(rsel * WSB + csel * 16 + 128 * wn);

    float acc[2][8][4];
#pragma unroll
    for (int mt = 0; mt < 2; mt++)
#pragma unroll
        for (int nt = 0; nt < 8; nt++)
#pragma unroll
            for (int q = 0; q < 4; q++) acc[mt][nt][q] = 0.f;

#pragma unroll
    for (int ks = 0; ks < 2; ks++) {
        uint32_t a[2][4], bf[4][4];
#pragma unroll
        for (int mt = 0; mt < 2; mt++)
            ldsm_x4(a[mt], aBase + (uint32_t)(16 * mt * IACT_STR + ks * 32));
#pragma unroll
        for (int np = 0; np < 4; np++)
            ldsm_x4t(bf[np], bBase + (uint32_t)(ks * 16 * WSB + 32 * np));
#pragma unroll
        for (int mt = 0; mt < 2; mt++)
#pragma unroll
            for (int nt = 0; nt < 8; nt++)
                mma_f16(acc[mt][nt], a[mt], bf[nt >> 1][2 * (nt & 1)], bf[nt >> 1][2 * (nt & 1) + 1]);
    }

    int r_lo = lane >> 2;
    int cpair = (lane & 3) * 2;
#pragma unroll
    for (int mt = 0; mt < 2; mt++) {
        int ra = row0 + 32 * wm + 16 * mt + r_lo;
#pragma unroll
        for (int nt = 0; nt < 8; nt++) {
            int col = 64 * wn + 8 * nt + cpair;
            float b0 = b[col], b1 = b[col + 1];
            if (ra < n)
                *(__half2*)(out16 + (size_t)ra * DD + col) =
                    __floats2half2_rn(acc[mt][nt][0] + b0, acc[mt][nt][1] + b1);
            if (ra + 8 < n)
                *(__half2*)(out16 + (size_t)(ra + 8) * DD + col) =
                    __floats2half2_rn(acc[mt][nt][2] + b0, acc[mt][nt][3] + b1);
        }
    }
}

// ---------------------------------------------------------------------------
// Producer: one 288-wide row; idx from compact uint16; agg HADD2; raw copies.
// ---------------------------------------------------------------------------
__device__ __forceinline__ void gather_row(
    const __half* __restrict__ agg16, const __half* __restrict__ self16,
    const __half* __restrict__ feat16, const unsigned short* __restrict__ idx16,
    int gr, int n, int lane, uint2* G)
{
    bool val = gr < n;
    const uint4* ip = (const uint4*)(idx16 + (size_t)(val ? gr : 0) * DEG);
    uint4 p0 = __ldg(ip), p1 = __ldg(ip + 1);
    uint32_t w[8] = {p0.x, p0.y, p0.z, p0.w, p1.x, p1.y, p1.z, p1.w};
    int srcs[DEG];
#pragma unroll
    for (int q = 0; q < 8; q++) {
        srcs[2 * q]     = (int)(w[q] & 0xffffu);
        srcs[2 * q + 1] = (int)(w[q] >> 16);
    }

    __half2 ax[4], ay[4];
#pragma unroll
    for (int j = 0; j < 4; j++) {
        uint2 d = __ldg(reinterpret_cast<const uint2*>(agg16 + (size_t)srcs[j] * DD) + lane);
        ax[j] = u2h(d.x); ay[j] = u2h(d.y);
    }
#pragma unroll
    for (int j = 4; j < DEG; j++) {
        uint2 d = __ldg(reinterpret_cast<const uint2*>(agg16 + (size_t)srcs[j] * DD) + lane);
        ax[j & 3] = __hadd2(ax[j & 3], u2h(d.x));
        ay[j & 3] = __hadd2(ay[j & 3], u2h(d.y));
    }
    __half2 sx = __hadd2(__hadd2(ax[0], ax[1]), __hadd2(ax[2], ax[3]));
    __half2 sy = __hadd2(__hadd2(ay[0], ay[1]), __hadd2(ay[2], ay[3]));

    uint2 sv = val ? __ldg(reinterpret_cast<const uint2*>(self16 + (size_t)gr * DD) + lane)
                   : make_uint2(0u, 0u);
    uint2 fv = (val && lane < 8)
        ? __ldg(reinterpret_cast<const uint2*>(feat16 + (size_t)gr * FIN) + lane)
        : make_uint2(0u, 0u);

    if (!val) { sx = u2h(0u); sy = u2h(0u); }
    G[0].x = h2u(sx); G[0].y = h2u(sy);
    G[1] = sv;
    G[2] = fv;
}

__device__ __forceinline__ void sts_row(char* act, int r, int lane, const uint2* G) {
    char* rowp = act + r * ACT_STR;
    *(uint2*)(rowp + lane * 8) = G[0];
    *(uint2*)(rowp + 256 + lane * 8) = G[1];
    if (lane < 8) *(uint2*)(rowp + 512 + lane * 8) = G[2];
}

// ---------------------------------------------------------------------------
// Dual-side layer: 512 threads, 2 CTAs/SM. Warps 8-15 produce (4 rows each,
// pre-gathered), warps 0-7 consume (2m x 4n, 16x32 tiles). 32-row slabs,
// 2-slot ring, per-CTA barrier domain.
// ---------------------------------------------------------------------------
__global__ __launch_bounds__(512, 2)
void layer_dual(int lv_sel, int lc_sel, int nlv_sel, int nlc_sel,
                const float* __restrict__ bv, const float* __restrict__ bc,
                int n, int last)
{
    extern __shared__ char sm[];
    uint32_t smb = smem_u32(sm);

    int side = blockIdx.x & 1;
    int blk = blockIdx.x >> 1;

    const __half* agg16; const __half* self16; __half* out16;
    const __half* feat16; const unsigned short* idx16; const float* b; int which;
    if (side == 0) {
        agg16 = g_h16[lv_sel]; self16 = g_h16[lc_sel]; out16 = g_h16[nlc_sel];
        feat16 = g_feat16 + (size_t)NVV * FIN; idx16 = g_idx16[1]; b = bc; which = 1;
    } else {
        agg16 = g_h16[lc_sel]; self16 = g_h16[lv_sel]; out16 = g_h16[nlv_sel];
        feat16 = g_feat16; idx16 = g_idx16[0]; b = bv; which = 0;
    }

    int tid = threadIdx.x, wid = tid >> 5, lane = tid & 31;

    {
        const uint4* sw = (const uint4*)g_w16[which];
        uint4* dw = (uint4*)(sm + SM_W16);
        for (int i = tid; i < 78336 / 16; i += 512) dw[i] = sw[i];
    }
    __syncthreads();

    if (wid >= 8) {
        // ================= PRODUCERS (8 warps, 4 rows each) =================
        int pw = wid - 8;
        int it = 0;
        for (int tile = blk; tile < NT32; tile += NBLK_SIDE, it++) {
            int slot = it & (NSLOT - 1);
            int row0 = tile * BM32 + pw * 4;

            uint2 G[4][3];
#pragma unroll
            for (int rr = 0; rr < 4; rr++)
                gather_row(agg16, self16, feat16, idx16, row0 + rr, n, lane, G[rr]);

            BAR_SYNC(3 + slot);        // wait slot empty
            char* act = sm + SM_ACT + slot * ACT_IMG;
#pragma unroll
            for (int rr = 0; rr < 4; rr++)
                sts_row(act, pw * 4 + rr, lane, G[rr]);
            BAR_ARRIVE(1 + slot);      // mark full
        }
    } else {
        // ================= CONSUMERS (8 warps: 2m x 4n, 16x32) ==============
        int wm = wid >> 2, wn = wid & 3;
        int rsel = lane & 15, csel = lane >> 4;
        BAR_ARRIVE(3); BAR_ARRIVE(4);  // prime both slots empty

        uint32_t aOff = (uint32_t)((16 * wm + rsel) * ACT_STR + csel * 16);
        uint32_t bBase = smb + SM_W16 + (uint32_t)(rsel * WSB + csel * 16 + 64 * wn);

        int cpair = (lane & 3) * 2;
        float2 bb[4];
#pragma unroll
        for (int nt = 0; nt < 4; nt++) {
            int col = 32 * wn + 8 * nt + cpair;
            bb[nt].x = b[col]; bb[nt].y = b[col + 1];
        }
        int do32 = last && (side == 1);
        float2 csum[4];
#pragma unroll
        for (int nt = 0; nt < 4; nt++) csum[nt] = make_float2(0.f, 0.f);

        int it = 0;
        for (int tile = blk; tile < NT32; tile += NBLK_SIDE, it++) {
            int slot = it & (NSLOT - 1);
            BAR_SYNC(1 + slot);        // wait full
            uint32_t aBase = smb + SM_ACT + (uint32_t)(slot * ACT_IMG) + aOff;

            float acc[4][4];
#pragma unroll
            for (int nt = 0; nt < 4; nt++)
#pragma unroll
                for (int q = 0; q < 4; q++) acc[nt][q] = 0.f;

#pragma unroll 3
            for (int ks = 0; ks < 18; ks++) {
                uint32_t a[4], bf[2][4];
                ldsm_x4(a, aBase + (uint32_t)(ks * 32));
#pragma unroll
                for (int np = 0; np < 2; np++)
                    ldsm_x4t(bf[np], bBase + (uint32_t)(ks * 16 * WSB + 32 * np));
#pragma unroll
                for (int nt = 0; nt < 4; nt++)
                    mma_f16(acc[nt], a, bf[nt >> 1][2 * (nt & 1)], bf[nt >> 1][2 * (nt & 1) + 1]);
            }
            BAR_ARRIVE(3 + slot);      // slot free

            int row0 = tile * BM32;
            int r_lo = lane >> 2;
            int ra0 = row0 + 16 * wm + r_lo;
#pragma unroll
            for (int nt = 0; nt < 4; nt++) {
                int col = 32 * wn + 8 * nt + cpair;
                if (ra0 < n) {
                    float v0 = acc[nt][0] + bb[nt].x, v1 = acc[nt][1] + bb[nt].y;
                    *(__half2*)(out16 + (size_t)ra0 * DD + col) = __floats2half2_rn(v0, v1);
                    if (do32) {
                        *(float2*)(g_lv32 + (size_t)ra0 * DD + col) = make_float2(v0, v1);
                        csum[nt].x += v0; csum[nt].y += v1;
                    }
                }
                if (ra0 + 8 < n) {
                    float v0 = acc[nt][2] + bb[nt].x, v1 = acc[nt][3] + bb[nt].y;
                    *(__half2*)(out16 + (size_t)(ra0 + 8) * DD + col) = __floats2half2_rn(v0, v1);
                    if (do32) {
                        *(float2*)(g_lv32 + (size_t)(ra0 + 8) * DD + col) = make_float2(v0, v1);
                        csum[nt].x += v0; csum[nt].y += v1;
                    }
                }
            }
        }

        if (do32) {
#pragma unroll
            for (int nt = 0; nt < 4; nt++) {
                float c0 = csum[nt].x, c1 = csum[nt].y;
#pragma unroll
                for (int o = 4; o < 32; o <<= 1) {
                    c0 += __shfl_xor_sync(0xffffffffu, c0, o);
                    c1 += __shfl_xor_sync(0xffffffffu, c1, o);
                }
                if (lane < 4) {
                    int col = 32 * wn + 8 * nt + lane * 2;
                    atomicAdd(&g_colsum[col], c0);
                    atomicAdd(&g_colsum[col + 1], c1);
                }
            }
        }
    }
}

// ---------------------------------------------------------------------------
__global__ void final_kernel(const float* __restrict__ Wq,
                             const float* __restrict__ bq,
                             float* __restrict__ Q, int n) {
    const float* lv = g_lv32;
    __shared__ float sW[DD];
    __shared__ float s_s;
    int tid = threadIdx.x;
    if (tid < DD) sW[tid] = Wq[DD + tid];
    if (tid < 32) {
        float p = 0.f;
#pragma unroll
        for (int t = 0; t < 4; t++) p += g_colsum[tid + 32 * t] * Wq[tid + 32 * t];
#pragma unroll
        for (int o = 16; o > 0; o >>= 1) p += __shfl_xor_sync(0xffffffffu, p, o);
        if (tid == 0) s_s = p + bq[0];
    }
    __syncthreads();
    int warp = tid >> 5, lane = tid & 31;
    int base = blockIdx.x * 64 + warp * 8;
    for (int i = 0; i < 8; i++) {
        int row = base + i;
        if (row >= n) break;
        const float* rp = lv + (size_t)row * DD;
        float p = rp[lane]      * sW[lane]
                + rp[lane + 32] * sW[lane + 32]
                + rp[lane + 64] * sW[lane + 64]
                + rp[lane + 96] * sW[lane + 96];
#pragma unroll
        for (int o = 16; o > 0; o >>= 1) p += __shfl_xor_sync(0xffffffffu, p, o);
        if (lane == 0) Q[row] = s_s + p;
    }
}

// ---------------------------------------------------------------------------
extern "C" void kernel_launch(void* const* d_in, const int* in_sizes, int n_in,
                              void* d_out, int out_size) {
    const float* x    = (const float*)d_in[0];
    const int*   vci  = (const int*)d_in[1];
    const int*   cvi  = (const int*)d_in[2];
    const float* W_iv = (const float*)d_in[3];
    const float* b_iv = (const float*)d_in[4];
    const float* W_ic = (const float*)d_in[5];
    const float* b_ic = (const float*)d_in[6];
    const float* W_v  = (const float*)d_in[7];
    const float* b_v  = (const float*)d_in[8];
    const float* W_c  = (const float*)d_in[9];
    const float* b_c  = (const float*)d_in[10];
    const float* W_q  = (const float*)d_in[11];
    const float* b_q  = (const float*)d_in[12];
    float* Q = (float*)d_out;

    cudaFuncSetAttribute(layer_dual,
                         cudaFuncAttributeMaxDynamicSharedMemorySize, SM_DYN);

    setup_all<<<NB_SETUP, 256>>>(x, vci, cvi, W_iv, W_ic, b_iv, b_ic, W_v, W_c, NVV);

    int lv = 0, lc = 2;
    for (int t = 0; t < 3; t++) {
        int nlc = 5 - lc, nlv = 1 - lv;
        layer_dual<<<GRID_TC, 512, SM_DYN>>>(lv, lc, nlv, nlc, b_v, b_c, NVV, t == 2);
        lv = nlv; lc = nlc;
    }

    final_kernel<<<(NVV + 63) / 64, 256>>>(W_q, b_q, Q, NVV);
}

// round 16
// speedup vs baseline: 1.7760x; 1.0120x over previous
#include <cuda_runtime.h>
#include <cuda_fp16.h>
#include <cstdint>

#define NVV 50000
#define DD 128
#define FIN 32
#define DEG 16
#define GRID_TC 152
#define NBLK_SIDE (GRID_TC / 2)          // 76 CTAs per side

#define BM32 32
#define NT32 ((NVV + BM32 - 1) / BM32)   // 1563
#define NSLOT 2

#define WSB 272
#define ACT_STR 592
#define ACT_IMG (32 * ACT_STR)            // 18944

#define SM_W16 0
#define SM_ACT 78336
#define SM_DYN (SM_ACT + NSLOT * ACT_IMG) // 116224

#define BAR_SYNC(id)   asm volatile("bar.sync %0, 512;"   :: "r"(id) : "memory")
#define BAR_ARRIVE(id) asm volatile("bar.arrive %0, 512;" :: "r"(id) : "memory")

// ---------------------------------------------------------------------------
__device__ __align__(16) unsigned short g_w16[2][288 * 136];
__device__ __align__(256) float g_lv32[(size_t)NVV * DD];
__device__ __align__(256) __half g_h16[4][(size_t)NVV * DD];
__device__ __align__(16) __half g_feat16[(size_t)2 * NVV * FIN];
__device__ __align__(16) unsigned short g_idx16[2][(size_t)NVV * DEG];
__device__ float g_colsum[DD];

__device__ __forceinline__ uint32_t smem_u32(const void* p) {
    uint32_t a;
    asm("{ .reg .u64 t; cvta.to.shared.u64 t, %1; cvt.u32.u64 %0, t; }" : "=r"(a) : "l"(p));
    return a;
}
__device__ __forceinline__ void ldsm_x4(uint32_t* r, uint32_t addr) {
    asm volatile("ldmatrix.sync.aligned.m8n8.x4.shared.b16 {%0,%1,%2,%3}, [%4];"
                 : "=r"(r[0]), "=r"(r[1]), "=r"(r[2]), "=r"(r[3]) : "r"(addr));
}
__device__ __forceinline__ void ldsm_x4t(uint32_t* r, uint32_t addr) {
    asm volatile("ldmatrix.sync.aligned.m8n8.x4.trans.shared.b16 {%0,%1,%2,%3}, [%4];"
                 : "=r"(r[0]), "=r"(r[1]), "=r"(r[2]), "=r"(r[3]) : "r"(addr));
}
__device__ __forceinline__ void mma_f16(float* d, const uint32_t* a, uint32_t b0, uint32_t b1) {
    asm volatile("mma.sync.aligned.m16n8k16.row.col.f32.f16.f16.f32 "
                 "{%0,%1,%2,%3}, {%4,%5,%6,%7}, {%8,%9}, {%0,%1,%2,%3};"
                 : "+f"(d[0]), "+f"(d[1]), "+f"(d[2]), "+f"(d[3])
                 : "r"(a[0]), "r"(a[1]), "r"(a[2]), "r"(a[3]), "r"(b0), "r"(b1));
}
__device__ __forceinline__ uint32_t pack_h2(float lo, float hi) {
    __half2 h = __floats2half2_rn(lo, hi);
    return *reinterpret_cast<uint32_t*>(&h);
}
__device__ __forceinline__ uint2 pack4_h(float4 v) {
    uint2 r;
    r.x = pack_h2(v.x, v.y);
    r.y = pack_h2(v.z, v.w);
    return r;
}
__device__ __forceinline__ __half2 u2h(uint32_t u) { return *reinterpret_cast<__half2*>(&u); }
__device__ __forceinline__ uint32_t h2u(__half2 h) { return *reinterpret_cast<uint32_t*>(&h); }

// ---------------------------------------------------------------------------
// setup_all (unchanged from R15): init GEMMs + W split + feat16 + idx16.
// ---------------------------------------------------------------------------
#define NB_INIT ((NVV + 127) / 128)       // 391
#define AUX0 (2 * NB_INIT)                // 782
#define NB_FEAT 32
#define NB_IDX 64
#define NB_SETUP (AUX0 + 3 + NB_FEAT + NB_IDX)

#define ISM_B 0
#define ISM_ACT 8704
#define IACT_STR 80

__global__ __launch_bounds__(256, 1)
void setup_all(const float* __restrict__ x,
               const int* __restrict__ vci, const int* __restrict__ cvi,
               const float* __restrict__ Wiv, const float* __restrict__ Wic,
               const float* __restrict__ biv, const float* __restrict__ bic,
               const float* __restrict__ Wv, const float* __restrict__ Wc, int n) {
    int bid = blockIdx.x;
    int tid = threadIdx.x;

    if (bid >= AUX0) {
        int aux = bid - AUX0;
        if (aux == 0 || aux == 1) {
            const float* W = aux ? Wc : Wv;
            for (int e = tid; e < 288 * 136; e += 256) {
                int k = e / 136, nn = e - k * 136;
                float w = (nn < 128) ? W[nn * 288 + k] : 0.f;
                __half h = __float2half_rn(w);
                g_w16[aux][e] = *reinterpret_cast<unsigned short*>(&h);
            }
        } else if (aux == 2) {
            if (tid < DD) g_colsum[tid] = 0.f;
        } else if (aux < 3 + NB_FEAT) {
            int fb = aux - 3;
            const int total = 2 * NVV * FIN;
            for (int e = fb * 256 + tid; e < total; e += NB_FEAT * 256)
                g_feat16[e] = __float2half_rn(x[e]);
        } else {
            __shared__ int s_is64;
            if (tid == 0) {
                int nz = 0;
#pragma unroll
                for (int i = 0; i < 64; i++) nz |= vci[2 * i + 1];
                s_is64 = (nz == 0) ? 1 : 0;
            }
            __syncthreads();
            int is64 = s_is64;
            int ib = aux - (3 + NB_FEAT);
            const int rows = 2 * NVV;
            for (int r = ib * 256 + tid; r < rows; r += NB_IDX * 256) {
                const int* src = (r < NVV) ? vci : cvi;
                int lr = (r < NVV) ? r : r - NVV;
                unsigned short* dst = g_idx16[(r < NVV) ? 0 : 1] + (size_t)lr * DEG;
                const int* ip = src + (size_t)lr * DEG * (is64 ? 2 : 1);
                uint32_t w[8];
#pragma unroll
                for (int q = 0; q < 8; q++) {
                    int a = is64 ? ip[4 * q]     : ip[2 * q];
                    int b = is64 ? ip[4 * q + 2] : ip[2 * q + 1];
                    w[q] = (uint32_t)(a & 0xffff) | ((uint32_t)(b & 0xffff) << 16);
                }
                uint4* d4 = (uint4*)dst;
                d4[0] = make_uint4(w[0], w[1], w[2], w[3]);
                d4[1] = make_uint4(w[4], w[5], w[6], w[7]);
            }
        }
        return;
    }

    // ---- init embedding tile ----
    __shared__ __align__(16) char ism[ISM_ACT + 128 * IACT_STR];
    uint32_t smb = smem_u32(ism);
    int side = bid & 1;
    int blk = bid >> 1;
    const float* feat = x + (side ? (size_t)NVV * FIN : 0);
    const float* W    = side ? Wic : Wiv;
    const float* b    = side ? bic : biv;
    __half* out16 = g_h16[side ? 2 : 0];

    int wid = tid >> 5, lane = tid & 31;
    int row0 = blk * 128;

    for (int e = tid; e < 32 * 136; e += 256) {
        int k = e / 136, nn = e - k * 136;
        float w = (nn < 128) ? W[nn * FIN + k] : 0.f;
        __half h = __float2half_rn(w);
        *(unsigned short*)(ism + ISM_B + k * WSB + nn * 2) =
            *reinterpret_cast<unsigned short*>(&h);
    }
    {
        int r = tid >> 1, half = tid & 1;
        int gr = row0 + r;
        char* rowp = ism + ISM_ACT + r * IACT_STR + half * 32;
#pragma unroll
        for (int i = 0; i < 4; i++) {
            float4 v = (gr < n)
                ? reinterpret_cast<const float4*>(feat + (size_t)gr * FIN)[half * 4 + i]
                : make_float4(0.f, 0.f, 0.f, 0.f);
            *(uint2*)(rowp + i * 8) = pack4_h(v);
        }
    }
    __syncthreads();

    int wm = wid >> 1, wn = wid & 1;
    int rsel = lane & 15, csel = lane >> 4;
    uint32_t aBase = smb + ISM_ACT + (uint32_t)((32 * wm + rsel) * IACT_STR + csel * 16);
    uint32_t bBase = smb + ISM_B + (uint32_t)(rsel * WSB + csel * 16 + 128 * wn);

    float acc[2][8][4];
#pragma unroll
    for (int mt = 0; mt < 2; mt++)
#pragma unroll
        for (int nt = 0; nt < 8; nt++)
#pragma unroll
            for (int q = 0; q < 4; q++) acc[mt][nt][q] = 0.f;

#pragma unroll
    for (int ks = 0; ks < 2; ks++) {
        uint32_t a[2][4], bf[4][4];
#pragma unroll
        for (int mt = 0; mt < 2; mt++)
            ldsm_x4(a[mt], aBase + (uint32_t)(16 * mt * IACT_STR + ks * 32));
#pragma unroll
        for (int np = 0; np < 4; np++)
            ldsm_x4t(bf[np], bBase + (uint32_t)(ks * 16 * WSB + 32 * np));
#pragma unroll
        for (int mt = 0; mt < 2; mt++)
#pragma unroll
            for (int nt = 0; nt < 8; nt++)
                mma_f16(acc[mt][nt], a[mt], bf[nt >> 1][2 * (nt & 1)], bf[nt >> 1][2 * (nt & 1) + 1]);
    }

    int r_lo = lane >> 2;
    int cpair = (lane & 3) * 2;
#pragma unroll
    for (int mt = 0; mt < 2; mt++) {
        int ra = row0 + 32 * wm + 16 * mt + r_lo;
#pragma unroll
        for (int nt = 0; nt < 8; nt++) {
            int col = 64 * wn + 8 * nt + cpair;
            float b0 = b[col], b1 = b[col + 1];
            if (ra < n)
                *(__half2*)(out16 + (size_t)ra * DD + col) =
                    __floats2half2_rn(acc[mt][nt][0] + b0, acc[mt][nt][1] + b1);
            if (ra + 8 < n)
                *(__half2*)(out16 + (size_t)(ra + 8) * DD + col) =
                    __floats2half2_rn(acc[mt][nt][2] + b0, acc[mt][nt][3] + b1);
        }
    }
}

// ---------------------------------------------------------------------------
// Producer: gather TWO rows with all loads issued before reductions (MLP 2x).
// ---------------------------------------------------------------------------
__device__ __forceinline__ void gather_pair(
    const __half* __restrict__ agg16, const __half* __restrict__ self16,
    const __half* __restrict__ feat16, const unsigned short* __restrict__ idx16,
    int gr0, int n, int lane, uint2* GA, uint2* GB)
{
    bool va = gr0 < n, vb = gr0 + 1 < n;
    const uint4* ipa = (const uint4*)(idx16 + (size_t)(va ? gr0 : 0) * DEG);
    const uint4* ipb = (const uint4*)(idx16 + (size_t)(vb ? gr0 + 1 : 0) * DEG);
    uint4 pa0 = __ldg(ipa), pa1 = __ldg(ipa + 1);
    uint4 pb0 = __ldg(ipb), pb1 = __ldg(ipb + 1);
    uint32_t wa[8] = {pa0.x, pa0.y, pa0.z, pa0.w, pa1.x, pa1.y, pa1.z, pa1.w};
    uint32_t wb[8] = {pb0.x, pb0.y, pb0.z, pb0.w, pb1.x, pb1.y, pb1.z, pb1.w};

    // issue ALL 32 gather loads + self/feat before any reduction
    uint2 da[DEG], db[DEG];
#pragma unroll
    for (int q = 0; q < 8; q++) {
        int s0 = (int)(wa[q] & 0xffffu), s1 = (int)(wa[q] >> 16);
        da[2*q]   = __ldg(reinterpret_cast<const uint2*>(agg16 + (size_t)s0 * DD) + lane);
        da[2*q+1] = __ldg(reinterpret_cast<const uint2*>(agg16 + (size_t)s1 * DD) + lane);
    }
#pragma unroll
    for (int q = 0; q < 8; q++) {
        int s0 = (int)(wb[q] & 0xffffu), s1 = (int)(wb[q] >> 16);
        db[2*q]   = __ldg(reinterpret_cast<const uint2*>(agg16 + (size_t)s0 * DD) + lane);
        db[2*q+1] = __ldg(reinterpret_cast<const uint2*>(agg16 + (size_t)s1 * DD) + lane);
    }
    uint2 sva = va ? __ldg(reinterpret_cast<const uint2*>(self16 + (size_t)gr0 * DD) + lane)
                   : make_uint2(0u, 0u);
    uint2 svb = vb ? __ldg(reinterpret_cast<const uint2*>(self16 + (size_t)(gr0 + 1) * DD) + lane)
                   : make_uint2(0u, 0u);
    uint2 fva = (va && lane < 8)
        ? __ldg(reinterpret_cast<const uint2*>(feat16 + (size_t)gr0 * FIN) + lane)
        : make_uint2(0u, 0u);
    uint2 fvb = (vb && lane < 8)
        ? __ldg(reinterpret_cast<const uint2*>(feat16 + (size_t)(gr0 + 1) * FIN) + lane)
        : make_uint2(0u, 0u);

    // reductions (loads already in flight / landed)
    __half2 ax0 = u2h(da[0].x), ay0 = u2h(da[0].y);
    __half2 ax1 = u2h(da[1].x), ay1 = u2h(da[1].y);
    __half2 ax2 = u2h(da[2].x), ay2 = u2h(da[2].y);
    __half2 ax3 = u2h(da[3].x), ay3 = u2h(da[3].y);
#pragma unroll
    for (int j = 4; j < DEG; j += 4) {
        ax0 = __hadd2(ax0, u2h(da[j].x));   ay0 = __hadd2(ay0, u2h(da[j].y));
        ax1 = __hadd2(ax1, u2h(da[j+1].x)); ay1 = __hadd2(ay1, u2h(da[j+1].y));
        ax2 = __hadd2(ax2, u2h(da[j+2].x)); ay2 = __hadd2(ay2, u2h(da[j+2].y));
        ax3 = __hadd2(ax3, u2h(da[j+3].x)); ay3 = __hadd2(ay3, u2h(da[j+3].y));
    }
    __half2 sax = __hadd2(__hadd2(ax0, ax1), __hadd2(ax2, ax3));
    __half2 say = __hadd2(__hadd2(ay0, ay1), __hadd2(ay2, ay3));

    __half2 bx0 = u2h(db[0].x), by0 = u2h(db[0].y);
    __half2 bx1 = u2h(db[1].x), by1 = u2h(db[1].y);
    __half2 bx2 = u2h(db[2].x), by2 = u2h(db[2].y);
    __half2 bx3 = u2h(db[3].x), by3 = u2h(db[3].y);
#pragma unroll
    for (int j = 4; j < DEG; j += 4) {
        bx0 = __hadd2(bx0, u2h(db[j].x));   by0 = __hadd2(by0, u2h(db[j].y));
        bx1 = __hadd2(bx1, u2h(db[j+1].x)); by1 = __hadd2(by1, u2h(db[j+1].y));
        bx2 = __hadd2(bx2, u2h(db[j+2].x)); by2 = __hadd2(by2, u2h(db[j+2].y));
        bx3 = __hadd2(bx3, u2h(db[j+3].x)); by3 = __hadd2(by3, u2h(db[j+3].y));
    }
    __half2 sbx = __hadd2(__hadd2(bx0, bx1), __hadd2(bx2, bx3));
    __half2 sby = __hadd2(__hadd2(by0, by1), __hadd2(by2, by3));

    if (!va) { sax = u2h(0u); say = u2h(0u); }
    if (!vb) { sbx = u2h(0u); sby = u2h(0u); }
    GA[0].x = h2u(sax); GA[0].y = h2u(say); GA[1] = sva; GA[2] = fva;
    GB[0].x = h2u(sbx); GB[0].y = h2u(sby); GB[1] = svb; GB[2] = fvb;
}

__device__ __forceinline__ void sts_row(char* act, int r, int lane, const uint2* G) {
    char* rowp = act + r * ACT_STR;
    *(uint2*)(rowp + lane * 8) = G[0];
    *(uint2*)(rowp + 256 + lane * 8) = G[1];
    if (lane < 8) *(uint2*)(rowp + 512 + lane * 8) = G[2];
}

// ---------------------------------------------------------------------------
// Dual-side layer: 512 threads, 128 regs (occupancy 1), grid 152 (1 wave).
// Producers: 8 warps x 4 rows (2 pairs, batched loads). Consumers: 8 warps
// (2m x 4n) with double-buffered ldsm fragments.
// ---------------------------------------------------------------------------
__global__ __launch_bounds__(512, 1)
void layer_dual(int lv_sel, int lc_sel, int nlv_sel, int nlc_sel,
                const float* __restrict__ bv, const float* __restrict__ bc,
                int n, int last)
{
    extern __shared__ char sm[];
    uint32_t smb = smem_u32(sm);

    int side = blockIdx.x & 1;
    int blk = blockIdx.x >> 1;

    const __half* agg16; const __half* self16; __half* out16;
    const __half* feat16; const unsigned short* idx16; const float* b; int which;
    if (side == 0) {
        agg16 = g_h16[lv_sel]; self16 = g_h16[lc_sel]; out16 = g_h16[nlc_sel];
        feat16 = g_feat16 + (size_t)NVV * FIN; idx16 = g_idx16[1]; b = bc; which = 1;
    } else {
        agg16 = g_h16[lc_sel]; self16 = g_h16[lv_sel]; out16 = g_h16[nlv_sel];
        feat16 = g_feat16; idx16 = g_idx16[0]; b = bv; which = 0;
    }

    int tid = threadIdx.x, wid = tid >> 5, lane = tid & 31;

    {
        const uint4* sw = (const uint4*)g_w16[which];
        uint4* dw = (uint4*)(sm + SM_W16);
        for (int i = tid; i < 78336 / 16; i += 512) dw[i] = sw[i];
    }
    __syncthreads();

    if (wid >= 8) {
        // ================= PRODUCERS (8 warps, 4 rows each) =================
        int pw = wid - 8;
        int it = 0;
        for (int tile = blk; tile < NT32; tile += NBLK_SIDE, it++) {
            int slot = it & (NSLOT - 1);
            int row0 = tile * BM32 + pw * 4;

            uint2 G[4][3];
            gather_pair(agg16, self16, feat16, idx16, row0 + 0, n, lane, G[0], G[1]);
            gather_pair(agg16, self16, feat16, idx16, row0 + 2, n, lane, G[2], G[3]);

            BAR_SYNC(3 + slot);        // wait slot empty
            char* act = sm + SM_ACT + slot * ACT_IMG;
#pragma unroll
            for (int rr = 0; rr < 4; rr++)
                sts_row(act, pw * 4 + rr, lane, G[rr]);
            BAR_ARRIVE(1 + slot);      // mark full
        }
    } else {
        // ================= CONSUMERS (8 warps: 2m x 4n, 16x32) ==============
        int wm = wid >> 2, wn = wid & 3;
        int rsel = lane & 15, csel = lane >> 4;
        BAR_ARRIVE(3); BAR_ARRIVE(4);  // prime both slots empty

        uint32_t aOff = (uint32_t)((16 * wm + rsel) * ACT_STR + csel * 16);
        uint32_t bBase = smb + SM_W16 + (uint32_t)(rsel * WSB + csel * 16 + 64 * wn);

        int cpair = (lane & 3) * 2;
        float2 bb[4];
#pragma unroll
        for (int nt = 0; nt < 4; nt++) {
            int col = 32 * wn + 8 * nt + cpair;
            bb[nt].x = b[col]; bb[nt].y = b[col + 1];
        }
        int do32 = last && (side == 1);
        float2 csum[4];
#pragma unroll
        for (int nt = 0; nt < 4; nt++) csum[nt] = make_float2(0.f, 0.f);

        int it = 0;
        for (int tile = blk; tile < NT32; tile += NBLK_SIDE, it++) {
            int slot = it & (NSLOT - 1);
            BAR_SYNC(1 + slot);        // wait full
            uint32_t aBase = smb + SM_ACT + (uint32_t)(slot * ACT_IMG) + aOff;

            float acc[4][4];
#pragma unroll
            for (int nt = 0; nt < 4; nt++)
#pragma unroll
                for (int q = 0; q < 4; q++) acc[nt][q] = 0.f;

            // double-buffered fragments: prefetch ks+1 before MMAs of ks
            uint32_t aF[2][4], bF[2][2][4];
            ldsm_x4(aF[0], aBase);
            ldsm_x4t(bF[0][0], bBase);
            ldsm_x4t(bF[0][1], bBase + 32);
#pragma unroll
            for (int ks = 0; ks < 18; ks++) {
                int cur = ks & 1, nxt = cur ^ 1;
                if (ks < 17) {
                    uint32_t ra = aBase + (uint32_t)((ks + 1) * 32);
                    uint32_t rb = bBase + (uint32_t)((ks + 1) * 16 * WSB);
                    ldsm_x4(aF[nxt], ra);
                    ldsm_x4t(bF[nxt][0], rb);
                    ldsm_x4t(bF[nxt][1], rb + 32);
                }
#pragma unroll
                for (int nt = 0; nt < 4; nt++)
                    mma_f16(acc[nt], aF[cur],
                            bF[cur][nt >> 1][2 * (nt & 1)],
                            bF[cur][nt >> 1][2 * (nt & 1) + 1]);
            }
            BAR_ARRIVE(3 + slot);      // slot free

            int row0 = tile * BM32;
            int r_lo = lane >> 2;
            int ra0 = row0 + 16 * wm + r_lo;
#pragma unroll
            for (int nt = 0; nt < 4; nt++) {
                int col = 32 * wn + 8 * nt + cpair;
                if (ra0 < n) {
                    float v0 = acc[nt][0] + bb[nt].x, v1 = acc[nt][1] + bb[nt].y;
                    *(__half2*)(out16 + (size_t)ra0 * DD + col) = __floats2half2_rn(v0, v1);
                    if (do32) {
                        *(float2*)(g_lv32 + (size_t)ra0 * DD + col) = make_float2(v0, v1);
                        csum[nt].x += v0; csum[nt].y += v1;
                    }
                }
                if (ra0 + 8 < n) {
                    float v0 = acc[nt][2] + bb[nt].x, v1 = acc[nt][3] + bb[nt].y;
                    *(__half2*)(out16 + (size_t)(ra0 + 8) * DD + col) = __floats2half2_rn(v0, v1);
                    if (do32) {
                        *(float2*)(g_lv32 + (size_t)(ra0 + 8) * DD + col) = make_float2(v0, v1);
                        csum[nt].x += v0; csum[nt].y += v1;
                    }
                }
            }
        }

        if (do32) {
#pragma unroll
            for (int nt = 0; nt < 4; nt++) {
                float c0 = csum[nt].x, c1 = csum[nt].y;
#pragma unroll
                for (int o = 4; o < 32; o <<= 1) {
                    c0 += __shfl_xor_sync(0xffffffffu, c0, o);
                    c1 += __shfl_xor_sync(0xffffffffu, c1, o);
                }
                if (lane < 4) {
                    int col = 32 * wn + 8 * nt + lane * 2;
                    atomicAdd(&g_colsum[col], c0);
                    atomicAdd(&g_colsum[col + 1], c1);
                }
            }
        }
    }
}

// ---------------------------------------------------------------------------
__global__ void final_kernel(const float* __restrict__ Wq,
                             const float* __restrict__ bq,
                             float* __restrict__ Q, int n) {
    const float* lv = g_lv32;
    __shared__ float sW[DD];
    __shared__ float s_s;
    int tid = threadIdx.x;
    if (tid < DD) sW[tid] = Wq[DD + tid];
    if (tid < 32) {
        float p = 0.f;
#pragma unroll
        for (int t = 0; t < 4; t++) p += g_colsum[tid + 32 * t] * Wq[tid + 32 * t];
#pragma unroll
        for (int o = 16; o > 0; o >>= 1) p += __shfl_xor_sync(0xffffffffu, p, o);
        if (tid == 0) s_s = p + bq[0];
    }
    __syncthreads();
    int warp = tid >> 5, lane = tid & 31;
    int base = blockIdx.x * 64 + warp * 8;
    for (int i = 0; i < 8; i++) {
        int row = base + i;
        if (row >= n) break;
        const float* rp = lv + (size_t)row * DD;
        float p = rp[lane]      * sW[lane]
                + rp[lane + 32] * sW[lane + 32]
                + rp[lane + 64] * sW[lane + 64]
                + rp[lane + 96] * sW[lane + 96];
#pragma unroll
        for (int o = 16; o > 0; o >>= 1) p += __shfl_xor_sync(0xffffffffu, p, o);
        if (lane == 0) Q[row] = s_s + p;
    }
}

// ---------------------------------------------------------------------------
extern "C" void kernel_launch(void* const* d_in, const int* in_sizes, int n_in,
                              void* d_out, int out_size) {
    const float* x    = (const float*)d_in[0];
    const int*   vci  = (const int*)d_in[1];
    const int*   cvi  = (const int*)d_in[2];
    const float* W_iv = (const float*)d_in[3];
    const float* b_iv = (const float*)d_in[4];
    const float* W_ic = (const float*)d_in[5];
    const float* b_ic = (const float*)d_in[6];
    const float* W_v  = (const float*)d_in[7];
    const float* b_v  = (const float*)d_in[8];
    const float* W_c  = (const float*)d_in[9];
    const float* b_c  = (const float*)d_in[10];
    const float* W_q  = (const float*)d_in[11];
    const float* b_q  = (const float*)d_in[12];
    float* Q = (float*)d_out;

    cudaFuncSetAttribute(layer_dual,
                         cudaFuncAttributeMaxDynamicSharedMemorySize, SM_DYN);

    setup_all<<<NB_SETUP, 256>>>(x, vci, cvi, W_iv, W_ic, b_iv, b_ic, W_v, W_c, NVV);

    int lv = 0, lc = 2;
    for (int t = 0; t < 3; t++) {
        int nlc = 5 - lc, nlv = 1 - lv;
        layer_dual<<<GRID_TC, 512, SM_DYN>>>(lv, lc, nlv, nlc, b_v, b_c, NVV, t == 2);
        lv = nlv; lc = nlc;
    }

    final_kernel<<<(NVV + 63) / 64, 256>>>(W_q, b_q, Q, NVV);
}

// round 17
// speedup vs baseline: 1.8607x; 1.0477x over previous
#include <cuda_runtime.h>
#include <cuda_fp16.h>
#include <cstdint>

#define NVV 50000
#define DD 128
#define FIN 32
#define DEG 16
#define GRID_TC 304
#define NBLK_SIDE (GRID_TC / 2)          // 152 CTAs per side

#define BM32 32
#define NT32 ((NVV + BM32 - 1) / BM32)   // 1563

#define WSB 272
#define ACT_STR 592
#define ACT_IMG (32 * ACT_STR)            // 18944

#define SM_W16 0
#define SM_ACT 78336
#define SM_DYN (SM_ACT + ACT_IMG)         // 97280 -> 2 CTAs/SM

// single slot: 1 = full, 2 = empty
#define BAR_SYNC(id)   asm volatile("bar.sync %0, 512;"   :: "r"(id) : "memory")
#define BAR_ARRIVE(id) asm volatile("bar.arrive %0, 512;" :: "r"(id) : "memory")

// ---------------------------------------------------------------------------
__device__ __align__(16) unsigned short g_w16[2][288 * 136];
__device__ __align__(256) float g_lv32[(size_t)NVV * DD];
__device__ __align__(256) __half g_h16[4][(size_t)NVV * DD];
__device__ __align__(16) __half g_feat16[(size_t)2 * NVV * FIN];
__device__ __align__(16) unsigned short g_idx16[2][(size_t)NVV * DEG];
__device__ float g_colsum[DD];

__device__ __forceinline__ uint32_t smem_u32(const void* p) {
    uint32_t a;
    asm("{ .reg .u64 t; cvta.to.shared.u64 t, %1; cvt.u32.u64 %0, t; }" : "=r"(a) : "l"(p));
    return a;
}
__device__ __forceinline__ void ldsm_x4(uint32_t* r, uint32_t addr) {
    asm volatile("ldmatrix.sync.aligned.m8n8.x4.shared.b16 {%0,%1,%2,%3}, [%4];"
                 : "=r"(r[0]), "=r"(r[1]), "=r"(r[2]), "=r"(r[3]) : "r"(addr));
}
__device__ __forceinline__ void ldsm_x4t(uint32_t* r, uint32_t addr) {
    asm volatile("ldmatrix.sync.aligned.m8n8.x4.trans.shared.b16 {%0,%1,%2,%3}, [%4];"
                 : "=r"(r[0]), "=r"(r[1]), "=r"(r[2]), "=r"(r[3]) : "r"(addr));
}
__device__ __forceinline__ void mma_f16(float* d, const uint32_t* a, uint32_t b0, uint32_t b1) {
    asm volatile("mma.sync.aligned.m16n8k16.row.col.f32.f16.f16.f32 "
                 "{%0,%1,%2,%3}, {%4,%5,%6,%7}, {%8,%9}, {%0,%1,%2,%3};"
                 : "+f"(d[0]), "+f"(d[1]), "+f"(d[2]), "+f"(d[3])
                 : "r"(a[0]), "r"(a[1]), "r"(a[2]), "r"(a[3]), "r"(b0), "r"(b1));
}
__device__ __forceinline__ uint32_t pack_h2(float lo, float hi) {
    __half2 h = __floats2half2_rn(lo, hi);
    return *reinterpret_cast<uint32_t*>(&h);
}
__device__ __forceinline__ uint2 pack4_h(float4 v) {
    uint2 r;
    r.x = pack_h2(v.x, v.y);
    r.y = pack_h2(v.z, v.w);
    return r;
}
__device__ __forceinline__ __half2 u2h(uint32_t u) { return *reinterpret_cast<__half2*>(&u); }
__device__ __forceinline__ uint32_t h2u(__half2 h) { return *reinterpret_cast<uint32_t*>(&h); }

// ---------------------------------------------------------------------------
// setup_all (unchanged from R15/16): init GEMMs + W split + feat16 + idx16.
// ---------------------------------------------------------------------------
#define NB_INIT ((NVV + 127) / 128)       // 391
#define AUX0 (2 * NB_INIT)                // 782
#define NB_FEAT 32
#define NB_IDX 64
#define NB_SETUP (AUX0 + 3 + NB_FEAT + NB_IDX)

#define ISM_B 0
#define ISM_ACT 8704
#define IACT_STR 80

__global__ __launch_bounds__(256, 1)
void setup_all(const float* __restrict__ x,
               const int* __restrict__ vci, const int* __restrict__ cvi,
               const float* __restrict__ Wiv, const float* __restrict__ Wic,
               const float* __restrict__ biv, const float* __restrict__ bic,
               const float* __restrict__ Wv, const float* __restrict__ Wc, int n) {
    int bid = blockIdx.x;
    int tid = threadIdx.x;

    if (bid >= AUX0) {
        int aux = bid - AUX0;
        if (aux == 0 || aux == 1) {
            const float* W = aux ? Wc : Wv;
            for (int e = tid; e < 288 * 136; e += 256) {
                int k = e / 136, nn = e - k * 136;
                float w = (nn < 128) ? W[nn * 288 + k] : 0.f;
                __half h = __float2half_rn(w);
                g_w16[aux][e] = *reinterpret_cast<unsigned short*>(&h);
            }
        } else if (aux == 2) {
            if (tid < DD) g_colsum[tid] = 0.f;
        } else if (aux < 3 + NB_FEAT) {
            int fb = aux - 3;
            const int total = 2 * NVV * FIN;
            for (int e = fb * 256 + tid; e < total; e += NB_FEAT * 256)
                g_feat16[e] = __float2half_rn(x[e]);
        } else {
            __shared__ int s_is64;
            if (tid == 0) {
                int nz = 0;
#pragma unroll
                for (int i = 0; i < 64; i++) nz |= vci[2 * i + 1];
                s_is64 = (nz == 0) ? 1 : 0;
            }
            __syncthreads();
            int is64 = s_is64;
            int ib = aux - (3 + NB_FEAT);
            const int rows = 2 * NVV;
            for (int r = ib * 256 + tid; r < rows; r += NB_IDX * 256) {
                const int* src = (r < NVV) ? vci : cvi;
                int lr = (r < NVV) ? r : r - NVV;
                unsigned short* dst = g_idx16[(r < NVV) ? 0 : 1] + (size_t)lr * DEG;
                const int* ip = src + (size_t)lr * DEG * (is64 ? 2 : 1);
                uint32_t w[8];
#pragma unroll
                for (int q = 0; q < 8; q++) {
                    int a = is64 ? ip[4 * q]     : ip[2 * q];
                    int b = is64 ? ip[4 * q + 2] : ip[2 * q + 1];
                    w[q] = (uint32_t)(a & 0xffff) | ((uint32_t)(b & 0xffff) << 16);
                }
                uint4* d4 = (uint4*)dst;
                d4[0] = make_uint4(w[0], w[1], w[2], w[3]);
                d4[1] = make_uint4(w[4], w[5], w[6], w[7]);
            }
        }
        return;
    }

    // ---- init embedding tile ----
    __shared__ __align__(16) char ism[ISM_ACT + 128 * IACT_STR];
    uint32_t smb = smem_u32(ism);
    int side = bid & 1;
    int blk = bid >> 1;
    const float* feat = x + (side ? (size_t)NVV * FIN : 0);
    const float* W    = side ? Wic : Wiv;
    const float* b    = side ? bic : biv;
    __half* out16 = g_h16[side ? 2 : 0];

    int wid = tid >> 5, lane = tid & 31;
    int row0 = blk * 128;

    for (int e = tid; e < 32 * 136; e += 256) {
        int k = e / 136, nn = e - k * 136;
        float w = (nn < 128) ? W[nn * FIN + k] : 0.f;
        __half h = __float2half_rn(w);
        *(unsigned short*)(ism + ISM_B + k * WSB + nn * 2) =
            *reinterpret_cast<unsigned short*>(&h);
    }
    {
        int r = tid >> 1, half = tid & 1;
        int gr = row0 + r;
        char* rowp = ism + ISM_ACT + r * IACT_STR + half * 32;
#pragma unroll
        for (int i = 0; i < 4; i++) {
            float4 v = (gr < n)
                ? reinterpret_cast<const float4*>(feat + (size_t)gr * FIN)[half * 4 + i]
                : make_float4(0.f, 0.f, 0.f, 0.f);
            *(uint2*)(rowp + i * 8) = pack4_h(v);
        }
    }
    __syncthreads();

    int wm = wid >> 1, wn = wid & 1;
    int rsel = lane & 15, csel = lane >> 4;
    uint32_t aBase = smb + ISM_ACT + (uint32_t)((32 * wm + rsel) * IACT_STR + csel * 16);
    uint32_t bBase = smb + ISM_B + (uint32_t)(rsel * WSB + csel * 16 + 128 * wn);

    float acc[2][8][4];
#pragma unroll
    for (int mt = 0; mt < 2; mt++)
#pragma unroll
        for (int nt = 0; nt < 8; nt++)
#pragma unroll
            for (int q = 0; q < 4; q++) acc[mt][nt][q] = 0.f;

#pragma unroll
    for (int ks = 0; ks < 2; ks++) {
        uint32_t a[2][4], bf[4][4];
#pragma unroll
        for (int mt = 0; mt < 2; mt++)
            ldsm_x4(a[mt], aBase + (uint32_t)(16 * mt * IACT_STR + ks * 32));
#pragma unroll
        for (int np = 0; np < 4; np++)
            ldsm_x4t(bf[np], bBase + (uint32_t)(ks * 16 * WSB + 32 * np));
#pragma unroll
        for (int mt = 0; mt < 2; mt++)
#pragma unroll
            for (int nt = 0; nt < 8; nt++)
                mma_f16(acc[mt][nt], a[mt], bf[nt >> 1][2 * (nt & 1)], bf[nt >> 1][2 * (nt & 1) + 1]);
    }

    int r_lo = lane >> 2;
    int cpair = (lane & 3) * 2;
#pragma unroll
    for (int mt = 0; mt < 2; mt++) {
        int ra = row0 + 32 * wm + 16 * mt + r_lo;
#pragma unroll
        for (int nt = 0; nt < 8; nt++) {
            int col = 64 * wn + 8 * nt + cpair;
            float b0 = b[col], b1 = b[col + 1];
            if (ra < n)
                *(__half2*)(out16 + (size_t)ra * DD + col) =
                    __floats2half2_rn(acc[mt][nt][0] + b0, acc[mt][nt][1] + b1);
            if (ra + 8 < n)
                *(__half2*)(out16 + (size_t)(ra + 8) * DD + col) =
                    __floats2half2_rn(acc[mt][nt][2] + b0, acc[mt][nt][3] + b1);
        }
    }
}

// ---------------------------------------------------------------------------
// Producer: one 288-wide row (64-reg friendly, R15-proven).
// ---------------------------------------------------------------------------
__device__ __forceinline__ void gather_row(
    const __half* __restrict__ agg16, const __half* __restrict__ self16,
    const __half* __restrict__ feat16, const unsigned short* __restrict__ idx16,
    int gr, int n, int lane, uint2* G)
{
    bool val = gr < n;
    const uint4* ip = (const uint4*)(idx16 + (size_t)(val ? gr : 0) * DEG);
    uint4 p0 = __ldg(ip), p1 = __ldg(ip + 1);
    uint32_t w[8] = {p0.x, p0.y, p0.z, p0.w, p1.x, p1.y, p1.z, p1.w};
    int srcs[DEG];
#pragma unroll
    for (int q = 0; q < 8; q++) {
        srcs[2 * q]     = (int)(w[q] & 0xffffu);
        srcs[2 * q + 1] = (int)(w[q] >> 16);
    }

    __half2 ax[4], ay[4];
#pragma unroll
    for (int j = 0; j < 4; j++) {
        uint2 d = __ldg(reinterpret_cast<const uint2*>(agg16 + (size_t)srcs[j] * DD) + lane);
        ax[j] = u2h(d.x); ay[j] = u2h(d.y);
    }
#pragma unroll
    for (int j = 4; j < DEG; j++) {
        uint2 d = __ldg(reinterpret_cast<const uint2*>(agg16 + (size_t)srcs[j] * DD) + lane);
        ax[j & 3] = __hadd2(ax[j & 3], u2h(d.x));
        ay[j & 3] = __hadd2(ay[j & 3], u2h(d.y));
    }
    __half2 sx = __hadd2(__hadd2(ax[0], ax[1]), __hadd2(ax[2], ax[3]));
    __half2 sy = __hadd2(__hadd2(ay[0], ay[1]), __hadd2(ay[2], ay[3]));

    uint2 sv = val ? __ldg(reinterpret_cast<const uint2*>(self16 + (size_t)gr * DD) + lane)
                   : make_uint2(0u, 0u);
    uint2 fv = (val && lane < 8)
        ? __ldg(reinterpret_cast<const uint2*>(feat16 + (size_t)gr * FIN) + lane)
        : make_uint2(0u, 0u);

    if (!val) { sx = u2h(0u); sy = u2h(0u); }
    G[0].x = h2u(sx); G[0].y = h2u(sy);
    G[1] = sv;
    G[2] = fv;
}

__device__ __forceinline__ void sts_row(char* act, int r, int lane, const uint2* G) {
    char* rowp = act + r * ACT_STR;
    *(uint2*)(rowp + lane * 8) = G[0];
    *(uint2*)(rowp + 256 + lane * 8) = G[1];
    if (lane < 8) *(uint2*)(rowp + 512 + lane * 8) = G[2];
}

// ---------------------------------------------------------------------------
// Dual-side layer: 512 threads, 2 CTAs/SM (97280 B smem, single Act slot;
// the producers' register staging acts as the second pipeline buffer).
// Two independent barrier domains per SM decouple pipeline stalls.
// ---------------------------------------------------------------------------
__global__ __launch_bounds__(512, 2)
void layer_dual(int lv_sel, int lc_sel, int nlv_sel, int nlc_sel,
                const float* __restrict__ bv, const float* __restrict__ bc,
                int n, int last)
{
    extern __shared__ char sm[];
    uint32_t smb = smem_u32(sm);

    int side = blockIdx.x & 1;
    int blk = blockIdx.x >> 1;

    const __half* agg16; const __half* self16; __half* out16;
    const __half* feat16; const unsigned short* idx16; const float* b; int which;
    if (side == 0) {
        agg16 = g_h16[lv_sel]; self16 = g_h16[lc_sel]; out16 = g_h16[nlc_sel];
        feat16 = g_feat16 + (size_t)NVV * FIN; idx16 = g_idx16[1]; b = bc; which = 1;
    } else {
        agg16 = g_h16[lc_sel]; self16 = g_h16[lv_sel]; out16 = g_h16[nlv_sel];
        feat16 = g_feat16; idx16 = g_idx16[0]; b = bv; which = 0;
    }

    int tid = threadIdx.x, wid = tid >> 5, lane = tid & 31;

    {
        const uint4* sw = (const uint4*)g_w16[which];
        uint4* dw = (uint4*)(sm + SM_W16);
        for (int i = tid; i < 78336 / 16; i += 512) dw[i] = sw[i];
    }
    __syncthreads();

    if (wid >= 8) {
        // ================= PRODUCERS (8 warps, 4 rows each) =================
        int pw = wid - 8;
        for (int tile = blk; tile < NT32; tile += NBLK_SIDE) {
            int row0 = tile * BM32 + pw * 4;

            uint2 G[4][3];
#pragma unroll
            for (int rr = 0; rr < 4; rr++)
                gather_row(agg16, self16, feat16, idx16, row0 + rr, n, lane, G[rr]);

            BAR_SYNC(2);               // wait slot empty
            char* act = sm + SM_ACT;
#pragma unroll
            for (int rr = 0; rr < 4; rr++)
                sts_row(act, pw * 4 + rr, lane, G[rr]);
            BAR_ARRIVE(1);             // mark full
        }
    } else {
        // ================= CONSUMERS (8 warps: 2m x 4n, 16x32) ==============
        int wm = wid >> 2, wn = wid & 3;
        int rsel = lane & 15, csel = lane >> 4;
        BAR_ARRIVE(2);                 // prime slot empty

        uint32_t aOff = (uint32_t)((16 * wm + rsel) * ACT_STR + csel * 16);
        uint32_t bBase = smb + SM_W16 + (uint32_t)(rsel * WSB + csel * 16 + 64 * wn);

        int cpair = (lane & 3) * 2;
        float2 bb[4];
#pragma unroll
        for (int nt = 0; nt < 4; nt++) {
            int col = 32 * wn + 8 * nt + cpair;
            bb[nt].x = b[col]; bb[nt].y = b[col + 1];
        }
        int do32 = last && (side == 1);
        float2 csum[4];
#pragma unroll
        for (int nt = 0; nt < 4; nt++) csum[nt] = make_float2(0.f, 0.f);

        for (int tile = blk; tile < NT32; tile += NBLK_SIDE) {
            BAR_SYNC(1);               // wait full
            uint32_t aBase = smb + SM_ACT + aOff;

            float acc[4][4];
#pragma unroll
            for (int nt = 0; nt < 4; nt++)
#pragma unroll
                for (int q = 0; q < 4; q++) acc[nt][q] = 0.f;

#pragma unroll 3
            for (int ks = 0; ks < 18; ks++) {
                uint32_t a[4], bf[2][4];
                ldsm_x4(a, aBase + (uint32_t)(ks * 32));
#pragma unroll
                for (int np = 0; np < 2; np++)
                    ldsm_x4t(bf[np], bBase + (uint32_t)(ks * 16 * WSB + 32 * np));
#pragma unroll
                for (int nt = 0; nt < 4; nt++)
                    mma_f16(acc[nt], a, bf[nt >> 1][2 * (nt & 1)], bf[nt >> 1][2 * (nt & 1) + 1]);
            }
            BAR_ARRIVE(2);             // slot free

            int row0 = tile * BM32;
            int r_lo = lane >> 2;
            int ra0 = row0 + 16 * wm + r_lo;
#pragma unroll
            for (int nt = 0; nt < 4; nt++) {
                int col = 32 * wn + 8 * nt + cpair;
                if (ra0 < n) {
                    float v0 = acc[nt][0] + bb[nt].x, v1 = acc[nt][1] + bb[nt].y;
                    *(__half2*)(out16 + (size_t)ra0 * DD + col) = __floats2half2_rn(v0, v1);
                    if (do32) {
                        *(float2*)(g_lv32 + (size_t)ra0 * DD + col) = make_float2(v0, v1);
                        csum[nt].x += v0; csum[nt].y += v1;
                    }
                }
                if (ra0 + 8 < n) {
                    float v0 = acc[nt][2] + bb[nt].x, v1 = acc[nt][3] + bb[nt].y;
                    *(__half2*)(out16 + (size_t)(ra0 + 8) * DD + col) = __floats2half2_rn(v0, v1);
                    if (do32) {
                        *(float2*)(g_lv32 + (size_t)(ra0 + 8) * DD + col) = make_float2(v0, v1);
                        csum[nt].x += v0; csum[nt].y += v1;
                    }
                }
            }
        }

        if (do32) {
#pragma unroll
            for (int nt = 0; nt < 4; nt++) {
                float c0 = csum[nt].x, c1 = csum[nt].y;
#pragma unroll
                for (int o = 4; o < 32; o <<= 1) {
                    c0 += __shfl_xor_sync(0xffffffffu, c0, o);
                    c1 += __shfl_xor_sync(0xffffffffu, c1, o);
                }
                if (lane < 4) {
                    int col = 32 * wn + 8 * nt + lane * 2;
                    atomicAdd(&g_colsum[col], c0);
                    atomicAdd(&g_colsum[col + 1], c1);
                }
            }
        }
    }
}

// ---------------------------------------------------------------------------
__global__ void final_kernel(const float* __restrict__ Wq,
                             const float* __restrict__ bq,
                             float* __restrict__ Q, int n) {
    const float* lv = g_lv32;
    __shared__ float sW[DD];
    __shared__ float s_s;
    int tid = threadIdx.x;
    if (tid < DD) sW[tid] = Wq[DD + tid];
    if (tid < 32) {
        float p = 0.f;
#pragma unroll
        for (int t = 0; t < 4; t++) p += g_colsum[tid + 32 * t] * Wq[tid + 32 * t];
#pragma unroll
        for (int o = 16; o > 0; o >>= 1) p += __shfl_xor_sync(0xffffffffu, p, o);
        if (tid == 0) s_s = p + bq[0];
    }
    __syncthreads();
    int warp = tid >> 5, lane = tid & 31;
    int base = blockIdx.x * 64 + warp * 8;
    for (int i = 0; i < 8; i++) {
        int row = base + i;
        if (row >= n) break;
        const float* rp = lv + (size_t)row * DD;
        float p = rp[lane]      * sW[lane]
                + rp[lane + 32] * sW[lane + 32]
                + rp[lane + 64] * sW[lane + 64]
                + rp[lane + 96] * sW[lane + 96];
#pragma unroll
        for (int o = 16; o > 0; o >>= 1) p += __shfl_xor_sync(0xffffffffu, p, o);
        if (lane == 0) Q[row] = s_s + p;
    }
}

// ---------------------------------------------------------------------------
extern "C" void kernel_launch(void* const* d_in, const int* in_sizes, int n_in,
                              void* d_out, int out_size) {
    const float* x    = (const float*)d_in[0];
    const int*   vci  = (const int*)d_in[1];
    const int*   cvi  = (const int*)d_in[2];
    const float* W_iv = (const float*)d_in[3];
    const float* b_iv = (const float*)d_in[4];
    const float* W_ic = (const float*)d_in[5];
    const float* b_ic = (const float*)d_in[6];
    const float* W_v  = (const float*)d_in[7];
    const float* b_v  = (const float*)d_in[8];
    const float* W_c  = (const float*)d_in[9];
    const float* b_c  = (const float*)d_in[10];
    const float* W_q  = (const float*)d_in[11];
    const float* b_q  = (const float*)d_in[12];
    float* Q = (float*)d_out;

    cudaFuncSetAttribute(layer_dual,
                         cudaFuncAttributeMaxDynamicSharedMemorySize, SM_DYN);

    setup_all<<<NB_SETUP, 256>>>(x, vci, cvi, W_iv, W_ic, b_iv, b_ic, W_v, W_c, NVV);

    int lv = 0, lc = 2;
    for (int t = 0; t < 3; t++) {
        int nlc = 5 - lc, nlv = 1 - lv;
        layer_dual<<<GRID_TC, 512, SM_DYN>>>(lv, lc, nlv, nlc, b_v, b_c, NVV, t == 2);
        lv = nlv; lc = nlc;
    }

    final_kernel<<<(NVV + 63) / 64, 256>>>(W_q, b_q, Q, NVV);
}